// round 2
// baseline (speedup 1.0000x reference)
#include <cuda_runtime.h>
#include <cstdint>
#include <cstddef>

#define H 256
#define BK 16

// ---------------- scratch (static device allocations; no cudaMalloc) ----------------
__device__ float d_m[50000 * 256];
__device__ float d_agg[50000 * 256];
__device__ float d_gi[50000 * 768];
__device__ float d_gh[50000 * 768];
__device__ float d_hidden[50000 * 256];
__device__ float d_Wt[256 * 256];
__device__ float d_vn[1024 * 256];
__device__ float d_a[1024 * 256];
__device__ float d_bth[12288 * 256];
__device__ float d_sg[1024 * 256];
__device__ float d_vns[1024 * 512];
__device__ float d_sh[1024 * 256];
__device__ int   d_lastidx[1024];

// ---------------- generic NT GEMM: C[m,n] = sum_k A[m,k] * B[n,k] ----------------
// A: [M,K] row-major, B: [N,K] row-major, C: [M,N] row-major. K % 16 == 0.
__global__ __launch_bounds__(256) void gemm_nt(
    const float* __restrict__ A, const float* __restrict__ B,
    float* __restrict__ C, int M, int N, int K)
{
    __shared__ float As[BK][128];
    __shared__ float Bs[BK][128];
    const int bm = blockIdx.y * 128;
    const int bn = blockIdx.x * 128;
    const int tid = threadIdx.x;
    const int tcol = (tid & 15) * 8;
    const int trow = (tid >> 4) * 8;

    float acc[8][8];
#pragma unroll
    for (int i = 0; i < 8; ++i)
#pragma unroll
        for (int j = 0; j < 8; ++j) acc[i][j] = 0.f;

    for (int k0 = 0; k0 < K; k0 += BK) {
#pragma unroll
        for (int it = 0; it < 2; ++it) {
            int lin = tid + it * 256;
            int r  = lin >> 2;
            int c4 = (lin & 3) << 2;
            int gm = bm + r; gm = gm < M ? gm : M - 1;
            float4 va = *reinterpret_cast<const float4*>(A + (size_t)gm * K + k0 + c4);
            As[c4 + 0][r] = va.x; As[c4 + 1][r] = va.y;
            As[c4 + 2][r] = va.z; As[c4 + 3][r] = va.w;
            int gn = bn + r; gn = gn < N ? gn : N - 1;
            float4 vb = *reinterpret_cast<const float4*>(B + (size_t)gn * K + k0 + c4);
            Bs[c4 + 0][r] = vb.x; Bs[c4 + 1][r] = vb.y;
            Bs[c4 + 2][r] = vb.z; Bs[c4 + 3][r] = vb.w;
        }
        __syncthreads();
#pragma unroll
        for (int k = 0; k < BK; ++k) {
            float4 a0 = *reinterpret_cast<const float4*>(&As[k][trow]);
            float4 a1 = *reinterpret_cast<const float4*>(&As[k][trow + 4]);
            float4 b0 = *reinterpret_cast<const float4*>(&Bs[k][tcol]);
            float4 b1 = *reinterpret_cast<const float4*>(&Bs[k][tcol + 4]);
            float ar[8] = {a0.x, a0.y, a0.z, a0.w, a1.x, a1.y, a1.z, a1.w};
            float br[8] = {b0.x, b0.y, b0.z, b0.w, b1.x, b1.y, b1.z, b1.w};
#pragma unroll
            for (int i = 0; i < 8; ++i)
#pragma unroll
                for (int j = 0; j < 8; ++j)
                    acc[i][j] = fmaf(ar[i], br[j], acc[i][j]);
        }
        __syncthreads();
    }

#pragma unroll
    for (int i = 0; i < 8; ++i) {
        int gm = bm + trow + i;
        if (gm >= M) break;
#pragma unroll
        for (int j = 0; j < 8; ++j) {
            int gn = bn + tcol + j;
            if (gn < N) C[(size_t)gm * N + gn] = acc[i][j];
        }
    }
}

// ---------------- small helpers ----------------
__global__ void transpose256(const float* __restrict__ in, float* __restrict__ out)
{
    int idx = blockIdx.x * blockDim.x + threadIdx.x;
    if (idx >= 256 * 256) return;
    int j = idx >> 8, k = idx & 255;
    out[j * 256 + k] = in[k * 256 + j];   // out[j,k] = W[k,j]
}

// scatter-add: agg[dst] += m[src] over all edges, float4 vector atomics
__global__ void scatter_add(const int* __restrict__ fg, const float* __restrict__ m,
                            float* __restrict__ agg, int E)
{
    long long idx = (long long)blockIdx.x * blockDim.x + threadIdx.x;
    long long total = (long long)E * (H / 4);
    if (idx >= total) return;
    int e  = (int)(idx >> 6);
    int c4 = (int)(idx & 63) * 4;
    int src = fg[e];
    int dst = fg[E + e];
    float4 v = *reinterpret_cast<const float4*>(m + (size_t)src * H + c4);
    atomicAdd(reinterpret_cast<float4*>(agg + (size_t)dst * H + c4), v);
}

__global__ void gru_elementwise(const float* __restrict__ gi, const float* __restrict__ gh,
                                const float* __restrict__ emb,
                                const float* __restrict__ bih, const float* __restrict__ bhh,
                                float* __restrict__ hidden, int NNODE)
{
    long long idx = (long long)blockIdx.x * blockDim.x + threadIdx.x;
    if (idx >= (long long)NNODE * H) return;
    int n = (int)(idx >> 8), h = (int)(idx & 255);
    size_t base = (size_t)n * 768;
    float ir = gi[base + h]       + bih[h];
    float hr = gh[base + h]       + bhh[h];
    float iz = gi[base + 256 + h] + bih[256 + h];
    float hz = gh[base + 256 + h] + bhh[256 + h];
    float in_ = gi[base + 512 + h] + bih[512 + h];
    float hn  = gh[base + 512 + h] + bhh[512 + h];
    float r = 1.f / (1.f + expf(-(ir + hr)));
    float z = 1.f / (1.f + expf(-(iz + hz)));
    float nn = tanhf(in_ + r * hn);
    float e = emb[(size_t)n * H + h];
    hidden[(size_t)n * H + h] = (1.f - z) * nn + z * e;
}

__global__ void gather_relu(const int* __restrict__ x, const float* __restrict__ hidden,
                            float* __restrict__ h2, int N)
{
    long long idx = (long long)blockIdx.x * blockDim.x + threadIdx.x;
    if (idx >= (long long)N * H) return;
    int i = (int)(idx >> 8), h = (int)(idx & 255);
    int node = x[i] - 1;
    float v = hidden[(size_t)node * H + h];
    h2[idx] = v > 0.f ? v : 0.f;
}

__global__ void last_max(const int* __restrict__ batch, int* __restrict__ lastidx, int N)
{
    int i = blockIdx.x * blockDim.x + threadIdx.x;
    if (i >= N) return;
    atomicMax(&lastidx[batch[i]], i);
}

__global__ void vn_gather(const float* __restrict__ h2, const int* __restrict__ lastidx,
                          float* __restrict__ vn, int B)
{
    int idx = blockIdx.x * blockDim.x + threadIdx.x;
    if (idx >= B * H) return;
    int b = idx >> 8, h = idx & 255;
    vn[idx] = h2[(size_t)lastidx[b] * H + h];
}

// one block (256 threads) per session node: gate -> alpha -> s_g accumulation
__global__ void attn_kernel(const float* __restrict__ a, const float* __restrict__ bth,
                            const float* __restrict__ h2, const int* __restrict__ batch,
                            const float* __restrict__ W1_b, const float* __restrict__ W2_b,
                            const float* __restrict__ q_w, const float* __restrict__ q_b,
                            float* __restrict__ sg)
{
    __shared__ float red[256];
    int i = blockIdx.x;
    int h = threadIdx.x;
    int b = batch[i];
    float g = a[(size_t)b * H + h] + W1_b[h] + bth[(size_t)i * H + h] + W2_b[h];
    g = 1.f / (1.f + expf(-g));
    red[h] = g * q_w[h];
    __syncthreads();
#pragma unroll
    for (int s = 128; s > 0; s >>= 1) {
        if (h < s) red[h] += red[h + s];
        __syncthreads();
    }
    float alpha = red[0] + q_b[0];
    atomicAdd(&sg[(size_t)b * H + h], alpha * h2[(size_t)i * H + h]);
}

__global__ void concat_vns(const float* __restrict__ vn, const float* __restrict__ sg,
                           float* __restrict__ vns, int B)
{
    int idx = blockIdx.x * blockDim.x + threadIdx.x;
    if (idx >= B * 512) return;
    int b = idx >> 9, c = idx & 511;
    vns[idx] = (c < 256) ? vn[b * 256 + c] : sg[b * 256 + (c - 256)];
}

__global__ void add_bias(float* __restrict__ sh, const float* __restrict__ W3_b, int B)
{
    int idx = blockIdx.x * blockDim.x + threadIdx.x;
    if (idx >= B * H) return;
    sh[idx] += W3_b[idx & 255];
}

__global__ void edges_to_float(const int* __restrict__ ei, float* __restrict__ out, int n)
{
    int idx = blockIdx.x * blockDim.x + threadIdx.x;
    if (idx >= n) return;
    out[idx] = (float)ei[idx];
}

// ---------------- driver ----------------
extern "C" void kernel_launch(void* const* d_in, const int* in_sizes, int n_in,
                              void* d_out, int out_size)
{
    const int*   x      = (const int*)d_in[0];
    const int*   batch  = (const int*)d_in[1];
    const int*   ei     = (const int*)d_in[2];
    const int*   fg     = (const int*)d_in[3];
    const float* emb    = (const float*)d_in[4];
    const float* ggnn_W = (const float*)d_in[5];
    const float* Wih    = (const float*)d_in[6];
    const float* Whh    = (const float*)d_in[7];
    const float* bih    = (const float*)d_in[8];
    const float* bhh    = (const float*)d_in[9];
    const float* W1_w   = (const float*)d_in[10];
    const float* W1_b   = (const float*)d_in[11];
    const float* W2_w   = (const float*)d_in[12];
    const float* W2_b   = (const float*)d_in[13];
    const float* q_w    = (const float*)d_in[14];
    const float* q_b    = (const float*)d_in[15];
    const float* W3_w   = (const float*)d_in[16];
    const float* W3_b   = (const float*)d_in[17];
    float* out = (float*)d_out;

    const int N     = in_sizes[0];          // 12288 session nodes
    const int E     = in_sizes[3] / 2;      // 500000 edges
    const int NNODE = in_sizes[4] / H;      // 50000 items
    const long long scores_elems = (long long)out_size - (long long)N * H - 2LL * N;
    const int B = (int)(scores_elems / NNODE);   // 1024

    float *m, *agg, *gi, *gh, *hidden, *Wt, *vn, *a, *bth, *sg, *vns, *sh;
    int* lastidx;
    cudaGetSymbolAddress((void**)&m,      d_m);
    cudaGetSymbolAddress((void**)&agg,    d_agg);
    cudaGetSymbolAddress((void**)&gi,     d_gi);
    cudaGetSymbolAddress((void**)&gh,     d_gh);
    cudaGetSymbolAddress((void**)&hidden, d_hidden);
    cudaGetSymbolAddress((void**)&Wt,     d_Wt);
    cudaGetSymbolAddress((void**)&vn,     d_vn);
    cudaGetSymbolAddress((void**)&a,      d_a);
    cudaGetSymbolAddress((void**)&bth,    d_bth);
    cudaGetSymbolAddress((void**)&sg,     d_sg);
    cudaGetSymbolAddress((void**)&vns,    d_vns);
    cudaGetSymbolAddress((void**)&sh,     d_sh);
    cudaGetSymbolAddress((void**)&lastidx, d_lastidx);

    float* scores = out;
    float* h2     = out + scores_elems;
    float* eout   = out + scores_elems + (long long)N * H;

    const int T = 256;
    dim3 blk(T);
    auto cdiv = [](long long v, long long d) { return (unsigned)((v + d - 1) / d); };

    // 1) Wt = ggnn_W^T
    transpose256<<<cdiv(256 * 256, T), blk>>>(ggnn_W, Wt);

    // 2) m = emb @ ggnn_W  (NT with transposed weight)
    gemm_nt<<<dim3(cdiv(H, 128), cdiv(NNODE, 128)), blk>>>(emb, Wt, m, NNODE, H, H);

    // 3) agg = segment_sum(m[src], dst)
    cudaMemsetAsync(agg, 0, (size_t)NNODE * H * sizeof(float));
    scatter_add<<<cdiv((long long)E * (H / 4), T), blk>>>(fg, m, agg, E);

    // 4) gi = agg @ Wih^T ; gh = emb @ Whh^T (biases folded into GRU elementwise)
    gemm_nt<<<dim3(cdiv(3 * H, 128), cdiv(NNODE, 128)), blk>>>(agg, Wih, gi, NNODE, 3 * H, H);
    gemm_nt<<<dim3(cdiv(3 * H, 128), cdiv(NNODE, 128)), blk>>>(emb, Whh, gh, NNODE, 3 * H, H);

    // 5) GRU cell -> hidden_all
    gru_elementwise<<<cdiv((long long)NNODE * H, T), blk>>>(gi, gh, emb, bih, bhh, hidden, NNODE);

    // 6) h2 = relu(hidden[x-1])   (written directly into d_out)
    gather_relu<<<cdiv((long long)N * H, T), blk>>>(x, hidden, h2, N);

    // 7) last node per session
    cudaMemsetAsync(lastidx, 0xFF, (size_t)B * sizeof(int));  // = -1
    last_max<<<cdiv(N, T), blk>>>(batch, lastidx, N);
    vn_gather<<<cdiv(B * H, T), blk>>>(h2, lastidx, vn, B);

    // 8) attention: a = vn @ W1^T ; bth = h2 @ W2^T ; alpha; s_g
    gemm_nt<<<dim3(cdiv(H, 128), cdiv(B, 128)), blk>>>(vn, W1_w, a, B, H, H);
    gemm_nt<<<dim3(cdiv(H, 128), cdiv(N, 128)), blk>>>(h2, W2_w, bth, N, H, H);
    cudaMemsetAsync(sg, 0, (size_t)B * H * sizeof(float));
    attn_kernel<<<N, blk>>>(a, bth, h2, batch, W1_b, W2_b, q_w, q_b, sg);

    // 9) s_h = [vn | s_g] @ W3^T + b3
    concat_vns<<<cdiv(B * 512, T), blk>>>(vn, sg, vns, B);
    gemm_nt<<<dim3(cdiv(H, 128), cdiv(B, 128)), blk>>>(vns, W3_w, sh, B, H, 2 * H);
    add_bias<<<cdiv(B * H, T), blk>>>(sh, W3_b, B);

    // 10) scores = s_h @ emb^T  -> d_out
    gemm_nt<<<dim3(cdiv(NNODE, 128), cdiv(B, 128)), blk>>>(sh, emb, scores, B, NNODE, H);

    // 11) passthrough edge_index as float
    edges_to_float<<<cdiv(2 * N, T), blk>>>(ei, eout, 2 * N);
}

// round 3
// speedup vs baseline: 2.2328x; 2.2328x over previous
#include <cuda_runtime.h>
#include <cstdint>
#include <cstddef>

#define H 256

// ---------------- scratch (static device allocations; no cudaMalloc) ----------------
__device__ float d_m[50000 * 256];
__device__ float d_agg[50000 * 256];
__device__ float d_gi[50000 * 768];
__device__ float d_gh[50000 * 768];
__device__ float d_hidden[50000 * 256];
__device__ float d_Wt[256 * 256];
__device__ float d_vn[1024 * 256];
__device__ float d_a[1024 * 256];
__device__ float d_bth[12288 * 256];
__device__ float d_sg[1024 * 256];
__device__ float d_vns[1024 * 512];
__device__ float d_sh[1024 * 256];
__device__ int   d_lastidx[1024];

// ---------------- tf32 helpers ----------------
__device__ __forceinline__ unsigned f2tf(float f) {
    unsigned u;
    asm("cvt.rna.tf32.f32 %0, %1;" : "=r"(u) : "f"(f));
    return u;
}
__device__ __forceinline__ void ldm_x4(unsigned r[4], unsigned addr) {
    asm volatile("ldmatrix.sync.aligned.m8n8.x4.shared.b16 {%0,%1,%2,%3}, [%4];"
                 : "=r"(r[0]), "=r"(r[1]), "=r"(r[2]), "=r"(r[3]) : "r"(addr));
}
__device__ __forceinline__ void mma_tf32(float d[4], const unsigned a[4], const unsigned b[2]) {
    asm volatile("mma.sync.aligned.m16n8k8.row.col.f32.tf32.tf32.f32 "
                 "{%0,%1,%2,%3}, {%4,%5,%6,%7}, {%8,%9}, {%0,%1,%2,%3};"
                 : "+f"(d[0]), "+f"(d[1]), "+f"(d[2]), "+f"(d[3])
                 : "r"(a[0]), "r"(a[1]), "r"(a[2]), "r"(a[3]), "r"(b[0]), "r"(b[1]));
}

// ---------------- tf32 tensor-core NT GEMM: C[m,n] = sum_k A[m,k]*B[n,k] ----------------
// 128x128 block tile, BK=32, 8 warps of 64x32. K % 32 == 0.
#define LDS_STRIDE 36
__global__ __launch_bounds__(256, 2) void gemm_tf32_nt(
    const float* __restrict__ A, const float* __restrict__ B,
    float* __restrict__ C, int M, int N, int K)
{
    __shared__ unsigned As[128][LDS_STRIDE];
    __shared__ unsigned Bs[128][LDS_STRIDE];

    const int tid  = threadIdx.x;
    const int warp = tid >> 5;
    const int lane = tid & 31;
    const int bm = blockIdx.y * 128;
    const int bn = blockIdx.x * 128;
    const int wm = (warp & 1) * 64;     // 2 warps along M
    const int wn = (warp >> 1) * 32;    // 4 warps along N

    float acc[4][4][4];
#pragma unroll
    for (int i = 0; i < 4; ++i)
#pragma unroll
        for (int j = 0; j < 4; ++j)
#pragma unroll
            for (int v = 0; v < 4; ++v) acc[i][j][v] = 0.f;

    // global staging: each thread loads 16 floats of A and 16 of B per k-step
    const int lr = tid >> 1;           // row 0..127
    const int lc = (tid & 1) * 16;     // 0 or 16
    const float* Aptr = A + (size_t)(bm + lr < M ? bm + lr : M - 1) * K + lc;
    const float* Bptr = B + (size_t)(bn + lr < N ? bn + lr : N - 1) * K + lc;

    // precomputed ldmatrix addresses
    const unsigned aAddr = (unsigned)__cvta_generic_to_shared(
        &As[wm + (lane & 15)][(lane >> 4) << 2]);
    const unsigned bAddr = (unsigned)__cvta_generic_to_shared(
        &Bs[wn + ((lane >> 4) << 3) + (lane & 7)][((lane >> 3) & 1) << 2]);

    for (int k0 = 0; k0 < K; k0 += 32) {
#pragma unroll
        for (int i = 0; i < 4; ++i) {
            float4 va = *reinterpret_cast<const float4*>(Aptr + k0 + 4 * i);
            float4 vb = *reinterpret_cast<const float4*>(Bptr + k0 + 4 * i);
            uint4 ua = make_uint4(f2tf(va.x), f2tf(va.y), f2tf(va.z), f2tf(va.w));
            uint4 ub = make_uint4(f2tf(vb.x), f2tf(vb.y), f2tf(vb.z), f2tf(vb.w));
            *reinterpret_cast<uint4*>(&As[lr][lc + 4 * i]) = ua;
            *reinterpret_cast<uint4*>(&Bs[lr][lc + 4 * i]) = ub;
        }
        __syncthreads();

#pragma unroll
        for (int kk = 0; kk < 32; kk += 8) {
            unsigned afrag[4][4];
            unsigned bfrag[4][2];
#pragma unroll
            for (int mi = 0; mi < 4; ++mi)
                ldm_x4(afrag[mi], aAddr + ((mi * 16) * LDS_STRIDE + kk) * 4u);
#pragma unroll
            for (int p = 0; p < 2; ++p) {
                unsigned t[4];
                ldm_x4(t, bAddr + ((p * 16) * LDS_STRIDE + kk) * 4u);
                bfrag[p * 2][0] = t[0]; bfrag[p * 2][1] = t[1];
                bfrag[p * 2 + 1][0] = t[2]; bfrag[p * 2 + 1][1] = t[3];
            }
#pragma unroll
            for (int mi = 0; mi < 4; ++mi)
#pragma unroll
                for (int nj = 0; nj < 4; ++nj)
                    mma_tf32(acc[mi][nj], afrag[mi], bfrag[nj]);
        }
        __syncthreads();
    }

    // epilogue
#pragma unroll
    for (int mi = 0; mi < 4; ++mi) {
        int gm0 = bm + wm + mi * 16 + (lane >> 2);
#pragma unroll
        for (int nj = 0; nj < 4; ++nj) {
            int gn = bn + wn + nj * 8 + ((lane & 3) << 1);
            if (gn < N) {
                if (gm0 < M)
                    *reinterpret_cast<float2*>(&C[(size_t)gm0 * N + gn]) =
                        make_float2(acc[mi][nj][0], acc[mi][nj][1]);
                if (gm0 + 8 < M)
                    *reinterpret_cast<float2*>(&C[(size_t)(gm0 + 8) * N + gn]) =
                        make_float2(acc[mi][nj][2], acc[mi][nj][3]);
            }
        }
    }
}

// ---------------- fp32 fallback GEMM for tiny matrices ----------------
#define BK 16
__global__ __launch_bounds__(256) void gemm_nt(
    const float* __restrict__ A, const float* __restrict__ B,
    float* __restrict__ C, int M, int N, int K)
{
    __shared__ float As[BK][128];
    __shared__ float Bs[BK][128];
    const int bm = blockIdx.y * 128;
    const int bn = blockIdx.x * 128;
    const int tid = threadIdx.x;
    const int tcol = (tid & 15) * 8;
    const int trow = (tid >> 4) * 8;

    float acc[8][8];
#pragma unroll
    for (int i = 0; i < 8; ++i)
#pragma unroll
        for (int j = 0; j < 8; ++j) acc[i][j] = 0.f;

    for (int k0 = 0; k0 < K; k0 += BK) {
#pragma unroll
        for (int it = 0; it < 2; ++it) {
            int lin = tid + it * 256;
            int r  = lin >> 2;
            int c4 = (lin & 3) << 2;
            int gm = bm + r; gm = gm < M ? gm : M - 1;
            float4 va = *reinterpret_cast<const float4*>(A + (size_t)gm * K + k0 + c4);
            As[c4 + 0][r] = va.x; As[c4 + 1][r] = va.y;
            As[c4 + 2][r] = va.z; As[c4 + 3][r] = va.w;
            int gn = bn + r; gn = gn < N ? gn : N - 1;
            float4 vb = *reinterpret_cast<const float4*>(B + (size_t)gn * K + k0 + c4);
            Bs[c4 + 0][r] = vb.x; Bs[c4 + 1][r] = vb.y;
            Bs[c4 + 2][r] = vb.z; Bs[c4 + 3][r] = vb.w;
        }
        __syncthreads();
#pragma unroll
        for (int k = 0; k < BK; ++k) {
            float4 a0 = *reinterpret_cast<const float4*>(&As[k][trow]);
            float4 a1 = *reinterpret_cast<const float4*>(&As[k][trow + 4]);
            float4 b0 = *reinterpret_cast<const float4*>(&Bs[k][tcol]);
            float4 b1 = *reinterpret_cast<const float4*>(&Bs[k][tcol + 4]);
            float ar[8] = {a0.x, a0.y, a0.z, a0.w, a1.x, a1.y, a1.z, a1.w};
            float br[8] = {b0.x, b0.y, b0.z, b0.w, b1.x, b1.y, b1.z, b1.w};
#pragma unroll
            for (int i = 0; i < 8; ++i)
#pragma unroll
                for (int j = 0; j < 8; ++j)
                    acc[i][j] = fmaf(ar[i], br[j], acc[i][j]);
        }
        __syncthreads();
    }

#pragma unroll
    for (int i = 0; i < 8; ++i) {
        int gm = bm + trow + i;
        if (gm >= M) break;
#pragma unroll
        for (int j = 0; j < 8; ++j) {
            int gn = bn + tcol + j;
            if (gn < N) C[(size_t)gm * N + gn] = acc[i][j];
        }
    }
}

// ---------------- small helpers ----------------
__global__ void transpose256(const float* __restrict__ in, float* __restrict__ out)
{
    int idx = blockIdx.x * blockDim.x + threadIdx.x;
    if (idx >= 256 * 256) return;
    int j = idx >> 8, k = idx & 255;
    out[j * 256 + k] = in[k * 256 + j];
}

__global__ void scatter_add(const int* __restrict__ fg, const float* __restrict__ m,
                            float* __restrict__ agg, int E)
{
    long long idx = (long long)blockIdx.x * blockDim.x + threadIdx.x;
    long long total = (long long)E * (H / 4);
    if (idx >= total) return;
    int e  = (int)(idx >> 6);
    int c4 = (int)(idx & 63) * 4;
    int src = fg[e];
    int dst = fg[E + e];
    float4 v = *reinterpret_cast<const float4*>(m + (size_t)src * H + c4);
    atomicAdd(reinterpret_cast<float4*>(agg + (size_t)dst * H + c4), v);
}

__global__ void gru_elementwise(const float* __restrict__ gi, const float* __restrict__ gh,
                                const float* __restrict__ emb,
                                const float* __restrict__ bih, const float* __restrict__ bhh,
                                float* __restrict__ hidden, int NNODE)
{
    long long idx = (long long)blockIdx.x * blockDim.x + threadIdx.x;
    if (idx >= (long long)NNODE * H) return;
    int n = (int)(idx >> 8), h = (int)(idx & 255);
    size_t base = (size_t)n * 768;
    float ir = gi[base + h]       + bih[h];
    float hr = gh[base + h]       + bhh[h];
    float iz = gi[base + 256 + h] + bih[256 + h];
    float hz = gh[base + 256 + h] + bhh[256 + h];
    float in_ = gi[base + 512 + h] + bih[512 + h];
    float hn  = gh[base + 512 + h] + bhh[512 + h];
    float r = 1.f / (1.f + expf(-(ir + hr)));
    float z = 1.f / (1.f + expf(-(iz + hz)));
    float nn = tanhf(in_ + r * hn);
    float e = emb[(size_t)n * H + h];
    hidden[(size_t)n * H + h] = (1.f - z) * nn + z * e;
}

__global__ void gather_relu(const int* __restrict__ x, const float* __restrict__ hidden,
                            float* __restrict__ h2, int N)
{
    long long idx = (long long)blockIdx.x * blockDim.x + threadIdx.x;
    if (idx >= (long long)N * H) return;
    int i = (int)(idx >> 8), h = (int)(idx & 255);
    int node = x[i] - 1;
    float v = hidden[(size_t)node * H + h];
    h2[idx] = v > 0.f ? v : 0.f;
}

__global__ void last_max(const int* __restrict__ batch, int* __restrict__ lastidx, int N)
{
    int i = blockIdx.x * blockDim.x + threadIdx.x;
    if (i >= N) return;
    atomicMax(&lastidx[batch[i]], i);
}

__global__ void vn_gather(const float* __restrict__ h2, const int* __restrict__ lastidx,
                          float* __restrict__ vn, int B)
{
    int idx = blockIdx.x * blockDim.x + threadIdx.x;
    if (idx >= B * H) return;
    int b = idx >> 8, h = idx & 255;
    vn[idx] = h2[(size_t)lastidx[b] * H + h];
}

__global__ void attn_kernel(const float* __restrict__ a, const float* __restrict__ bth,
                            const float* __restrict__ h2, const int* __restrict__ batch,
                            const float* __restrict__ W1_b, const float* __restrict__ W2_b,
                            const float* __restrict__ q_w, const float* __restrict__ q_b,
                            float* __restrict__ sg)
{
    __shared__ float red[256];
    int i = blockIdx.x;
    int h = threadIdx.x;
    int b = batch[i];
    float g = a[(size_t)b * H + h] + W1_b[h] + bth[(size_t)i * H + h] + W2_b[h];
    g = 1.f / (1.f + expf(-g));
    red[h] = g * q_w[h];
    __syncthreads();
#pragma unroll
    for (int s = 128; s > 0; s >>= 1) {
        if (h < s) red[h] += red[h + s];
        __syncthreads();
    }
    float alpha = red[0] + q_b[0];
    atomicAdd(&sg[(size_t)b * H + h], alpha * h2[(size_t)i * H + h]);
}

__global__ void concat_vns(const float* __restrict__ vn, const float* __restrict__ sg,
                           float* __restrict__ vns, int B)
{
    int idx = blockIdx.x * blockDim.x + threadIdx.x;
    if (idx >= B * 512) return;
    int b = idx >> 9, c = idx & 511;
    vns[idx] = (c < 256) ? vn[b * 256 + c] : sg[b * 256 + (c - 256)];
}

__global__ void add_bias(float* __restrict__ sh, const float* __restrict__ W3_b, int B)
{
    int idx = blockIdx.x * blockDim.x + threadIdx.x;
    if (idx >= B * H) return;
    sh[idx] += W3_b[idx & 255];
}

__global__ void edges_to_float(const int* __restrict__ ei, float* __restrict__ out, int n)
{
    int idx = blockIdx.x * blockDim.x + threadIdx.x;
    if (idx >= n) return;
    out[idx] = (float)ei[idx];
}

// ---------------- driver ----------------
extern "C" void kernel_launch(void* const* d_in, const int* in_sizes, int n_in,
                              void* d_out, int out_size)
{
    const int*   x      = (const int*)d_in[0];
    const int*   batch  = (const int*)d_in[1];
    const int*   ei     = (const int*)d_in[2];
    const int*   fg     = (const int*)d_in[3];
    const float* emb    = (const float*)d_in[4];
    const float* ggnn_W = (const float*)d_in[5];
    const float* Wih    = (const float*)d_in[6];
    const float* Whh    = (const float*)d_in[7];
    const float* bih    = (const float*)d_in[8];
    const float* bhh    = (const float*)d_in[9];
    const float* W1_w   = (const float*)d_in[10];
    const float* W1_b   = (const float*)d_in[11];
    const float* W2_w   = (const float*)d_in[12];
    const float* W2_b   = (const float*)d_in[13];
    const float* q_w    = (const float*)d_in[14];
    const float* q_b    = (const float*)d_in[15];
    const float* W3_w   = (const float*)d_in[16];
    const float* W3_b   = (const float*)d_in[17];
    float* out = (float*)d_out;

    const int N     = in_sizes[0];          // 12288 session nodes
    const int E     = in_sizes[3] / 2;      // 500000 edges
    const int NNODE = in_sizes[4] / H;      // 50000 items
    const long long scores_elems = (long long)out_size - (long long)N * H - 2LL * N;
    const int B = (int)(scores_elems / NNODE);   // 1024

    float *m, *agg, *gi, *gh, *hidden, *Wt, *vn, *a, *bth, *sg, *vns, *sh;
    int* lastidx;
    cudaGetSymbolAddress((void**)&m,      d_m);
    cudaGetSymbolAddress((void**)&agg,    d_agg);
    cudaGetSymbolAddress((void**)&gi,     d_gi);
    cudaGetSymbolAddress((void**)&gh,     d_gh);
    cudaGetSymbolAddress((void**)&hidden, d_hidden);
    cudaGetSymbolAddress((void**)&Wt,     d_Wt);
    cudaGetSymbolAddress((void**)&vn,     d_vn);
    cudaGetSymbolAddress((void**)&a,      d_a);
    cudaGetSymbolAddress((void**)&bth,    d_bth);
    cudaGetSymbolAddress((void**)&sg,     d_sg);
    cudaGetSymbolAddress((void**)&vns,    d_vns);
    cudaGetSymbolAddress((void**)&sh,     d_sh);
    cudaGetSymbolAddress((void**)&lastidx, d_lastidx);

    float* scores = out;
    float* h2     = out + scores_elems;
    float* eout   = out + scores_elems + (long long)N * H;

    const int T = 256;
    dim3 blk(T);
    auto cdiv = [](long long v, long long d) { return (unsigned)((v + d - 1) / d); };

    // 1) Wt = ggnn_W^T
    transpose256<<<cdiv(256 * 256, T), blk>>>(ggnn_W, Wt);

    // 2) m = emb @ ggnn_W  (tf32 tensor cores)
    gemm_tf32_nt<<<dim3(cdiv(H, 128), cdiv(NNODE, 128)), blk>>>(emb, Wt, m, NNODE, H, H);

    // 3) agg = segment_sum(m[src], dst)
    cudaMemsetAsync(agg, 0, (size_t)NNODE * H * sizeof(float));
    scatter_add<<<cdiv((long long)E * (H / 4), T), blk>>>(fg, m, agg, E);

    // 4) gi = agg @ Wih^T ; gh = emb @ Whh^T (tf32)
    gemm_tf32_nt<<<dim3(cdiv(3 * H, 128), cdiv(NNODE, 128)), blk>>>(agg, Wih, gi, NNODE, 3 * H, H);
    gemm_tf32_nt<<<dim3(cdiv(3 * H, 128), cdiv(NNODE, 128)), blk>>>(emb, Whh, gh, NNODE, 3 * H, H);

    // 5) GRU cell -> hidden_all
    gru_elementwise<<<cdiv((long long)NNODE * H, T), blk>>>(gi, gh, emb, bih, bhh, hidden, NNODE);

    // 6) h2 = relu(hidden[x-1])
    gather_relu<<<cdiv((long long)N * H, T), blk>>>(x, hidden, h2, N);

    // 7) last node per session
    cudaMemsetAsync(lastidx, 0xFF, (size_t)B * sizeof(int));
    last_max<<<cdiv(N, T), blk>>>(batch, lastidx, N);
    vn_gather<<<cdiv(B * H, T), blk>>>(h2, lastidx, vn, B);

    // 8) attention
    gemm_nt<<<dim3(cdiv(H, 128), cdiv(B, 128)), blk>>>(vn, W1_w, a, B, H, H);
    gemm_tf32_nt<<<dim3(cdiv(H, 128), cdiv(N, 128)), blk>>>(h2, W2_w, bth, N, H, H);
    cudaMemsetAsync(sg, 0, (size_t)B * H * sizeof(float));
    attn_kernel<<<N, blk>>>(a, bth, h2, batch, W1_b, W2_b, q_w, q_b, sg);

    // 9) s_h = [vn | s_g] @ W3^T + b3  (small, fp32)
    concat_vns<<<cdiv(B * 512, T), blk>>>(vn, sg, vns, B);
    gemm_nt<<<dim3(cdiv(H, 128), cdiv(B, 128)), blk>>>(vns, W3_w, sh, B, H, 2 * H);
    add_bias<<<cdiv(B * H, T), blk>>>(sh, W3_b, B);

    // 10) scores = s_h @ emb^T  (tf32)
    gemm_tf32_nt<<<dim3(cdiv(NNODE, 128), cdiv(B, 128)), blk>>>(sh, emb, scores, B, NNODE, H);

    // 11) passthrough edge_index as float
    edges_to_float<<<cdiv(2 * N, T), blk>>>(ei, eout, 2 * N);
}

// round 4
// speedup vs baseline: 2.5041x; 1.1215x over previous
#include <cuda_runtime.h>
#include <cstdint>
#include <cstddef>

#define H 256

// ---------------- scratch (static device allocations; no cudaMalloc) ----------------
__device__ float d_m[50000 * 256];
__device__ float d_agg[50000 * 256];
__device__ float d_gi[50000 * 768];
__device__ float d_gh[50000 * 768];
__device__ float d_hidden[50000 * 256];
__device__ float d_Wt[256 * 256];
__device__ float d_vn[1024 * 256];
__device__ float d_a[1024 * 256];
__device__ float d_bth[12288 * 256];
__device__ float d_sg[1024 * 256];
__device__ float d_vns[1024 * 512];
__device__ float d_sh[1024 * 256];
__device__ int   d_lastidx[1024];

// ---------------- tf32 / async helpers ----------------
__device__ __forceinline__ unsigned f2tf(float f) {
    unsigned u;
    asm("cvt.rna.tf32.f32 %0, %1;" : "=r"(u) : "f"(f));
    return u;
}
__device__ __forceinline__ unsigned f2tf_u(unsigned x) {
    unsigned u;
    asm("cvt.rna.tf32.f32 %0, %1;" : "=r"(u) : "f"(__uint_as_float(x)));
    return u;
}
__device__ __forceinline__ void ldm_x4(unsigned r[4], unsigned addr) {
    asm volatile("ldmatrix.sync.aligned.m8n8.x4.shared.b16 {%0,%1,%2,%3}, [%4];"
                 : "=r"(r[0]), "=r"(r[1]), "=r"(r[2]), "=r"(r[3]) : "r"(addr));
}
__device__ __forceinline__ void mma_tf32(float d[4], const unsigned a[4], const unsigned b[2]) {
    asm volatile("mma.sync.aligned.m16n8k8.row.col.f32.tf32.tf32.f32 "
                 "{%0,%1,%2,%3}, {%4,%5,%6,%7}, {%8,%9}, {%0,%1,%2,%3};"
                 : "+f"(d[0]), "+f"(d[1]), "+f"(d[2]), "+f"(d[3])
                 : "r"(a[0]), "r"(a[1]), "r"(a[2]), "r"(a[3]), "r"(b[0]), "r"(b[1]));
}
__device__ __forceinline__ void cp_async16(unsigned saddr, const void* gptr) {
    asm volatile("cp.async.cg.shared.global [%0], [%1], 16;" :: "r"(saddr), "l"(gptr));
}

// ---------------- tf32 tensor-core NT GEMM, cp.async double-buffered ----------------
// C[m,n] = sum_k A[m,k]*B[n,k]. Block tile 128(M) x 256(N), BK=32, 8 warps of 64x64.
// K % 32 == 0. Dynamic smem: 2 stages * (128+256) rows * 36 floats.
#define PADW 36
#define ASTAGE_F (128 * PADW)
#define BOFF_F   (2 * ASTAGE_F)
#define BSTAGE_F (256 * PADW)
#define SMEM_BYTES ((BOFF_F + 2 * BSTAGE_F) * 4)

__global__ __launch_bounds__(256, 1) void gemm_tf32_nt(
    const float* __restrict__ A, const float* __restrict__ B,
    float* __restrict__ C, int M, int N, int K)
{
    extern __shared__ float sm[];
    const unsigned smu = (unsigned)__cvta_generic_to_shared(sm);

    const int tid  = threadIdx.x;
    const int warp = tid >> 5;
    const int lane = tid & 31;
    const int bm = blockIdx.y * 128;
    const int bn = blockIdx.x * 256;
    const int wm = (warp & 1) * 64;     // 2 warps along M
    const int wn = (warp >> 1) * 64;    // 4 warps along N

    float acc[4][8][4];
#pragma unroll
    for (int i = 0; i < 4; ++i)
#pragma unroll
        for (int j = 0; j < 8; ++j)
#pragma unroll
            for (int v = 0; v < 4; ++v) acc[i][j][v] = 0.f;

    // loader coordinates (16B chunks)
    int arow[4], acol[4];
    const float* agp[4];
#pragma unroll
    for (int i = 0; i < 4; ++i) {
        int lin = tid + i * 256;
        arow[i] = lin >> 3;
        acol[i] = (lin & 7) << 2;
        int gm = bm + arow[i]; gm = gm < M ? gm : M - 1;
        agp[i] = A + (size_t)gm * K + acol[i];
    }
    int brow[8], bcol[8];
    const float* bgp[8];
#pragma unroll
    for (int i = 0; i < 8; ++i) {
        int lin = tid + i * 256;
        brow[i] = lin >> 3;
        bcol[i] = (lin & 7) << 2;
        int gn = bn + brow[i]; gn = gn < N ? gn : N - 1;
        bgp[i] = B + (size_t)gn * K + bcol[i];
    }

    // ldmatrix warp base addresses (bytes)
    const unsigned aBase = smu + ((wm + (lane & 15)) * PADW + ((lane >> 4) << 2)) * 4u;
    const unsigned bBase = smu + (BOFF_F +
        (wn + ((lane >> 4) << 3) + (lane & 7)) * PADW + (((lane >> 3) & 1) << 2)) * 4u;

    const int KT = K >> 5;

    // prefetch stage 0
#pragma unroll
    for (int i = 0; i < 4; ++i)
        cp_async16(smu + (arow[i] * PADW + acol[i]) * 4u, agp[i]);
#pragma unroll
    for (int i = 0; i < 8; ++i)
        cp_async16(smu + (BOFF_F + brow[i] * PADW + bcol[i]) * 4u, bgp[i]);
    asm volatile("cp.async.commit_group;");

    for (int kt = 0; kt < KT; ++kt) {
        if (kt + 1 < KT) {
            int s = (kt + 1) & 1;
            int k0 = (kt + 1) << 5;
#pragma unroll
            for (int i = 0; i < 4; ++i)
                cp_async16(smu + (s * ASTAGE_F + arow[i] * PADW + acol[i]) * 4u, agp[i] + k0);
#pragma unroll
            for (int i = 0; i < 8; ++i)
                cp_async16(smu + (BOFF_F + s * BSTAGE_F + brow[i] * PADW + bcol[i]) * 4u, bgp[i] + k0);
            asm volatile("cp.async.commit_group;");
            asm volatile("cp.async.wait_group 1;");
        } else {
            asm volatile("cp.async.wait_group 0;");
        }
        __syncthreads();

        const int s = kt & 1;
        const unsigned aw = aBase + s * (ASTAGE_F * 4u);
        const unsigned bw = bBase + s * (BSTAGE_F * 4u);
#pragma unroll
        for (int kk = 0; kk < 32; kk += 8) {
            unsigned af[4][4];
            unsigned bf[8][2];
#pragma unroll
            for (int mi = 0; mi < 4; ++mi) {
                ldm_x4(af[mi], aw + (mi * 16 * PADW + kk) * 4u);
#pragma unroll
                for (int v = 0; v < 4; ++v) af[mi][v] = f2tf_u(af[mi][v]);
            }
#pragma unroll
            for (int p = 0; p < 4; ++p) {
                unsigned t[4];
                ldm_x4(t, bw + (p * 16 * PADW + kk) * 4u);
#pragma unroll
                for (int v = 0; v < 4; ++v) t[v] = f2tf_u(t[v]);
                bf[p * 2][0] = t[0]; bf[p * 2][1] = t[1];
                bf[p * 2 + 1][0] = t[2]; bf[p * 2 + 1][1] = t[3];
            }
#pragma unroll
            for (int mi = 0; mi < 4; ++mi)
#pragma unroll
                for (int nj = 0; nj < 8; ++nj)
                    mma_tf32(acc[mi][nj], af[mi], bf[nj]);
        }
        __syncthreads();
    }

    // epilogue
#pragma unroll
    for (int mi = 0; mi < 4; ++mi) {
        int gm0 = bm + wm + mi * 16 + (lane >> 2);
#pragma unroll
        for (int nj = 0; nj < 8; ++nj) {
            int gn = bn + wn + nj * 8 + ((lane & 3) << 1);
            if (gn < N) {
                if (gm0 < M)
                    *reinterpret_cast<float2*>(&C[(size_t)gm0 * N + gn]) =
                        make_float2(acc[mi][nj][0], acc[mi][nj][1]);
                if (gm0 + 8 < M)
                    *reinterpret_cast<float2*>(&C[(size_t)(gm0 + 8) * N + gn]) =
                        make_float2(acc[mi][nj][2], acc[mi][nj][3]);
            }
        }
    }
}

// ---------------- fp32 fallback GEMM for tiny matrices ----------------
#define BK 16
__global__ __launch_bounds__(256) void gemm_nt(
    const float* __restrict__ A, const float* __restrict__ B,
    float* __restrict__ C, int M, int N, int K)
{
    __shared__ float As[BK][128];
    __shared__ float Bs[BK][128];
    const int bm = blockIdx.y * 128;
    const int bn = blockIdx.x * 128;
    const int tid = threadIdx.x;
    const int tcol = (tid & 15) * 8;
    const int trow = (tid >> 4) * 8;

    float acc[8][8];
#pragma unroll
    for (int i = 0; i < 8; ++i)
#pragma unroll
        for (int j = 0; j < 8; ++j) acc[i][j] = 0.f;

    for (int k0 = 0; k0 < K; k0 += BK) {
#pragma unroll
        for (int it = 0; it < 2; ++it) {
            int lin = tid + it * 256;
            int r  = lin >> 2;
            int c4 = (lin & 3) << 2;
            int gm = bm + r; gm = gm < M ? gm : M - 1;
            float4 va = *reinterpret_cast<const float4*>(A + (size_t)gm * K + k0 + c4);
            As[c4 + 0][r] = va.x; As[c4 + 1][r] = va.y;
            As[c4 + 2][r] = va.z; As[c4 + 3][r] = va.w;
            int gn = bn + r; gn = gn < N ? gn : N - 1;
            float4 vb = *reinterpret_cast<const float4*>(B + (size_t)gn * K + k0 + c4);
            Bs[c4 + 0][r] = vb.x; Bs[c4 + 1][r] = vb.y;
            Bs[c4 + 2][r] = vb.z; Bs[c4 + 3][r] = vb.w;
        }
        __syncthreads();
#pragma unroll
        for (int k = 0; k < BK; ++k) {
            float4 a0 = *reinterpret_cast<const float4*>(&As[k][trow]);
            float4 a1 = *reinterpret_cast<const float4*>(&As[k][trow + 4]);
            float4 b0 = *reinterpret_cast<const float4*>(&Bs[k][tcol]);
            float4 b1 = *reinterpret_cast<const float4*>(&Bs[k][tcol + 4]);
            float ar[8] = {a0.x, a0.y, a0.z, a0.w, a1.x, a1.y, a1.z, a1.w};
            float br[8] = {b0.x, b0.y, b0.z, b0.w, b1.x, b1.y, b1.z, b1.w};
#pragma unroll
            for (int i = 0; i < 8; ++i)
#pragma unroll
                for (int j = 0; j < 8; ++j)
                    acc[i][j] = fmaf(ar[i], br[j], acc[i][j]);
        }
        __syncthreads();
    }

#pragma unroll
    for (int i = 0; i < 8; ++i) {
        int gm = bm + trow + i;
        if (gm >= M) break;
#pragma unroll
        for (int j = 0; j < 8; ++j) {
            int gn = bn + tcol + j;
            if (gn < N) C[(size_t)gm * N + gn] = acc[i][j];
        }
    }
}

// ---------------- small helpers ----------------
__global__ void transpose256(const float* __restrict__ in, float* __restrict__ out)
{
    int idx = blockIdx.x * blockDim.x + threadIdx.x;
    if (idx >= 256 * 256) return;
    int j = idx >> 8, k = idx & 255;
    out[j * 256 + k] = in[k * 256 + j];
}

__global__ void scatter_add(const int* __restrict__ fg, const float* __restrict__ m,
                            float* __restrict__ agg, int E)
{
    long long idx = (long long)blockIdx.x * blockDim.x + threadIdx.x;
    long long total = (long long)E * (H / 4);
    if (idx >= total) return;
    int e  = (int)(idx >> 6);
    int c4 = (int)(idx & 63) * 4;
    int src = fg[e];
    int dst = fg[E + e];
    float4 v = *reinterpret_cast<const float4*>(m + (size_t)src * H + c4);
    atomicAdd(reinterpret_cast<float4*>(agg + (size_t)dst * H + c4), v);
}

__global__ void gru_elementwise(const float* __restrict__ gi, const float* __restrict__ gh,
                                const float* __restrict__ emb,
                                const float* __restrict__ bih, const float* __restrict__ bhh,
                                float* __restrict__ hidden, int NNODE)
{
    long long idx = (long long)blockIdx.x * blockDim.x + threadIdx.x;
    if (idx >= (long long)NNODE * H) return;
    int n = (int)(idx >> 8), h = (int)(idx & 255);
    size_t base = (size_t)n * 768;
    float ir = gi[base + h]       + bih[h];
    float hr = gh[base + h]       + bhh[h];
    float iz = gi[base + 256 + h] + bih[256 + h];
    float hz = gh[base + 256 + h] + bhh[256 + h];
    float in_ = gi[base + 512 + h] + bih[512 + h];
    float hn  = gh[base + 512 + h] + bhh[512 + h];
    float r = 1.f / (1.f + expf(-(ir + hr)));
    float z = 1.f / (1.f + expf(-(iz + hz)));
    float nn = tanhf(in_ + r * hn);
    float e = emb[(size_t)n * H + h];
    hidden[(size_t)n * H + h] = (1.f - z) * nn + z * e;
}

__global__ void gather_relu(const int* __restrict__ x, const float* __restrict__ hidden,
                            float* __restrict__ h2, int N)
{
    long long idx = (long long)blockIdx.x * blockDim.x + threadIdx.x;
    if (idx >= (long long)N * H) return;
    int i = (int)(idx >> 8), h = (int)(idx & 255);
    int node = x[i] - 1;
    float v = hidden[(size_t)node * H + h];
    h2[idx] = v > 0.f ? v : 0.f;
}

__global__ void last_max(const int* __restrict__ batch, int* __restrict__ lastidx, int N)
{
    int i = blockIdx.x * blockDim.x + threadIdx.x;
    if (i >= N) return;
    atomicMax(&lastidx[batch[i]], i);
}

__global__ void vn_gather(const float* __restrict__ h2, const int* __restrict__ lastidx,
                          float* __restrict__ vn, int B)
{
    int idx = blockIdx.x * blockDim.x + threadIdx.x;
    if (idx >= B * H) return;
    int b = idx >> 8, h = idx & 255;
    vn[idx] = h2[(size_t)lastidx[b] * H + h];
}

__global__ void attn_kernel(const float* __restrict__ a, const float* __restrict__ bth,
                            const float* __restrict__ h2, const int* __restrict__ batch,
                            const float* __restrict__ W1_b, const float* __restrict__ W2_b,
                            const float* __restrict__ q_w, const float* __restrict__ q_b,
                            float* __restrict__ sg)
{
    __shared__ float red[256];
    int i = blockIdx.x;
    int h = threadIdx.x;
    int b = batch[i];
    float g = a[(size_t)b * H + h] + W1_b[h] + bth[(size_t)i * H + h] + W2_b[h];
    g = 1.f / (1.f + expf(-g));
    red[h] = g * q_w[h];
    __syncthreads();
#pragma unroll
    for (int s = 128; s > 0; s >>= 1) {
        if (h < s) red[h] += red[h + s];
        __syncthreads();
    }
    float alpha = red[0] + q_b[0];
    atomicAdd(&sg[(size_t)b * H + h], alpha * h2[(size_t)i * H + h]);
}

__global__ void concat_vns(const float* __restrict__ vn, const float* __restrict__ sg,
                           float* __restrict__ vns, int B)
{
    int idx = blockIdx.x * blockDim.x + threadIdx.x;
    if (idx >= B * 512) return;
    int b = idx >> 9, c = idx & 511;
    vns[idx] = (c < 256) ? vn[b * 256 + c] : sg[b * 256 + (c - 256)];
}

__global__ void add_bias(float* __restrict__ sh, const float* __restrict__ W3_b, int B)
{
    int idx = blockIdx.x * blockDim.x + threadIdx.x;
    if (idx >= B * H) return;
    sh[idx] += W3_b[idx & 255];
}

__global__ void edges_to_float(const int* __restrict__ ei, float* __restrict__ out, int n)
{
    int idx = blockIdx.x * blockDim.x + threadIdx.x;
    if (idx >= n) return;
    out[idx] = (float)ei[idx];
}

// ---------------- driver ----------------
extern "C" void kernel_launch(void* const* d_in, const int* in_sizes, int n_in,
                              void* d_out, int out_size)
{
    const int*   x      = (const int*)d_in[0];
    const int*   batch  = (const int*)d_in[1];
    const int*   ei     = (const int*)d_in[2];
    const int*   fg     = (const int*)d_in[3];
    const float* emb    = (const float*)d_in[4];
    const float* ggnn_W = (const float*)d_in[5];
    const float* Wih    = (const float*)d_in[6];
    const float* Whh    = (const float*)d_in[7];
    const float* bih    = (const float*)d_in[8];
    const float* bhh    = (const float*)d_in[9];
    const float* W1_w   = (const float*)d_in[10];
    const float* W1_b   = (const float*)d_in[11];
    const float* W2_w   = (const float*)d_in[12];
    const float* W2_b   = (const float*)d_in[13];
    const float* q_w    = (const float*)d_in[14];
    const float* q_b    = (const float*)d_in[15];
    const float* W3_w   = (const float*)d_in[16];
    const float* W3_b   = (const float*)d_in[17];
    float* out = (float*)d_out;

    const int N     = in_sizes[0];          // 12288 session nodes
    const int E     = in_sizes[3] / 2;      // 500000 edges
    const int NNODE = in_sizes[4] / H;      // 50000 items
    const long long scores_elems = (long long)out_size - (long long)N * H - 2LL * N;
    const int B = (int)(scores_elems / NNODE);   // 1024

    static int smem_set = 0;
    if (!smem_set) {
        cudaFuncSetAttribute(gemm_tf32_nt, cudaFuncAttributeMaxDynamicSharedMemorySize, SMEM_BYTES);
        smem_set = 1;
    }

    float *m, *agg, *gi, *gh, *hidden, *Wt, *vn, *a, *bth, *sg, *vns, *sh;
    int* lastidx;
    cudaGetSymbolAddress((void**)&m,      d_m);
    cudaGetSymbolAddress((void**)&agg,    d_agg);
    cudaGetSymbolAddress((void**)&gi,     d_gi);
    cudaGetSymbolAddress((void**)&gh,     d_gh);
    cudaGetSymbolAddress((void**)&hidden, d_hidden);
    cudaGetSymbolAddress((void**)&Wt,     d_Wt);
    cudaGetSymbolAddress((void**)&vn,     d_vn);
    cudaGetSymbolAddress((void**)&a,      d_a);
    cudaGetSymbolAddress((void**)&bth,    d_bth);
    cudaGetSymbolAddress((void**)&sg,     d_sg);
    cudaGetSymbolAddress((void**)&vns,    d_vns);
    cudaGetSymbolAddress((void**)&sh,     d_sh);
    cudaGetSymbolAddress((void**)&lastidx, d_lastidx);

    float* scores = out;
    float* h2     = out + scores_elems;
    float* eout   = out + scores_elems + (long long)N * H;

    const int T = 256;
    dim3 blk(T);
    auto cdiv = [](long long v, long long d) { return (unsigned)((v + d - 1) / d); };

    // 1) Wt = ggnn_W^T
    transpose256<<<cdiv(256 * 256, T), blk>>>(ggnn_W, Wt);

    // 2) m = emb @ ggnn_W  (tf32 tensor cores)
    gemm_tf32_nt<<<dim3(cdiv(H, 256), cdiv(NNODE, 128)), blk, SMEM_BYTES>>>(emb, Wt, m, NNODE, H, H);

    // 3) agg = segment_sum(m[src], dst)
    cudaMemsetAsync(agg, 0, (size_t)NNODE * H * sizeof(float));
    scatter_add<<<cdiv((long long)E * (H / 4), T), blk>>>(fg, m, agg, E);

    // 4) gi = agg @ Wih^T ; gh = emb @ Whh^T (tf32)
    gemm_tf32_nt<<<dim3(cdiv(3 * H, 256), cdiv(NNODE, 128)), blk, SMEM_BYTES>>>(agg, Wih, gi, NNODE, 3 * H, H);
    gemm_tf32_nt<<<dim3(cdiv(3 * H, 256), cdiv(NNODE, 128)), blk, SMEM_BYTES>>>(emb, Whh, gh, NNODE, 3 * H, H);

    // 5) GRU cell -> hidden_all
    gru_elementwise<<<cdiv((long long)NNODE * H, T), blk>>>(gi, gh, emb, bih, bhh, hidden, NNODE);

    // 6) h2 = relu(hidden[x-1])
    gather_relu<<<cdiv((long long)N * H, T), blk>>>(x, hidden, h2, N);

    // 7) last node per session
    cudaMemsetAsync(lastidx, 0xFF, (size_t)B * sizeof(int));
    last_max<<<cdiv(N, T), blk>>>(batch, lastidx, N);
    vn_gather<<<cdiv(B * H, T), blk>>>(h2, lastidx, vn, B);

    // 8) attention
    gemm_nt<<<dim3(cdiv(H, 128), cdiv(B, 128)), blk>>>(vn, W1_w, a, B, H, H);
    gemm_tf32_nt<<<dim3(cdiv(H, 256), cdiv(N, 128)), blk, SMEM_BYTES>>>(h2, W2_w, bth, N, H, H);
    cudaMemsetAsync(sg, 0, (size_t)B * H * sizeof(float));
    attn_kernel<<<N, blk>>>(a, bth, h2, batch, W1_b, W2_b, q_w, q_b, sg);

    // 9) s_h = [vn | s_g] @ W3^T + b3  (small, fp32)
    concat_vns<<<cdiv(B * 512, T), blk>>>(vn, sg, vns, B);
    gemm_nt<<<dim3(cdiv(H, 128), cdiv(B, 128)), blk>>>(vns, W3_w, sh, B, H, 2 * H);
    add_bias<<<cdiv(B * H, T), blk>>>(sh, W3_b, B);

    // 10) scores = s_h @ emb^T  (tf32)
    gemm_tf32_nt<<<dim3(cdiv(NNODE, 256), cdiv(B, 128)), blk, SMEM_BYTES>>>(sh, emb, scores, B, NNODE, H);

    // 11) passthrough edge_index as float
    edges_to_float<<<cdiv(2 * N, T), blk>>>(ei, eout, 2 * N);
}

// round 5
// speedup vs baseline: 2.6816x; 1.0709x over previous
#include <cuda_runtime.h>
#include <cstdint>
#include <cstddef>

#define H 256

// ---------------- scratch (static device allocations; no cudaMalloc) ----------------
__device__ float d_m[50000 * 256];
__device__ float d_agg[50000 * 256];
__device__ float d_gi[50000 * 768];
__device__ float d_gh[50000 * 768];
__device__ float d_hidden[50000 * 256];
__device__ float d_Wt[256 * 256];
__device__ float d_vn[1024 * 256];
__device__ float d_a[1024 * 256];
__device__ float d_bth[12288 * 256];
__device__ float d_sg[1024 * 256];
__device__ float d_vns[1024 * 512];
__device__ float d_sh[1024 * 256];
__device__ int   d_lastidx[1024];

// ---------------- tf32 / async helpers ----------------
__device__ __forceinline__ unsigned f2tf_u(unsigned x) {
    unsigned u;
    asm("cvt.rna.tf32.f32 %0, %1;" : "=r"(u) : "f"(__uint_as_float(x)));
    return u;
}
__device__ __forceinline__ void ldm_x4(unsigned r[4], unsigned addr) {
    asm volatile("ldmatrix.sync.aligned.m8n8.x4.shared.b16 {%0,%1,%2,%3}, [%4];"
                 : "=r"(r[0]), "=r"(r[1]), "=r"(r[2]), "=r"(r[3]) : "r"(addr));
}
__device__ __forceinline__ void mma_tf32(float d[4], const unsigned a[4], const unsigned b[2]) {
    asm volatile("mma.sync.aligned.m16n8k8.row.col.f32.tf32.tf32.f32 "
                 "{%0,%1,%2,%3}, {%4,%5,%6,%7}, {%8,%9}, {%0,%1,%2,%3};"
                 : "+f"(d[0]), "+f"(d[1]), "+f"(d[2]), "+f"(d[3])
                 : "r"(a[0]), "r"(a[1]), "r"(a[2]), "r"(a[3]), "r"(b[0]), "r"(b[1]));
}
__device__ __forceinline__ void cp_async16(unsigned saddr, const void* gptr) {
    asm volatile("cp.async.cg.shared.global [%0], [%1], 16;" :: "r"(saddr), "l"(gptr));
}

// ---------------- tf32 tensor-core NT GEMM, cp.async double-buffered ----------------
// C[m,n] = sum_k A[m,k]*B[n,k]. Block tile 128(M) x 128(N), BK=32, 8 warps of 64x32.
// 2 CTAs/SM. K % 32 == 0. Dynamic smem: 2 stages * (128+128) rows * 36 floats = 73.7KB.
#define PADW 36
#define ASTAGE_F (128 * PADW)
#define BOFF_F   (2 * ASTAGE_F)
#define BSTAGE_F (128 * PADW)
#define SMEM_BYTES ((BOFF_F + 2 * BSTAGE_F) * 4)

__global__ __launch_bounds__(256, 2) void gemm_tf32_nt(
    const float* __restrict__ A, const float* __restrict__ B,
    float* __restrict__ C, int M, int N, int K)
{
    extern __shared__ float sm[];
    const unsigned smu = (unsigned)__cvta_generic_to_shared(sm);

    const int tid  = threadIdx.x;
    const int warp = tid >> 5;
    const int lane = tid & 31;
    const int bm = blockIdx.y * 128;
    const int bn = blockIdx.x * 128;
    const int wm = (warp & 1) * 64;     // 2 warps along M
    const int wn = (warp >> 1) * 32;    // 4 warps along N

    float acc[4][4][4];
#pragma unroll
    for (int i = 0; i < 4; ++i)
#pragma unroll
        for (int j = 0; j < 4; ++j)
#pragma unroll
            for (int v = 0; v < 4; ++v) acc[i][j][v] = 0.f;

    // loader coordinates (16B chunks): A and B each 128 rows x 32 floats per stage
    int arow[4], acol[4];
    const float* agp[4];
    const float* bgp[4];
#pragma unroll
    for (int i = 0; i < 4; ++i) {
        int lin = tid + i * 256;
        arow[i] = lin >> 3;
        acol[i] = (lin & 7) << 2;
        int gm = bm + arow[i]; gm = gm < M ? gm : M - 1;
        agp[i] = A + (size_t)gm * K + acol[i];
        int gn = bn + arow[i]; gn = gn < N ? gn : N - 1;
        bgp[i] = B + (size_t)gn * K + acol[i];
    }

    // ldmatrix warp base addresses (bytes)
    const unsigned aBase = smu + ((wm + (lane & 15)) * PADW + ((lane >> 4) << 2)) * 4u;
    const unsigned bBase = smu + (BOFF_F +
        (wn + ((lane >> 4) << 3) + (lane & 7)) * PADW + (((lane >> 3) & 1) << 2)) * 4u;

    const int KT = K >> 5;

    // prefetch stage 0
#pragma unroll
    for (int i = 0; i < 4; ++i) {
        cp_async16(smu + (arow[i] * PADW + acol[i]) * 4u, agp[i]);
        cp_async16(smu + (BOFF_F + arow[i] * PADW + acol[i]) * 4u, bgp[i]);
    }
    asm volatile("cp.async.commit_group;");

    for (int kt = 0; kt < KT; ++kt) {
        if (kt + 1 < KT) {
            int s = (kt + 1) & 1;
            int k0 = (kt + 1) << 5;
#pragma unroll
            for (int i = 0; i < 4; ++i) {
                cp_async16(smu + (s * ASTAGE_F + arow[i] * PADW + acol[i]) * 4u, agp[i] + k0);
                cp_async16(smu + (BOFF_F + s * BSTAGE_F + arow[i] * PADW + acol[i]) * 4u, bgp[i] + k0);
            }
            asm volatile("cp.async.commit_group;");
            asm volatile("cp.async.wait_group 1;");
        } else {
            asm volatile("cp.async.wait_group 0;");
        }
        __syncthreads();

        const int s = kt & 1;
        const unsigned aw = aBase + s * (ASTAGE_F * 4u);
        const unsigned bw = bBase + s * (BSTAGE_F * 4u);
#pragma unroll
        for (int kk = 0; kk < 32; kk += 8) {
            unsigned af[4][4];
            unsigned bf[4][2];
#pragma unroll
            for (int mi = 0; mi < 4; ++mi) {
                ldm_x4(af[mi], aw + (mi * 16 * PADW + kk) * 4u);
#pragma unroll
                for (int v = 0; v < 4; ++v) af[mi][v] = f2tf_u(af[mi][v]);
            }
#pragma unroll
            for (int p = 0; p < 2; ++p) {
                unsigned t[4];
                ldm_x4(t, bw + (p * 16 * PADW + kk) * 4u);
#pragma unroll
                for (int v = 0; v < 4; ++v) t[v] = f2tf_u(t[v]);
                bf[p * 2][0] = t[0]; bf[p * 2][1] = t[1];
                bf[p * 2 + 1][0] = t[2]; bf[p * 2 + 1][1] = t[3];
            }
#pragma unroll
            for (int mi = 0; mi < 4; ++mi)
#pragma unroll
                for (int nj = 0; nj < 4; ++nj)
                    mma_tf32(acc[mi][nj], af[mi], bf[nj]);
        }
        __syncthreads();
    }

    // epilogue
#pragma unroll
    for (int mi = 0; mi < 4; ++mi) {
        int gm0 = bm + wm + mi * 16 + (lane >> 2);
#pragma unroll
        for (int nj = 0; nj < 4; ++nj) {
            int gn = bn + wn + nj * 8 + ((lane & 3) << 1);
            if (gn < N) {
                if (gm0 < M)
                    *reinterpret_cast<float2*>(&C[(size_t)gm0 * N + gn]) =
                        make_float2(acc[mi][nj][0], acc[mi][nj][1]);
                if (gm0 + 8 < M)
                    *reinterpret_cast<float2*>(&C[(size_t)(gm0 + 8) * N + gn]) =
                        make_float2(acc[mi][nj][2], acc[mi][nj][3]);
            }
        }
    }
}

// ---------------- fp32 fallback GEMM for tiny matrices ----------------
#define BK 16
__global__ __launch_bounds__(256) void gemm_nt(
    const float* __restrict__ A, const float* __restrict__ B,
    float* __restrict__ C, int M, int N, int K)
{
    __shared__ float As[BK][128];
    __shared__ float Bs[BK][128];
    const int bm = blockIdx.y * 128;
    const int bn = blockIdx.x * 128;
    const int tid = threadIdx.x;
    const int tcol = (tid & 15) * 8;
    const int trow = (tid >> 4) * 8;

    float acc[8][8];
#pragma unroll
    for (int i = 0; i < 8; ++i)
#pragma unroll
        for (int j = 0; j < 8; ++j) acc[i][j] = 0.f;

    for (int k0 = 0; k0 < K; k0 += BK) {
#pragma unroll
        for (int it = 0; it < 2; ++it) {
            int lin = tid + it * 256;
            int r  = lin >> 2;
            int c4 = (lin & 3) << 2;
            int gm = bm + r; gm = gm < M ? gm : M - 1;
            float4 va = *reinterpret_cast<const float4*>(A + (size_t)gm * K + k0 + c4);
            As[c4 + 0][r] = va.x; As[c4 + 1][r] = va.y;
            As[c4 + 2][r] = va.z; As[c4 + 3][r] = va.w;
            int gn = bn + r; gn = gn < N ? gn : N - 1;
            float4 vb = *reinterpret_cast<const float4*>(B + (size_t)gn * K + k0 + c4);
            Bs[c4 + 0][r] = vb.x; Bs[c4 + 1][r] = vb.y;
            Bs[c4 + 2][r] = vb.z; Bs[c4 + 3][r] = vb.w;
        }
        __syncthreads();
#pragma unroll
        for (int k = 0; k < BK; ++k) {
            float4 a0 = *reinterpret_cast<const float4*>(&As[k][trow]);
            float4 a1 = *reinterpret_cast<const float4*>(&As[k][trow + 4]);
            float4 b0 = *reinterpret_cast<const float4*>(&Bs[k][tcol]);
            float4 b1 = *reinterpret_cast<const float4*>(&Bs[k][tcol + 4]);
            float ar[8] = {a0.x, a0.y, a0.z, a0.w, a1.x, a1.y, a1.z, a1.w};
            float br[8] = {b0.x, b0.y, b0.z, b0.w, b1.x, b1.y, b1.z, b1.w};
#pragma unroll
            for (int i = 0; i < 8; ++i)
#pragma unroll
                for (int j = 0; j < 8; ++j)
                    acc[i][j] = fmaf(ar[i], br[j], acc[i][j]);
        }
        __syncthreads();
    }

#pragma unroll
    for (int i = 0; i < 8; ++i) {
        int gm = bm + trow + i;
        if (gm >= M) break;
#pragma unroll
        for (int j = 0; j < 8; ++j) {
            int gn = bn + tcol + j;
            if (gn < N) C[(size_t)gm * N + gn] = acc[i][j];
        }
    }
}

// ---------------- small helpers ----------------
__global__ void transpose256(const float* __restrict__ in, float* __restrict__ out)
{
    int idx = blockIdx.x * blockDim.x + threadIdx.x;
    if (idx >= 256 * 256) return;
    int j = idx >> 8, k = idx & 255;
    out[j * 256 + k] = in[k * 256 + j];
}

__global__ void scatter_add(const int* __restrict__ fg, const float* __restrict__ m,
                            float* __restrict__ agg, int E)
{
    long long idx = (long long)blockIdx.x * blockDim.x + threadIdx.x;
    long long total = (long long)E * (H / 4);
    if (idx >= total) return;
    int e  = (int)(idx >> 6);
    int c4 = (int)(idx & 63) * 4;
    int src = fg[e];
    int dst = fg[E + e];
    float4 v = *reinterpret_cast<const float4*>(m + (size_t)src * H + c4);
    atomicAdd(reinterpret_cast<float4*>(agg + (size_t)dst * H + c4), v);
}

__global__ void gru_elementwise(const float* __restrict__ gi, const float* __restrict__ gh,
                                const float* __restrict__ emb,
                                const float* __restrict__ bih, const float* __restrict__ bhh,
                                float* __restrict__ hidden, int NNODE)
{
    long long idx = (long long)blockIdx.x * blockDim.x + threadIdx.x;
    if (idx >= (long long)NNODE * H) return;
    int n = (int)(idx >> 8), h = (int)(idx & 255);
    size_t base = (size_t)n * 768;
    float ir = gi[base + h]       + bih[h];
    float hr = gh[base + h]       + bhh[h];
    float iz = gi[base + 256 + h] + bih[256 + h];
    float hz = gh[base + 256 + h] + bhh[256 + h];
    float in_ = gi[base + 512 + h] + bih[512 + h];
    float hn  = gh[base + 512 + h] + bhh[512 + h];
    float r = 1.f / (1.f + expf(-(ir + hr)));
    float z = 1.f / (1.f + expf(-(iz + hz)));
    float nn = tanhf(in_ + r * hn);
    float e = emb[(size_t)n * H + h];
    hidden[(size_t)n * H + h] = (1.f - z) * nn + z * e;
}

__global__ void gather_relu(const int* __restrict__ x, const float* __restrict__ hidden,
                            float* __restrict__ h2, int N)
{
    long long idx = (long long)blockIdx.x * blockDim.x + threadIdx.x;
    if (idx >= (long long)N * H) return;
    int i = (int)(idx >> 8), h = (int)(idx & 255);
    int node = x[i] - 1;
    float v = hidden[(size_t)node * H + h];
    h2[idx] = v > 0.f ? v : 0.f;
}

__global__ void last_max(const int* __restrict__ batch, int* __restrict__ lastidx, int N)
{
    int i = blockIdx.x * blockDim.x + threadIdx.x;
    if (i >= N) return;
    atomicMax(&lastidx[batch[i]], i);
}

__global__ void vn_gather(const float* __restrict__ h2, const int* __restrict__ lastidx,
                          float* __restrict__ vn, int B)
{
    int idx = blockIdx.x * blockDim.x + threadIdx.x;
    if (idx >= B * H) return;
    int b = idx >> 8, h = idx & 255;
    vn[idx] = h2[(size_t)lastidx[b] * H + h];
}

__global__ void attn_kernel(const float* __restrict__ a, const float* __restrict__ bth,
                            const float* __restrict__ h2, const int* __restrict__ batch,
                            const float* __restrict__ W1_b, const float* __restrict__ W2_b,
                            const float* __restrict__ q_w, const float* __restrict__ q_b,
                            float* __restrict__ sg)
{
    __shared__ float red[256];
    int i = blockIdx.x;
    int h = threadIdx.x;
    int b = batch[i];
    float g = a[(size_t)b * H + h] + W1_b[h] + bth[(size_t)i * H + h] + W2_b[h];
    g = 1.f / (1.f + expf(-g));
    red[h] = g * q_w[h];
    __syncthreads();
#pragma unroll
    for (int s = 128; s > 0; s >>= 1) {
        if (h < s) red[h] += red[h + s];
        __syncthreads();
    }
    float alpha = red[0] + q_b[0];
    atomicAdd(&sg[(size_t)b * H + h], alpha * h2[(size_t)i * H + h]);
}

__global__ void concat_vns(const float* __restrict__ vn, const float* __restrict__ sg,
                           float* __restrict__ vns, int B)
{
    int idx = blockIdx.x * blockDim.x + threadIdx.x;
    if (idx >= B * 512) return;
    int b = idx >> 9, c = idx & 511;
    vns[idx] = (c < 256) ? vn[b * 256 + c] : sg[b * 256 + (c - 256)];
}

__global__ void add_bias(float* __restrict__ sh, const float* __restrict__ W3_b, int B)
{
    int idx = blockIdx.x * blockDim.x + threadIdx.x;
    if (idx >= B * H) return;
    sh[idx] += W3_b[idx & 255];
}

__global__ void edges_to_float(const int* __restrict__ ei, float* __restrict__ out, int n)
{
    int idx = blockIdx.x * blockDim.x + threadIdx.x;
    if (idx >= n) return;
    out[idx] = (float)ei[idx];
}

// ---------------- driver ----------------
extern "C" void kernel_launch(void* const* d_in, const int* in_sizes, int n_in,
                              void* d_out, int out_size)
{
    const int*   x      = (const int*)d_in[0];
    const int*   batch  = (const int*)d_in[1];
    const int*   ei     = (const int*)d_in[2];
    const int*   fg     = (const int*)d_in[3];
    const float* emb    = (const float*)d_in[4];
    const float* ggnn_W = (const float*)d_in[5];
    const float* Wih    = (const float*)d_in[6];
    const float* Whh    = (const float*)d_in[7];
    const float* bih    = (const float*)d_in[8];
    const float* bhh    = (const float*)d_in[9];
    const float* W1_w   = (const float*)d_in[10];
    const float* W1_b   = (const float*)d_in[11];
    const float* W2_w   = (const float*)d_in[12];
    const float* W2_b   = (const float*)d_in[13];
    const float* q_w    = (const float*)d_in[14];
    const float* q_b    = (const float*)d_in[15];
    const float* W3_w   = (const float*)d_in[16];
    const float* W3_b   = (const float*)d_in[17];
    float* out = (float*)d_out;

    const int N     = in_sizes[0];          // 12288 session nodes
    const int E     = in_sizes[3] / 2;      // 500000 edges
    const int NNODE = in_sizes[4] / H;      // 50000 items
    const long long scores_elems = (long long)out_size - (long long)N * H - 2LL * N;
    const int B = (int)(scores_elems / NNODE);   // 1024

    static int smem_set = 0;
    if (!smem_set) {
        cudaFuncSetAttribute(gemm_tf32_nt, cudaFuncAttributeMaxDynamicSharedMemorySize, SMEM_BYTES);
        smem_set = 1;
    }

    float *m, *agg, *gi, *gh, *hidden, *Wt, *vn, *a, *bth, *sg, *vns, *sh;
    int* lastidx;
    cudaGetSymbolAddress((void**)&m,      d_m);
    cudaGetSymbolAddress((void**)&agg,    d_agg);
    cudaGetSymbolAddress((void**)&gi,     d_gi);
    cudaGetSymbolAddress((void**)&gh,     d_gh);
    cudaGetSymbolAddress((void**)&hidden, d_hidden);
    cudaGetSymbolAddress((void**)&Wt,     d_Wt);
    cudaGetSymbolAddress((void**)&vn,     d_vn);
    cudaGetSymbolAddress((void**)&a,      d_a);
    cudaGetSymbolAddress((void**)&bth,    d_bth);
    cudaGetSymbolAddress((void**)&sg,     d_sg);
    cudaGetSymbolAddress((void**)&vns,    d_vns);
    cudaGetSymbolAddress((void**)&sh,     d_sh);
    cudaGetSymbolAddress((void**)&lastidx, d_lastidx);

    float* scores = out;
    float* h2     = out + scores_elems;
    float* eout   = out + scores_elems + (long long)N * H;

    const int T = 256;
    dim3 blk(T);
    auto cdiv = [](long long v, long long d) { return (unsigned)((v + d - 1) / d); };

    // 1) Wt = ggnn_W^T
    transpose256<<<cdiv(256 * 256, T), blk>>>(ggnn_W, Wt);

    // 2) m = emb @ ggnn_W  (tf32 tensor cores)
    gemm_tf32_nt<<<dim3(cdiv(H, 128), cdiv(NNODE, 128)), blk, SMEM_BYTES>>>(emb, Wt, m, NNODE, H, H);

    // 3) agg = segment_sum(m[src], dst)
    cudaMemsetAsync(agg, 0, (size_t)NNODE * H * sizeof(float));
    scatter_add<<<cdiv((long long)E * (H / 4), T), blk>>>(fg, m, agg, E);

    // 4) gi = agg @ Wih^T ; gh = emb @ Whh^T (tf32)
    gemm_tf32_nt<<<dim3(cdiv(3 * H, 128), cdiv(NNODE, 128)), blk, SMEM_BYTES>>>(agg, Wih, gi, NNODE, 3 * H, H);
    gemm_tf32_nt<<<dim3(cdiv(3 * H, 128), cdiv(NNODE, 128)), blk, SMEM_BYTES>>>(emb, Whh, gh, NNODE, 3 * H, H);

    // 5) GRU cell -> hidden_all
    gru_elementwise<<<cdiv((long long)NNODE * H, T), blk>>>(gi, gh, emb, bih, bhh, hidden, NNODE);

    // 6) h2 = relu(hidden[x-1])
    gather_relu<<<cdiv((long long)N * H, T), blk>>>(x, hidden, h2, N);

    // 7) last node per session
    cudaMemsetAsync(lastidx, 0xFF, (size_t)B * sizeof(int));
    last_max<<<cdiv(N, T), blk>>>(batch, lastidx, N);
    vn_gather<<<cdiv(B * H, T), blk>>>(h2, lastidx, vn, B);

    // 8) attention
    gemm_nt<<<dim3(cdiv(H, 128), cdiv(B, 128)), blk>>>(vn, W1_w, a, B, H, H);
    gemm_tf32_nt<<<dim3(cdiv(H, 128), cdiv(N, 128)), blk, SMEM_BYTES>>>(h2, W2_w, bth, N, H, H);
    cudaMemsetAsync(sg, 0, (size_t)B * H * sizeof(float));
    attn_kernel<<<N, blk>>>(a, bth, h2, batch, W1_b, W2_b, q_w, q_b, sg);

    // 9) s_h = [vn | s_g] @ W3^T + b3  (small, fp32)
    concat_vns<<<cdiv(B * 512, T), blk>>>(vn, sg, vns, B);
    gemm_nt<<<dim3(cdiv(H, 128), cdiv(B, 128)), blk>>>(vns, W3_w, sh, B, H, 2 * H);
    add_bias<<<cdiv(B * H, T), blk>>>(sh, W3_b, B);

    // 10) scores = s_h @ emb^T  (tf32)
    gemm_tf32_nt<<<dim3(cdiv(NNODE, 128), cdiv(B, 128)), blk, SMEM_BYTES>>>(sh, emb, scores, B, NNODE, H);

    // 11) passthrough edge_index as float
    edges_to_float<<<cdiv(2 * N, T), blk>>>(ei, eout, 2 * N);
}

// round 7
// speedup vs baseline: 2.6962x; 1.0055x over previous
#include <cuda_runtime.h>
#include <cstdint>
#include <cstddef>

#define H 256

// ---------------- scratch (static device allocations; no cudaMalloc) ----------------
__device__ float d_m[50000 * 256];
__device__ float d_agg[50000 * 256];       // tf32-rounded
__device__ float d_gi[50000 * 768];
__device__ float d_gh[50000 * 768];
__device__ float d_hidden[50000 * 256];
__device__ float d_embc[50000 * 256];      // tf32-rounded emb
__device__ float d_Wtc[256 * 256];         // tf32-rounded ggnn_W^T
__device__ float d_Wihc[768 * 256];
__device__ float d_Whhc[768 * 256];
__device__ float d_W2c[256 * 256];
__device__ float d_h2c[12288 * 256];       // tf32-rounded relu(h2)
__device__ float d_vn[1024 * 256];
__device__ float d_a[1024 * 256];
__device__ float d_bth[12288 * 256];
__device__ float d_sg[1024 * 256];
__device__ float d_vns[1024 * 512];
__device__ float d_sh[1024 * 256];
__device__ int   d_lastidx[1024];
__device__ int   d_deg[50000];
__device__ int   d_start[50001];
__device__ int   d_cursor[50000];
__device__ int   d_csr[500000];

// ---------------- helpers ----------------
__device__ __forceinline__ float f2tf_f(float f) {
    unsigned u;
    asm("cvt.rna.tf32.f32 %0, %1;" : "=r"(u) : "f"(f));
    return __uint_as_float(u);
}
__device__ __forceinline__ void ldm_x4(unsigned r[4], unsigned addr) {
    asm volatile("ldmatrix.sync.aligned.m8n8.x4.shared.b16 {%0,%1,%2,%3}, [%4];"
                 : "=r"(r[0]), "=r"(r[1]), "=r"(r[2]), "=r"(r[3]) : "r"(addr));
}
__device__ __forceinline__ void mma_tf32(float d[4], const unsigned a[4], const unsigned b[2]) {
    asm volatile("mma.sync.aligned.m16n8k8.row.col.f32.tf32.tf32.f32 "
                 "{%0,%1,%2,%3}, {%4,%5,%6,%7}, {%8,%9}, {%0,%1,%2,%3};"
                 : "+f"(d[0]), "+f"(d[1]), "+f"(d[2]), "+f"(d[3])
                 : "r"(a[0]), "r"(a[1]), "r"(a[2]), "r"(a[3]), "r"(b[0]), "r"(b[1]));
}
__device__ __forceinline__ void cp_async16(unsigned saddr, const void* gptr) {
    asm volatile("cp.async.cg.shared.global [%0], [%1], 16;" :: "r"(saddr), "l"(gptr));
}

// ---------------- tf32 tensor-core NT GEMM (operands pre-rounded to tf32) ----------------
// C[m,n] = sum_k A[m,k]*B[n,k]. Block 128x128, BK=32, 8 warps of 64x32, 2 CTAs/SM.
#define PADW 36
#define ASTAGE_F (128 * PADW)
#define BOFF_F   (2 * ASTAGE_F)
#define BSTAGE_F (128 * PADW)
#define SMEM_BYTES ((BOFF_F + 2 * BSTAGE_F) * 4)

__global__ __launch_bounds__(256, 2) void gemm_tf32_nt(
    const float* __restrict__ A, const float* __restrict__ B,
    float* __restrict__ C, int M, int N, int K)
{
    extern __shared__ float sm[];
    const unsigned smu = (unsigned)__cvta_generic_to_shared(sm);

    const int tid  = threadIdx.x;
    const int warp = tid >> 5;
    const int lane = tid & 31;
    const int bm = blockIdx.y * 128;
    const int bn = blockIdx.x * 128;
    const int wm = (warp & 1) * 64;
    const int wn = (warp >> 1) * 32;

    float acc[4][4][4];
#pragma unroll
    for (int i = 0; i < 4; ++i)
#pragma unroll
        for (int j = 0; j < 4; ++j)
#pragma unroll
            for (int v = 0; v < 4; ++v) acc[i][j][v] = 0.f;

    int arow[4], acol[4];
    const float* agp[4];
    const float* bgp[4];
#pragma unroll
    for (int i = 0; i < 4; ++i) {
        int lin = tid + i * 256;
        arow[i] = lin >> 3;
        acol[i] = (lin & 7) << 2;
        int gm = bm + arow[i]; gm = gm < M ? gm : M - 1;
        agp[i] = A + (size_t)gm * K + acol[i];
        int gn = bn + arow[i]; gn = gn < N ? gn : N - 1;
        bgp[i] = B + (size_t)gn * K + acol[i];
    }

    const unsigned aBase = smu + ((wm + (lane & 15)) * PADW + ((lane >> 4) << 2)) * 4u;
    const unsigned bBase = smu + (BOFF_F +
        (wn + ((lane >> 4) << 3) + (lane & 7)) * PADW + (((lane >> 3) & 1) << 2)) * 4u;

    const int KT = K >> 5;

#pragma unroll
    for (int i = 0; i < 4; ++i) {
        cp_async16(smu + (arow[i] * PADW + acol[i]) * 4u, agp[i]);
        cp_async16(smu + (BOFF_F + arow[i] * PADW + acol[i]) * 4u, bgp[i]);
    }
    asm volatile("cp.async.commit_group;");

    for (int kt = 0; kt < KT; ++kt) {
        if (kt + 1 < KT) {
            int s = (kt + 1) & 1;
            int k0 = (kt + 1) << 5;
#pragma unroll
            for (int i = 0; i < 4; ++i) {
                cp_async16(smu + (s * ASTAGE_F + arow[i] * PADW + acol[i]) * 4u, agp[i] + k0);
                cp_async16(smu + (BOFF_F + s * BSTAGE_F + arow[i] * PADW + acol[i]) * 4u, bgp[i] + k0);
            }
            asm volatile("cp.async.commit_group;");
            asm volatile("cp.async.wait_group 1;");
        } else {
            asm volatile("cp.async.wait_group 0;");
        }
        __syncthreads();

        const int s = kt & 1;
        const unsigned aw = aBase + s * (ASTAGE_F * 4u);
        const unsigned bw = bBase + s * (BSTAGE_F * 4u);
#pragma unroll
        for (int kk = 0; kk < 32; kk += 8) {
            unsigned af[4][4];
            unsigned bf[4][2];
#pragma unroll
            for (int mi = 0; mi < 4; ++mi)
                ldm_x4(af[mi], aw + (mi * 16 * PADW + kk) * 4u);
#pragma unroll
            for (int p = 0; p < 2; ++p) {
                unsigned t[4];
                ldm_x4(t, bw + (p * 16 * PADW + kk) * 4u);
                bf[p * 2][0] = t[0]; bf[p * 2][1] = t[1];
                bf[p * 2 + 1][0] = t[2]; bf[p * 2 + 1][1] = t[3];
            }
#pragma unroll
            for (int mi = 0; mi < 4; ++mi)
#pragma unroll
                for (int nj = 0; nj < 4; ++nj)
                    mma_tf32(acc[mi][nj], af[mi], bf[nj]);
        }
        __syncthreads();
    }

#pragma unroll
    for (int mi = 0; mi < 4; ++mi) {
        int gm0 = bm + wm + mi * 16 + (lane >> 2);
#pragma unroll
        for (int nj = 0; nj < 4; ++nj) {
            int gn = bn + wn + nj * 8 + ((lane & 3) << 1);
            if (gn < N) {
                if (gm0 < M)
                    *reinterpret_cast<float2*>(&C[(size_t)gm0 * N + gn]) =
                        make_float2(acc[mi][nj][0], acc[mi][nj][1]);
                if (gm0 + 8 < M)
                    *reinterpret_cast<float2*>(&C[(size_t)(gm0 + 8) * N + gn]) =
                        make_float2(acc[mi][nj][2], acc[mi][nj][3]);
            }
        }
    }
}

// ---------------- fp32 fallback GEMM for tiny matrices ----------------
#define BK 16
__global__ __launch_bounds__(256) void gemm_nt(
    const float* __restrict__ A, const float* __restrict__ B,
    float* __restrict__ C, int M, int N, int K)
{
    __shared__ float As[BK][128];
    __shared__ float Bs[BK][128];
    const int bm = blockIdx.y * 128;
    const int bn = blockIdx.x * 128;
    const int tid = threadIdx.x;
    const int tcol = (tid & 15) * 8;
    const int trow = (tid >> 4) * 8;

    float acc[8][8];
#pragma unroll
    for (int i = 0; i < 8; ++i)
#pragma unroll
        for (int j = 0; j < 8; ++j) acc[i][j] = 0.f;

    for (int k0 = 0; k0 < K; k0 += BK) {
#pragma unroll
        for (int it = 0; it < 2; ++it) {
            int lin = tid + it * 256;
            int r  = lin >> 2;
            int c4 = (lin & 3) << 2;
            int gm = bm + r; gm = gm < M ? gm : M - 1;
            float4 va = *reinterpret_cast<const float4*>(A + (size_t)gm * K + k0 + c4);
            As[c4 + 0][r] = va.x; As[c4 + 1][r] = va.y;
            As[c4 + 2][r] = va.z; As[c4 + 3][r] = va.w;
            int gn = bn + r; gn = gn < N ? gn : N - 1;
            float4 vb = *reinterpret_cast<const float4*>(B + (size_t)gn * K + k0 + c4);
            Bs[c4 + 0][r] = vb.x; Bs[c4 + 1][r] = vb.y;
            Bs[c4 + 2][r] = vb.z; Bs[c4 + 3][r] = vb.w;
        }
        __syncthreads();
#pragma unroll
        for (int k = 0; k < BK; ++k) {
            float4 a0 = *reinterpret_cast<const float4*>(&As[k][trow]);
            float4 a1 = *reinterpret_cast<const float4*>(&As[k][trow + 4]);
            float4 b0 = *reinterpret_cast<const float4*>(&Bs[k][tcol]);
            float4 b1 = *reinterpret_cast<const float4*>(&Bs[k][tcol + 4]);
            float ar[8] = {a0.x, a0.y, a0.z, a0.w, a1.x, a1.y, a1.z, a1.w};
            float br[8] = {b0.x, b0.y, b0.z, b0.w, b1.x, b1.y, b1.z, b1.w};
#pragma unroll
            for (int i = 0; i < 8; ++i)
#pragma unroll
                for (int j = 0; j < 8; ++j)
                    acc[i][j] = fmaf(ar[i], br[j], acc[i][j]);
        }
        __syncthreads();
    }

#pragma unroll
    for (int i = 0; i < 8; ++i) {
        int gm = bm + trow + i;
        if (gm >= M) break;
#pragma unroll
        for (int j = 0; j < 8; ++j) {
            int gn = bn + tcol + j;
            if (gn < N) C[(size_t)gm * N + gn] = acc[i][j];
        }
    }
}

// ---------------- prep: tf32-convert operands ----------------
__global__ void cvt_tf32_vec(const float* __restrict__ in, float* __restrict__ out, int n4)
{
    int i = blockIdx.x * blockDim.x + threadIdx.x;
    if (i >= n4) return;
    float4 v = reinterpret_cast<const float4*>(in)[i];
    v.x = f2tf_f(v.x); v.y = f2tf_f(v.y); v.z = f2tf_f(v.z); v.w = f2tf_f(v.w);
    reinterpret_cast<float4*>(out)[i] = v;
}

// one kernel: Wt (transpose+cvt), Wih, Whh, W2 (cvt)
__global__ void prep_weights(const float* __restrict__ ggnn_W, const float* __restrict__ Wih,
                             const float* __restrict__ Whh, const float* __restrict__ W2,
                             float* __restrict__ Wtc, float* __restrict__ Wihc,
                             float* __restrict__ Whhc, float* __restrict__ W2c)
{
    int idx = blockIdx.x * blockDim.x + threadIdx.x;
    if (idx < 65536) {
        int j = idx >> 8, k = idx & 255;
        Wtc[idx] = f2tf_f(ggnn_W[k * 256 + j]);
    } else if (idx < 65536 + 196608) {
        int i = idx - 65536;
        Wihc[i] = f2tf_f(Wih[i]);
    } else if (idx < 65536 + 2 * 196608) {
        int i = idx - 65536 - 196608;
        Whhc[i] = f2tf_f(Whh[i]);
    } else if (idx < 2 * 65536 + 2 * 196608) {
        int i = idx - 65536 - 2 * 196608;
        W2c[i] = f2tf_f(W2[i]);
    }
}

// ---------------- CSR build + gather aggregation ----------------
__global__ void edge_hist(const int* __restrict__ fg, int* __restrict__ deg, int E)
{
    int e = blockIdx.x * blockDim.x + threadIdx.x;
    if (e >= E) return;
    atomicAdd(&deg[fg[E + e]], 1);
}

// single-block chunked exclusive scan over nnode entries
__global__ void csr_scan(const int* __restrict__ deg, int* __restrict__ start, int nnode)
{
    __shared__ int warpsum[32];
    const int tid = threadIdx.x;
    const int lane = tid & 31, w = tid >> 5;
    int run = 0;
    for (int c0 = 0; c0 < nnode; c0 += 1024) {
        int v = (c0 + tid < nnode) ? deg[c0 + tid] : 0;
        int x = v;
#pragma unroll
        for (int o = 1; o < 32; o <<= 1) {
            int y = __shfl_up_sync(0xFFFFFFFFu, x, o);
            if (lane >= o) x += y;
        }
        if (lane == 31) warpsum[w] = x;
        __syncthreads();
        if (w == 0) {
            int s = warpsum[lane];
#pragma unroll
            for (int o = 1; o < 32; o <<= 1) {
                int y = __shfl_up_sync(0xFFFFFFFFu, s, o);
                if (lane >= o) s += y;
            }
            warpsum[lane] = s;
        }
        __syncthreads();
        int incl = x + (w > 0 ? warpsum[w - 1] : 0);
        if (c0 + tid < nnode) start[c0 + tid] = run + incl - v;
        int total = warpsum[31];
        __syncthreads();
        run += total;
    }
    if (tid == 0) start[nnode] = run;
}

__global__ void csr_fill(const int* __restrict__ fg, const int* __restrict__ start,
                         int* __restrict__ cursor, int* __restrict__ csr, int E)
{
    int e = blockIdx.x * blockDim.x + threadIdx.x;
    if (e >= E) return;
    int dst = fg[E + e];
    int slot = atomicAdd(&cursor[dst], 1);
    csr[start[dst] + slot] = fg[e];
}

// one block per dst node: agg[dst] = cvt_tf32( sum_{e in dst} m[src_e] )
__global__ __launch_bounds__(256) void gather_agg(
    const int* __restrict__ start, const int* __restrict__ csr,
    const float* __restrict__ m, float* __restrict__ agg)
{
    int d = blockIdx.x;
    int tid = threadIdx.x;
    int s0 = start[d], s1 = start[d + 1];
    float acc = 0.f;
    for (int j = s0; j < s1; ++j) {
        int src = csr[j];
        acc += m[(size_t)src * H + tid];
    }
    agg[(size_t)d * H + tid] = f2tf_f(acc);
}

// ---------------- small helpers ----------------
__global__ void gru_elementwise(const float* __restrict__ gi, const float* __restrict__ gh,
                                const float* __restrict__ emb,
                                const float* __restrict__ bih, const float* __restrict__ bhh,
                                float* __restrict__ hidden, int NNODE)
{
    long long idx = (long long)blockIdx.x * blockDim.x + threadIdx.x;
    if (idx >= (long long)NNODE * H) return;
    int n = (int)(idx >> 8), h = (int)(idx & 255);
    size_t base = (size_t)n * 768;
    float ir = gi[base + h]       + bih[h];
    float hr = gh[base + h]       + bhh[h];
    float iz = gi[base + 256 + h] + bih[256 + h];
    float hz = gh[base + 256 + h] + bhh[256 + h];
    float in_ = gi[base + 512 + h] + bih[512 + h];
    float hn  = gh[base + 512 + h] + bhh[512 + h];
    float r = 1.f / (1.f + expf(-(ir + hr)));
    float z = 1.f / (1.f + expf(-(iz + hz)));
    float nn = tanhf(in_ + r * hn);
    float e = emb[(size_t)n * H + h];
    hidden[(size_t)n * H + h] = (1.f - z) * nn + z * e;
}

__global__ void gather_relu(const int* __restrict__ x, const float* __restrict__ hidden,
                            float* __restrict__ h2, float* __restrict__ h2c, int N)
{
    long long idx = (long long)blockIdx.x * blockDim.x + threadIdx.x;
    if (idx >= (long long)N * H) return;
    int i = (int)(idx >> 8), h = (int)(idx & 255);
    int node = x[i] - 1;
    float v = hidden[(size_t)node * H + h];
    v = v > 0.f ? v : 0.f;
    h2[idx] = v;
    h2c[idx] = f2tf_f(v);
}

__global__ void last_max(const int* __restrict__ batch, int* __restrict__ lastidx, int N)
{
    int i = blockIdx.x * blockDim.x + threadIdx.x;
    if (i >= N) return;
    atomicMax(&lastidx[batch[i]], i);
}

__global__ void vn_gather(const float* __restrict__ h2, const int* __restrict__ lastidx,
                          float* __restrict__ vn, int B)
{
    int idx = blockIdx.x * blockDim.x + threadIdx.x;
    if (idx >= B * H) return;
    int b = idx >> 8, h = idx & 255;
    vn[idx] = h2[(size_t)lastidx[b] * H + h];
}

__global__ void attn_kernel(const float* __restrict__ a, const float* __restrict__ bth,
                            const float* __restrict__ h2, const int* __restrict__ batch,
                            const float* __restrict__ W1_b, const float* __restrict__ W2_b,
                            const float* __restrict__ q_w, const float* __restrict__ q_b,
                            float* __restrict__ sg)
{
    __shared__ float red[256];
    int i = blockIdx.x;
    int h = threadIdx.x;
    int b = batch[i];
    float g = a[(size_t)b * H + h] + W1_b[h] + bth[(size_t)i * H + h] + W2_b[h];
    g = 1.f / (1.f + expf(-g));
    red[h] = g * q_w[h];
    __syncthreads();
#pragma unroll
    for (int s = 128; s > 0; s >>= 1) {
        if (h < s) red[h] += red[h + s];
        __syncthreads();
    }
    float alpha = red[0] + q_b[0];
    atomicAdd(&sg[(size_t)b * H + h], alpha * h2[(size_t)i * H + h]);
}

__global__ void concat_vns(const float* __restrict__ vn, const float* __restrict__ sg,
                           float* __restrict__ vns, int B)
{
    int idx = blockIdx.x * blockDim.x + threadIdx.x;
    if (idx >= B * 512) return;
    int b = idx >> 9, c = idx & 511;
    vns[idx] = (c < 256) ? vn[b * 256 + c] : sg[b * 256 + (c - 256)];
}

// sh = cvt_tf32(sh + b3) — sh feeds only the scores GEMM
__global__ void add_bias_cvt(float* __restrict__ sh, const float* __restrict__ W3_b, int B)
{
    int idx = blockIdx.x * blockDim.x + threadIdx.x;
    if (idx >= B * H) return;
    sh[idx] = f2tf_f(sh[idx] + W3_b[idx & 255]);
}

__global__ void edges_to_float(const int* __restrict__ ei, float* __restrict__ out, int n)
{
    int idx = blockIdx.x * blockDim.x + threadIdx.x;
    if (idx >= n) return;
    out[idx] = (float)ei[idx];
}

// ---------------- driver ----------------
extern "C" void kernel_launch(void* const* d_in, const int* in_sizes, int n_in,
                              void* d_out, int out_size)
{
    const int*   x      = (const int*)d_in[0];
    const int*   batch  = (const int*)d_in[1];
    const int*   ei     = (const int*)d_in[2];
    const int*   fg     = (const int*)d_in[3];
    const float* emb    = (const float*)d_in[4];
    const float* ggnn_W = (const float*)d_in[5];
    const float* Wih    = (const float*)d_in[6];
    const float* Whh    = (const float*)d_in[7];
    const float* bih    = (const float*)d_in[8];
    const float* bhh    = (const float*)d_in[9];
    const float* W1_w   = (const float*)d_in[10];
    const float* W1_b   = (const float*)d_in[11];
    const float* W2_w   = (const float*)d_in[12];
    const float* W2_b   = (const float*)d_in[13];
    const float* q_w    = (const float*)d_in[14];
    const float* q_b    = (const float*)d_in[15];
    const float* W3_w   = (const float*)d_in[16];
    const float* W3_b   = (const float*)d_in[17];
    float* out = (float*)d_out;

    const int N     = in_sizes[0];          // 12288
    const int E     = in_sizes[3] / 2;      // 500000
    const int NNODE = in_sizes[4] / H;      // 50000
    const long long scores_elems = (long long)out_size - (long long)N * H - 2LL * N;
    const int B = (int)(scores_elems / NNODE);   // 1024

    static int smem_set = 0;
    if (!smem_set) {
        cudaFuncSetAttribute(gemm_tf32_nt, cudaFuncAttributeMaxDynamicSharedMemorySize, SMEM_BYTES);
        smem_set = 1;
    }

    float *m, *agg, *gi, *gh, *hidden, *embc, *Wtc, *Wihc, *Whhc, *W2c, *h2c;
    float *vn, *a, *bth, *sg, *vns, *sh;
    int *lastidx, *deg, *startp, *cursor, *csr;
    cudaGetSymbolAddress((void**)&m,      d_m);
    cudaGetSymbolAddress((void**)&agg,    d_agg);
    cudaGetSymbolAddress((void**)&gi,     d_gi);
    cudaGetSymbolAddress((void**)&gh,     d_gh);
    cudaGetSymbolAddress((void**)&hidden, d_hidden);
    cudaGetSymbolAddress((void**)&embc,   d_embc);
    cudaGetSymbolAddress((void**)&Wtc,    d_Wtc);
    cudaGetSymbolAddress((void**)&Wihc,   d_Wihc);
    cudaGetSymbolAddress((void**)&Whhc,   d_Whhc);
    cudaGetSymbolAddress((void**)&W2c,    d_W2c);
    cudaGetSymbolAddress((void**)&h2c,    d_h2c);
    cudaGetSymbolAddress((void**)&vn,     d_vn);
    cudaGetSymbolAddress((void**)&a,      d_a);
    cudaGetSymbolAddress((void**)&bth,    d_bth);
    cudaGetSymbolAddress((void**)&sg,     d_sg);
    cudaGetSymbolAddress((void**)&vns,    d_vns);
    cudaGetSymbolAddress((void**)&sh,     d_sh);
    cudaGetSymbolAddress((void**)&lastidx, d_lastidx);
    cudaGetSymbolAddress((void**)&deg,    d_deg);
    cudaGetSymbolAddress((void**)&startp, d_start);
    cudaGetSymbolAddress((void**)&cursor, d_cursor);
    cudaGetSymbolAddress((void**)&csr,    d_csr);

    float* scores = out;
    float* h2     = out + scores_elems;
    float* eout   = out + scores_elems + (long long)N * H;

    const int T = 256;
    dim3 blk(T);
    auto cdiv = [](long long v, long long d) { return (unsigned)((v + d - 1) / d); };

    // 0) prep: tf32-convert emb + weights; build CSR
    cvt_tf32_vec<<<cdiv((long long)NNODE * H / 4, T), blk>>>(emb, embc, NNODE * H / 4);
    prep_weights<<<cdiv(2 * 65536 + 2 * 196608, T), blk>>>(ggnn_W, Wih, Whh, W2_w,
                                                           Wtc, Wihc, Whhc, W2c);
    cudaMemsetAsync(deg, 0, (size_t)NNODE * sizeof(int));
    edge_hist<<<cdiv(E, T), blk>>>(fg, deg, E);
    csr_scan<<<1, 1024>>>(deg, startp, NNODE);
    cudaMemsetAsync(cursor, 0, (size_t)NNODE * sizeof(int));
    csr_fill<<<cdiv(E, T), blk>>>(fg, startp, cursor, csr, E);

    // 1) m = emb @ ggnn_W
    gemm_tf32_nt<<<dim3(cdiv(H, 128), cdiv(NNODE, 128)), blk, SMEM_BYTES>>>(embc, Wtc, m, NNODE, H, H);

    // 2) agg = segment_sum(m[src], dst)  (gather, no atomics; writes tf32-rounded)
    gather_agg<<<NNODE, blk>>>(startp, csr, m, agg);

    // 3) gi = agg @ Wih^T ; gh = emb @ Whh^T
    gemm_tf32_nt<<<dim3(cdiv(3 * H, 128), cdiv(NNODE, 128)), blk, SMEM_BYTES>>>(agg, Wihc, gi, NNODE, 3 * H, H);
    gemm_tf32_nt<<<dim3(cdiv(3 * H, 128), cdiv(NNODE, 128)), blk, SMEM_BYTES>>>(embc, Whhc, gh, NNODE, 3 * H, H);

    // 4) GRU cell -> hidden_all
    gru_elementwise<<<cdiv((long long)NNODE * H, T), blk>>>(gi, gh, emb, bih, bhh, hidden, NNODE);

    // 5) h2 = relu(hidden[x-1]) (+ tf32 copy)
    gather_relu<<<cdiv((long long)N * H, T), blk>>>(x, hidden, h2, h2c, N);

    // 6) last node per session
    cudaMemsetAsync(lastidx, 0xFF, (size_t)B * sizeof(int));
    last_max<<<cdiv(N, T), blk>>>(batch, lastidx, N);
    vn_gather<<<cdiv(B * H, T), blk>>>(h2, lastidx, vn, B);

    // 7) attention
    gemm_nt<<<dim3(cdiv(H, 128), cdiv(B, 128)), blk>>>(vn, W1_w, a, B, H, H);
    gemm_tf32_nt<<<dim3(cdiv(H, 128), cdiv(N, 128)), blk, SMEM_BYTES>>>(h2c, W2c, bth, N, H, H);
    cudaMemsetAsync(sg, 0, (size_t)B * H * sizeof(float));
    attn_kernel<<<N, blk>>>(a, bth, h2, batch, W1_b, W2_b, q_w, q_b, sg);

    // 8) s_h = [vn | s_g] @ W3^T + b3  (fp32), then tf32-round for scores GEMM
    concat_vns<<<cdiv(B * 512, T), blk>>>(vn, sg, vns, B);
    gemm_nt<<<dim3(cdiv(H, 128), cdiv(B, 128)), blk>>>(vns, W3_w, sh, B, H, 2 * H);
    add_bias_cvt<<<cdiv(B * H, T), blk>>>(sh, W3_b, B);

    // 9) scores = s_h @ emb^T
    gemm_tf32_nt<<<dim3(cdiv(NNODE, 128), cdiv(B, 128)), blk, SMEM_BYTES>>>(sh, embc, scores, B, NNODE, H);

    // 10) passthrough edge_index as float
    edges_to_float<<<cdiv(2 * N, T), blk>>>(ei, eout, 2 * N);
}

// round 9
// speedup vs baseline: 2.7933x; 1.0360x over previous
#include <cuda_runtime.h>
#include <cstdint>
#include <cstddef>

#define H 256

// ---------------- scratch ----------------
__device__ float d_aggE[50000 * 256];      // segsum(emb), tf32-rounded
__device__ float d_gi[50000 * 768];
__device__ float d_gh[50000 * 768];
__device__ float d_hidden[50000 * 256];
__device__ float d_embc[50000 * 256];      // tf32 emb
__device__ float d_F[768 * 256];           // Wih @ ggnn_W^T (fp32)
__device__ float d_Fc[768 * 256];          // tf32
__device__ float d_Whhc[768 * 256];
__device__ float d_W2c[256 * 256];
__device__ float d_h2c[12288 * 256];
__device__ float d_vn[1024 * 256];
__device__ float d_a[1024 * 256];
__device__ float d_bth[12288 * 256];
__device__ float d_sg[1024 * 256];
__device__ float d_vns[1024 * 512];
__device__ float d_sh[1024 * 256];
__device__ int   d_lastidx[1024];
__device__ int   d_deg[50176];
__device__ int   d_start[50001];
__device__ int   d_bsum[80];
__device__ int   d_cursor[50000];
__device__ int   d_csr[500000];

// ---------------- helpers ----------------
__device__ __forceinline__ float f2tf_f(float f) {
    unsigned u;
    asm("cvt.rna.tf32.f32 %0, %1;" : "=r"(u) : "f"(f));
    return __uint_as_float(u);
}
__device__ __forceinline__ void ldm_x4(unsigned r[4], unsigned addr) {
    asm volatile("ldmatrix.sync.aligned.m8n8.x4.shared.b16 {%0,%1,%2,%3}, [%4];"
                 : "=r"(r[0]), "=r"(r[1]), "=r"(r[2]), "=r"(r[3]) : "r"(addr));
}
__device__ __forceinline__ void mma_tf32(float d[4], const unsigned a[4], const unsigned b[2]) {
    asm volatile("mma.sync.aligned.m16n8k8.row.col.f32.tf32.tf32.f32 "
                 "{%0,%1,%2,%3}, {%4,%5,%6,%7}, {%8,%9}, {%0,%1,%2,%3};"
                 : "+f"(d[0]), "+f"(d[1]), "+f"(d[2]), "+f"(d[3])
                 : "r"(a[0]), "r"(a[1]), "r"(a[2]), "r"(a[3]), "r"(b[0]), "r"(b[1]));
}
__device__ __forceinline__ void cp_async16(unsigned saddr, const void* gptr) {
    asm volatile("cp.async.cg.shared.global [%0], [%1], 16;" :: "r"(saddr), "l"(gptr));
}

// ---------------- tf32 tensor-core NT GEMM (operands pre-rounded) ----------------
#define PADW 36
#define ASTAGE_F (128 * PADW)
#define BOFF_F   (2 * ASTAGE_F)
#define BSTAGE_F (128 * PADW)
#define SMEM_BYTES ((BOFF_F + 2 * BSTAGE_F) * 4)

__global__ __launch_bounds__(256, 2) void gemm_tf32_nt(
    const float* __restrict__ A, const float* __restrict__ B,
    float* __restrict__ C, int M, int N, int K)
{
    extern __shared__ float sm[];
    const unsigned smu = (unsigned)__cvta_generic_to_shared(sm);

    const int tid  = threadIdx.x;
    const int warp = tid >> 5;
    const int lane = tid & 31;
    const int bm = blockIdx.y * 128;
    const int bn = blockIdx.x * 128;
    const int wm = (warp & 1) * 64;
    const int wn = (warp >> 1) * 32;

    float acc[4][4][4];
#pragma unroll
    for (int i = 0; i < 4; ++i)
#pragma unroll
        for (int j = 0; j < 4; ++j)
#pragma unroll
            for (int v = 0; v < 4; ++v) acc[i][j][v] = 0.f;

    int arow[4], acol[4];
    const float* agp[4];
    const float* bgp[4];
#pragma unroll
    for (int i = 0; i < 4; ++i) {
        int lin = tid + i * 256;
        arow[i] = lin >> 3;
        acol[i] = (lin & 7) << 2;
        int gm = bm + arow[i]; gm = gm < M ? gm : M - 1;
        agp[i] = A + (size_t)gm * K + acol[i];
        int gn = bn + arow[i]; gn = gn < N ? gn : N - 1;
        bgp[i] = B + (size_t)gn * K + acol[i];
    }

    const unsigned aBase = smu + ((wm + (lane & 15)) * PADW + ((lane >> 4) << 2)) * 4u;
    const unsigned bBase = smu + (BOFF_F +
        (wn + ((lane >> 4) << 3) + (lane & 7)) * PADW + (((lane >> 3) & 1) << 2)) * 4u;

    const int KT = K >> 5;

#pragma unroll
    for (int i = 0; i < 4; ++i) {
        cp_async16(smu + (arow[i] * PADW + acol[i]) * 4u, agp[i]);
        cp_async16(smu + (BOFF_F + arow[i] * PADW + acol[i]) * 4u, bgp[i]);
    }
    asm volatile("cp.async.commit_group;");

    for (int kt = 0; kt < KT; ++kt) {
        if (kt + 1 < KT) {
            int s = (kt + 1) & 1;
            int k0 = (kt + 1) << 5;
#pragma unroll
            for (int i = 0; i < 4; ++i) {
                cp_async16(smu + (s * ASTAGE_F + arow[i] * PADW + acol[i]) * 4u, agp[i] + k0);
                cp_async16(smu + (BOFF_F + s * BSTAGE_F + arow[i] * PADW + acol[i]) * 4u, bgp[i] + k0);
            }
            asm volatile("cp.async.commit_group;");
            asm volatile("cp.async.wait_group 1;");
        } else {
            asm volatile("cp.async.wait_group 0;");
        }
        __syncthreads();

        const int s = kt & 1;
        const unsigned aw = aBase + s * (ASTAGE_F * 4u);
        const unsigned bw = bBase + s * (BSTAGE_F * 4u);
#pragma unroll
        for (int kk = 0; kk < 32; kk += 8) {
            unsigned af[4][4];
            unsigned bf[4][2];
#pragma unroll
            for (int mi = 0; mi < 4; ++mi)
                ldm_x4(af[mi], aw + (mi * 16 * PADW + kk) * 4u);
#pragma unroll
            for (int p = 0; p < 2; ++p) {
                unsigned t[4];
                ldm_x4(t, bw + (p * 16 * PADW + kk) * 4u);
                bf[p * 2][0] = t[0]; bf[p * 2][1] = t[1];
                bf[p * 2 + 1][0] = t[2]; bf[p * 2 + 1][1] = t[3];
            }
#pragma unroll
            for (int mi = 0; mi < 4; ++mi)
#pragma unroll
                for (int nj = 0; nj < 4; ++nj)
                    mma_tf32(acc[mi][nj], af[mi], bf[nj]);
        }
        __syncthreads();
    }

#pragma unroll
    for (int mi = 0; mi < 4; ++mi) {
        int gm0 = bm + wm + mi * 16 + (lane >> 2);
#pragma unroll
        for (int nj = 0; nj < 4; ++nj) {
            int gn = bn + wn + nj * 8 + ((lane & 3) << 1);
            if (gn < N) {
                if (gm0 < M)
                    *reinterpret_cast<float2*>(&C[(size_t)gm0 * N + gn]) =
                        make_float2(acc[mi][nj][0], acc[mi][nj][1]);
                if (gm0 + 8 < M)
                    *reinterpret_cast<float2*>(&C[(size_t)(gm0 + 8) * N + gn]) =
                        make_float2(acc[mi][nj][2], acc[mi][nj][3]);
            }
        }
    }
}

// ---------------- fp32 fallback GEMM ----------------
#define BK 16
__global__ __launch_bounds__(256) void gemm_nt(
    const float* __restrict__ A, const float* __restrict__ B,
    float* __restrict__ C, int M, int N, int K)
{
    __shared__ float As[BK][128];
    __shared__ float Bs[BK][128];
    const int bm = blockIdx.y * 128;
    const int bn = blockIdx.x * 128;
    const int tid = threadIdx.x;
    const int tcol = (tid & 15) * 8;
    const int trow = (tid >> 4) * 8;

    float acc[8][8];
#pragma unroll
    for (int i = 0; i < 8; ++i)
#pragma unroll
        for (int j = 0; j < 8; ++j) acc[i][j] = 0.f;

    for (int k0 = 0; k0 < K; k0 += BK) {
#pragma unroll
        for (int it = 0; it < 2; ++it) {
            int lin = tid + it * 256;
            int r  = lin >> 2;
            int c4 = (lin & 3) << 2;
            int gm = bm + r; gm = gm < M ? gm : M - 1;
            float4 va = *reinterpret_cast<const float4*>(A + (size_t)gm * K + k0 + c4);
            As[c4 + 0][r] = va.x; As[c4 + 1][r] = va.y;
            As[c4 + 2][r] = va.z; As[c4 + 3][r] = va.w;
            int gn = bn + r; gn = gn < N ? gn : N - 1;
            float4 vb = *reinterpret_cast<const float4*>(B + (size_t)gn * K + k0 + c4);
            Bs[c4 + 0][r] = vb.x; Bs[c4 + 1][r] = vb.y;
            Bs[c4 + 2][r] = vb.z; Bs[c4 + 3][r] = vb.w;
        }
        __syncthreads();
#pragma unroll
        for (int k = 0; k < BK; ++k) {
            float4 a0 = *reinterpret_cast<const float4*>(&As[k][trow]);
            float4 a1 = *reinterpret_cast<const float4*>(&As[k][trow + 4]);
            float4 b0 = *reinterpret_cast<const float4*>(&Bs[k][tcol]);
            float4 b1 = *reinterpret_cast<const float4*>(&Bs[k][tcol + 4]);
            float ar[8] = {a0.x, a0.y, a0.z, a0.w, a1.x, a1.y, a1.z, a1.w};
            float br[8] = {b0.x, b0.y, b0.z, b0.w, b1.x, b1.y, b1.z, b1.w};
#pragma unroll
            for (int i = 0; i < 8; ++i)
#pragma unroll
                for (int j = 0; j < 8; ++j)
                    acc[i][j] = fmaf(ar[i], br[j], acc[i][j]);
        }
        __syncthreads();
    }

#pragma unroll
    for (int i = 0; i < 8; ++i) {
        int gm = bm + trow + i;
        if (gm >= M) break;
#pragma unroll
        for (int j = 0; j < 8; ++j) {
            int gn = bn + tcol + j;
            if (gn < N) C[(size_t)gm * N + gn] = acc[i][j];
        }
    }
}

// ---------------- prep ----------------
__global__ void cvt_tf32_vec(const float* __restrict__ in, float* __restrict__ out, int n4)
{
    int i = blockIdx.x * blockDim.x + threadIdx.x;
    if (i >= n4) return;
    float4 v = reinterpret_cast<const float4*>(in)[i];
    v.x = f2tf_f(v.x); v.y = f2tf_f(v.y); v.z = f2tf_f(v.z); v.w = f2tf_f(v.w);
    reinterpret_cast<float4*>(out)[i] = v;
}

__global__ void prep_weights(const float* __restrict__ Whh, const float* __restrict__ W2,
                             float* __restrict__ Whhc, float* __restrict__ W2c)
{
    int idx = blockIdx.x * blockDim.x + threadIdx.x;
    if (idx < 196608) Whhc[idx] = f2tf_f(Whh[idx]);
    else if (idx < 196608 + 65536) {
        int i = idx - 196608;
        W2c[i] = f2tf_f(W2[i]);
    }
}

// ---------------- CSR build ----------------
__global__ void edge_hist(const int* __restrict__ fg, int* __restrict__ deg, int E)
{
    int e = blockIdx.x * blockDim.x + threadIdx.x;
    if (e >= E) return;
    atomicAdd(&deg[fg[E + e]], 1);
}

// phase 1: per-block (1024) exclusive scan; write block totals
__global__ void scan_blocks(const int* __restrict__ deg, int* __restrict__ start,
                            int* __restrict__ bsum, int nnode)
{
    __shared__ int ws[32];
    const int tid = threadIdx.x, lane = tid & 31, w = tid >> 5;
    int gid = blockIdx.x * 1024 + tid;
    int v = (gid < nnode) ? deg[gid] : 0;
    int x = v;
#pragma unroll
    for (int o = 1; o < 32; o <<= 1) {
        int y = __shfl_up_sync(0xFFFFFFFFu, x, o);
        if (lane >= o) x += y;
    }
    if (lane == 31) ws[w] = x;
    __syncthreads();
    if (w == 0) {
        int s = ws[lane];
#pragma unroll
        for (int o = 1; o < 32; o <<= 1) {
            int y = __shfl_up_sync(0xFFFFFFFFu, s, o);
            if (lane >= o) s += y;
        }
        ws[lane] = s;
    }
    __syncthreads();
    int excl = x - v + (w > 0 ? ws[w - 1] : 0);
    if (gid < nnode) start[gid] = excl;
    if (tid == 0) bsum[blockIdx.x] = ws[31];
}

// phase 2: exclusive scan of block totals (nb <= 1024), in place; bsum[nb] = grand total
__global__ void scan_totals(int* __restrict__ bsum, int nb)
{
    __shared__ int ws[32];
    const int tid = threadIdx.x, lane = tid & 31, w = tid >> 5;
    int v = (tid < nb) ? bsum[tid] : 0;
    int x = v;
#pragma unroll
    for (int o = 1; o < 32; o <<= 1) {
        int y = __shfl_up_sync(0xFFFFFFFFu, x, o);
        if (lane >= o) x += y;
    }
    if (lane == 31) ws[w] = x;
    __syncthreads();
    if (w == 0) {
        int s = ws[lane];
#pragma unroll
        for (int o = 1; o < 32; o <<= 1) {
            int y = __shfl_up_sync(0xFFFFFFFFu, s, o);
            if (lane >= o) s += y;
        }
        ws[lane] = s;
    }
    __syncthreads();
    int excl = x - v + (w > 0 ? ws[w - 1] : 0);
    if (tid < nb) bsum[tid] = excl;
    if (tid == 0) bsum[nb] = ws[31];
}

// phase 3: add block offsets; set start[nnode]
__global__ void add_offsets(int* __restrict__ start, const int* __restrict__ bsum,
                            int nnode, int nb)
{
    int gid = blockIdx.x * blockDim.x + threadIdx.x;
    if (gid < nnode) start[gid] += bsum[gid >> 10];
    if (gid == 0) start[nnode] = bsum[nb];
}

__global__ void csr_fill(const int* __restrict__ fg, const int* __restrict__ start,
                         int* __restrict__ cursor, int* __restrict__ csr, int E)
{
    int e = blockIdx.x * blockDim.x + threadIdx.x;
    if (e >= E) return;
    int dst = fg[E + e];
    int slot = atomicAdd(&cursor[dst], 1);
    csr[start[dst] + slot] = fg[e];
}

// aggE[dst] = cvt_tf32( sum_{e->dst} emb[src_e] )   (one block of 256 per node)
__global__ __launch_bounds__(256) void gather_agg(
    const int* __restrict__ start, const int* __restrict__ csr,
    const float* __restrict__ emb, float* __restrict__ aggE)
{
    int d = blockIdx.x;
    int tid = threadIdx.x;
    int s0 = start[d], s1 = start[d + 1];
    float acc = 0.f;
    for (int j = s0; j < s1; ++j) {
        int src = csr[j];
        acc += emb[(size_t)src * H + tid];
    }
    aggE[(size_t)d * H + tid] = f2tf_f(acc);
}

// ---------------- small helpers ----------------
__global__ void gru_elementwise(const float* __restrict__ gi, const float* __restrict__ gh,
                                const float* __restrict__ emb,
                                const float* __restrict__ bih, const float* __restrict__ bhh,
                                float* __restrict__ hidden, int NNODE)
{
    long long idx = (long long)blockIdx.x * blockDim.x + threadIdx.x;
    if (idx >= (long long)NNODE * H) return;
    int n = (int)(idx >> 8), h = (int)(idx & 255);
    size_t base = (size_t)n * 768;
    float ir = gi[base + h]       + bih[h];
    float hr = gh[base + h]       + bhh[h];
    float iz = gi[base + 256 + h] + bih[256 + h];
    float hz = gh[base + 256 + h] + bhh[256 + h];
    float in_ = gi[base + 512 + h] + bih[512 + h];
    float hn  = gh[base + 512 + h] + bhh[512 + h];
    float r = 1.f / (1.f + expf(-(ir + hr)));
    float z = 1.f / (1.f + expf(-(iz + hz)));
    float nn = tanhf(in_ + r * hn);
    float e = emb[(size_t)n * H + h];
    hidden[(size_t)n * H + h] = (1.f - z) * nn + z * e;
}

__global__ void gather_relu(const int* __restrict__ x, const float* __restrict__ hidden,
                            float* __restrict__ h2, float* __restrict__ h2c, int N)
{
    long long idx = (long long)blockIdx.x * blockDim.x + threadIdx.x;
    if (idx >= (long long)N * H) return;
    int i = (int)(idx >> 8), h = (int)(idx & 255);
    int node = x[i] - 1;
    float v = hidden[(size_t)node * H + h];
    v = v > 0.f ? v : 0.f;
    h2[idx] = v;
    h2c[idx] = f2tf_f(v);
}

__global__ void last_max(const int* __restrict__ batch, int* __restrict__ lastidx, int N)
{
    int i = blockIdx.x * blockDim.x + threadIdx.x;
    if (i >= N) return;
    atomicMax(&lastidx[batch[i]], i);
}

__global__ void vn_gather(const float* __restrict__ h2, const int* __restrict__ lastidx,
                          float* __restrict__ vn, int B)
{
    int idx = blockIdx.x * blockDim.x + threadIdx.x;
    if (idx >= B * H) return;
    int b = idx >> 8, h = idx & 255;
    vn[idx] = h2[(size_t)lastidx[b] * H + h];
}

__global__ void attn_kernel(const float* __restrict__ a, const float* __restrict__ bth,
                            const float* __restrict__ h2, const int* __restrict__ batch,
                            const float* __restrict__ W1_b, const float* __restrict__ W2_b,
                            const float* __restrict__ q_w, const float* __restrict__ q_b,
                            float* __restrict__ sg)
{
    __shared__ float red[256];
    int i = blockIdx.x;
    int h = threadIdx.x;
    int b = batch[i];
    float g = a[(size_t)b * H + h] + W1_b[h] + bth[(size_t)i * H + h] + W2_b[h];
    g = 1.f / (1.f + expf(-g));
    red[h] = g * q_w[h];
    __syncthreads();
#pragma unroll
    for (int s = 128; s > 0; s >>= 1) {
        if (h < s) red[h] += red[h + s];
        __syncthreads();
    }
    float alpha = red[0] + q_b[0];
    atomicAdd(&sg[(size_t)b * H + h], alpha * h2[(size_t)i * H + h]);
}

__global__ void concat_vns(const float* __restrict__ vn, const float* __restrict__ sg,
                           float* __restrict__ vns, int B)
{
    int idx = blockIdx.x * blockDim.x + threadIdx.x;
    if (idx >= B * 512) return;
    int b = idx >> 9, c = idx & 511;
    vns[idx] = (c < 256) ? vn[b * 256 + c] : sg[b * 256 + (c - 256)];
}

__global__ void add_bias_cvt(float* __restrict__ sh, const float* __restrict__ W3_b, int B)
{
    int idx = blockIdx.x * blockDim.x + threadIdx.x;
    if (idx >= B * H) return;
    sh[idx] = f2tf_f(sh[idx] + W3_b[idx & 255]);
}

__global__ void edges_to_float(const int* __restrict__ ei, float* __restrict__ out, int n)
{
    int idx = blockIdx.x * blockDim.x + threadIdx.x;
    if (idx >= n) return;
    out[idx] = (float)ei[idx];
}

// ---------------- driver ----------------
extern "C" void kernel_launch(void* const* d_in, const int* in_sizes, int n_in,
                              void* d_out, int out_size)
{
    const int*   x      = (const int*)d_in[0];
    const int*   batch  = (const int*)d_in[1];
    const int*   ei     = (const int*)d_in[2];
    const int*   fg     = (const int*)d_in[3];
    const float* emb    = (const float*)d_in[4];
    const float* ggnn_W = (const float*)d_in[5];
    const float* Wih    = (const float*)d_in[6];
    const float* Whh    = (const float*)d_in[7];
    const float* bih    = (const float*)d_in[8];
    const float* bhh    = (const float*)d_in[9];
    const float* W1_w   = (const float*)d_in[10];
    const float* W1_b   = (const float*)d_in[11];
    const float* W2_w   = (const float*)d_in[12];
    const float* W2_b   = (const float*)d_in[13];
    const float* q_w    = (const float*)d_in[14];
    const float* q_b    = (const float*)d_in[15];
    const float* W3_w   = (const float*)d_in[16];
    const float* W3_b   = (const float*)d_in[17];
    float* out = (float*)d_out;

    const int N     = in_sizes[0];          // 12288
    const int E     = in_sizes[3] / 2;      // 500000
    const int NNODE = in_sizes[4] / H;      // 50000
    const long long scores_elems = (long long)out_size - (long long)N * H - 2LL * N;
    const int B = (int)(scores_elems / NNODE);   // 1024

    static int smem_set = 0;
    if (!smem_set) {
        cudaFuncSetAttribute(gemm_tf32_nt, cudaFuncAttributeMaxDynamicSharedMemorySize, SMEM_BYTES);
        smem_set = 1;
    }

    float *aggE, *gi, *gh, *hidden, *embc, *F, *Fc, *Whhc, *W2c, *h2c;
    float *vn, *a, *bth, *sg, *vns, *sh;
    int *lastidx, *deg, *startp, *bsum, *cursor, *csr;
    cudaGetSymbolAddress((void**)&aggE,   d_aggE);
    cudaGetSymbolAddress((void**)&gi,     d_gi);
    cudaGetSymbolAddress((void**)&gh,     d_gh);
    cudaGetSymbolAddress((void**)&hidden, d_hidden);
    cudaGetSymbolAddress((void**)&embc,   d_embc);
    cudaGetSymbolAddress((void**)&F,      d_F);
    cudaGetSymbolAddress((void**)&Fc,     d_Fc);
    cudaGetSymbolAddress((void**)&Whhc,   d_Whhc);
    cudaGetSymbolAddress((void**)&W2c,    d_W2c);
    cudaGetSymbolAddress((void**)&h2c,    d_h2c);
    cudaGetSymbolAddress((void**)&vn,     d_vn);
    cudaGetSymbolAddress((void**)&a,      d_a);
    cudaGetSymbolAddress((void**)&bth,    d_bth);
    cudaGetSymbolAddress((void**)&sg,     d_sg);
    cudaGetSymbolAddress((void**)&vns,    d_vns);
    cudaGetSymbolAddress((void**)&sh,     d_sh);
    cudaGetSymbolAddress((void**)&lastidx, d_lastidx);
    cudaGetSymbolAddress((void**)&deg,    d_deg);
    cudaGetSymbolAddress((void**)&startp, d_start);
    cudaGetSymbolAddress((void**)&bsum,   d_bsum);
    cudaGetSymbolAddress((void**)&cursor, d_cursor);
    cudaGetSymbolAddress((void**)&csr,    d_csr);

    float* scores = out;
    float* h2     = out + scores_elems;
    float* eout   = out + scores_elems + (long long)N * H;

    const int T = 256;
    dim3 blk(T);
    auto cdiv = [](long long v, long long d) { return (unsigned)((v + d - 1) / d); };
    const int NB = (int)cdiv(NNODE, 1024);

    // 0) prep: F = Wih @ ggnn_W^T ; tf32 conversions; CSR build (parallel scan)
    gemm_nt<<<dim3(2, 6), blk>>>(Wih, ggnn_W, F, 3 * H, H, H);
    cvt_tf32_vec<<<cdiv(768 * 256 / 4, T), blk>>>(F, Fc, 768 * 256 / 4);
    cvt_tf32_vec<<<cdiv((long long)NNODE * H / 4, T), blk>>>(emb, embc, NNODE * H / 4);
    prep_weights<<<cdiv(196608 + 65536, T), blk>>>(Whh, W2_w, Whhc, W2c);
    cudaMemsetAsync(deg, 0, (size_t)NNODE * sizeof(int));
    edge_hist<<<cdiv(E, T), blk>>>(fg, deg, E);
    scan_blocks<<<NB, 1024>>>(deg, startp, bsum, NNODE);
    scan_totals<<<1, 1024>>>(bsum, NB);
    add_offsets<<<cdiv(NNODE, 1024), 1024>>>(startp, bsum, NNODE, NB);
    cudaMemsetAsync(cursor, 0, (size_t)NNODE * sizeof(int));
    csr_fill<<<cdiv(E, T), blk>>>(fg, startp, cursor, csr, E);

    // 1) aggE = segment_sum(emb[src], dst)  (fused: replaces m GEMM + old gather)
    gather_agg<<<NNODE, blk>>>(startp, csr, emb, aggE);

    // 2) gi = aggE @ F^T ; gh = emb @ Whh^T
    gemm_tf32_nt<<<dim3(cdiv(3 * H, 128), cdiv(NNODE, 128)), blk, SMEM_BYTES>>>(aggE, Fc, gi, NNODE, 3 * H, H);
    gemm_tf32_nt<<<dim3(cdiv(3 * H, 128), cdiv(NNODE, 128)), blk, SMEM_BYTES>>>(embc, Whhc, gh, NNODE, 3 * H, H);

    // 3) GRU cell -> hidden_all
    gru_elementwise<<<cdiv((long long)NNODE * H, T), blk>>>(gi, gh, emb, bih, bhh, hidden, NNODE);

    // 4) h2 = relu(hidden[x-1]) (+ tf32 copy)
    gather_relu<<<cdiv((long long)N * H, T), blk>>>(x, hidden, h2, h2c, N);

    // 5) last node per session
    cudaMemsetAsync(lastidx, 0xFF, (size_t)B * sizeof(int));
    last_max<<<cdiv(N, T), blk>>>(batch, lastidx, N);
    vn_gather<<<cdiv(B * H, T), blk>>>(h2, lastidx, vn, B);

    // 6) attention
    gemm_nt<<<dim3(cdiv(H, 128), cdiv(B, 128)), blk>>>(vn, W1_w, a, B, H, H);
    gemm_tf32_nt<<<dim3(cdiv(H, 128), cdiv(N, 128)), blk, SMEM_BYTES>>>(h2c, W2c, bth, N, H, H);
    cudaMemsetAsync(sg, 0, (size_t)B * H * sizeof(float));
    attn_kernel<<<N, blk>>>(a, bth, h2, batch, W1_b, W2_b, q_w, q_b, sg);

    // 7) s_h = [vn | s_g] @ W3^T + b3, tf32-round
    concat_vns<<<cdiv(B * 512, T), blk>>>(vn, sg, vns, B);
    gemm_nt<<<dim3(cdiv(H, 128), cdiv(B, 128)), blk>>>(vns, W3_w, sh, B, H, 2 * H);
    add_bias_cvt<<<cdiv(B * H, T), blk>>>(sh, W3_b, B);

    // 8) scores = s_h @ emb^T
    gemm_tf32_nt<<<dim3(cdiv(NNODE, 128), cdiv(B, 128)), blk, SMEM_BYTES>>>(sh, embc, scores, B, NNODE, H);

    // 9) passthrough edge_index as float
    edges_to_float<<<cdiv(2 * N, T), blk>>>(ei, eout, 2 * N);
}

// round 12
// speedup vs baseline: 4.3795x; 1.5678x over previous
#include <cuda_runtime.h>
#include <cstdint>
#include <cstddef>

#define H 256

// ---------------- scratch ----------------
__device__ float d_aggEp[12288 * 256];     // per-position segsum(emb), tf32-rounded
__device__ float d_gi[12288 * 768];
__device__ float d_gh[12288 * 768];
__device__ float d_embc[50000 * 256];      // tf32 emb
__device__ float d_F[768 * 256];           // Wih @ ggnn_W^T (fp32)
__device__ float d_Fc[768 * 256];          // tf32
__device__ float d_Whhc[768 * 256];
__device__ float d_W2c[256 * 256];
__device__ float d_h2c[12288 * 256];
__device__ float d_vn[1024 * 256];
__device__ float d_a[1024 * 256];
__device__ float d_bth[12288 * 256];
__device__ float d_sg[1024 * 256];
__device__ float d_vns[1024 * 512];
__device__ float d_sh[1024 * 256];
__device__ int   d_lastidx[1024];
__device__ int   d_deg[50176];
__device__ int   d_start[50001];
__device__ int   d_bsum[80];
__device__ int   d_cursor[50000];
__device__ int   d_csr[500000];

// ---------------- helpers ----------------
__device__ __forceinline__ float f2tf_f(float f) {
    unsigned u;
    asm("cvt.rna.tf32.f32 %0, %1;" : "=r"(u) : "f"(f));
    return __uint_as_float(u);
}
__device__ __forceinline__ void ldm_x4(unsigned r[4], unsigned addr) {
    asm volatile("ldmatrix.sync.aligned.m8n8.x4.shared.b16 {%0,%1,%2,%3}, [%4];"
                 : "=r"(r[0]), "=r"(r[1]), "=r"(r[2]), "=r"(r[3]) : "r"(addr));
}
__device__ __forceinline__ void mma_tf32(float d[4], const unsigned a[4], const unsigned b[2]) {
    asm volatile("mma.sync.aligned.m16n8k8.row.col.f32.tf32.tf32.f32 "
                 "{%0,%1,%2,%3}, {%4,%5,%6,%7}, {%8,%9}, {%0,%1,%2,%3};"
                 : "+f"(d[0]), "+f"(d[1]), "+f"(d[2]), "+f"(d[3])
                 : "r"(a[0]), "r"(a[1]), "r"(a[2]), "r"(a[3]), "r"(b[0]), "r"(b[1]));
}
__device__ __forceinline__ void cp_async16(unsigned saddr, const void* gptr) {
    asm volatile("cp.async.cg.shared.global [%0], [%1], 16;" :: "r"(saddr), "l"(gptr));
}

// ---------------- tf32 tensor-core NT GEMM (operands pre-rounded) ----------------
// C[m,n] = sum_k A[ra,k]*B[n,k], ra = Aidx ? Aidx[m]-1 : m (Aidx is 1-based ids).
// Block 128x128, BK=32, 8 warps of 64x32, 2 CTAs/SM. K % 32 == 0.
#define PADW 36
#define ASTAGE_F (128 * PADW)
#define BOFF_F   (2 * ASTAGE_F)
#define BSTAGE_F (128 * PADW)
#define SMEM_BYTES ((BOFF_F + 2 * BSTAGE_F) * 4)

__global__ __launch_bounds__(256, 2) void gemm_tf32_nt(
    const float* __restrict__ A, const int* __restrict__ Aidx,
    const float* __restrict__ B,
    float* __restrict__ C, int M, int N, int K)
{
    extern __shared__ float sm[];
    const unsigned smu = (unsigned)__cvta_generic_to_shared(sm);

    const int tid  = threadIdx.x;
    const int warp = tid >> 5;
    const int lane = tid & 31;
    const int bm = blockIdx.y * 128;
    const int bn = blockIdx.x * 128;
    const int wm = (warp & 1) * 64;
    const int wn = (warp >> 1) * 32;

    float acc[4][4][4];
#pragma unroll
    for (int i = 0; i < 4; ++i)
#pragma unroll
        for (int j = 0; j < 4; ++j)
#pragma unroll
            for (int v = 0; v < 4; ++v) acc[i][j][v] = 0.f;

    int arow[4], acol[4];
    const float* agp[4];
    const float* bgp[4];
#pragma unroll
    for (int i = 0; i < 4; ++i) {
        int lin = tid + i * 256;
        arow[i] = lin >> 3;
        acol[i] = (lin & 7) << 2;
        int gm = bm + arow[i]; gm = gm < M ? gm : M - 1;
        int ra = Aidx ? (Aidx[gm] - 1) : gm;
        agp[i] = A + (size_t)ra * K + acol[i];
        int gn = bn + arow[i]; gn = gn < N ? gn : N - 1;
        bgp[i] = B + (size_t)gn * K + acol[i];
    }

    const unsigned aBase = smu + ((wm + (lane & 15)) * PADW + ((lane >> 4) << 2)) * 4u;
    const unsigned bBase = smu + (BOFF_F +
        (wn + ((lane >> 4) << 3) + (lane & 7)) * PADW + (((lane >> 3) & 1) << 2)) * 4u;

    const int KT = K >> 5;

#pragma unroll
    for (int i = 0; i < 4; ++i) {
        cp_async16(smu + (arow[i] * PADW + acol[i]) * 4u, agp[i]);
        cp_async16(smu + (BOFF_F + arow[i] * PADW + acol[i]) * 4u, bgp[i]);
    }
    asm volatile("cp.async.commit_group;");

    for (int kt = 0; kt < KT; ++kt) {
        if (kt + 1 < KT) {
            int s = (kt + 1) & 1;
            int k0 = (kt + 1) << 5;
#pragma unroll
            for (int i = 0; i < 4; ++i) {
                cp_async16(smu + (s * ASTAGE_F + arow[i] * PADW + acol[i]) * 4u, agp[i] + k0);
                cp_async16(smu + (BOFF_F + s * BSTAGE_F + arow[i] * PADW + acol[i]) * 4u, bgp[i] + k0);
            }
            asm volatile("cp.async.commit_group;");
            asm volatile("cp.async.wait_group 1;");
        } else {
            asm volatile("cp.async.wait_group 0;");
        }
        __syncthreads();

        const int s = kt & 1;
        const unsigned aw = aBase + s * (ASTAGE_F * 4u);
        const unsigned bw = bBase + s * (BSTAGE_F * 4u);
#pragma unroll
        for (int kk = 0; kk < 32; kk += 8) {
            unsigned af[4][4];
            unsigned bf[4][2];
#pragma unroll
            for (int mi = 0; mi < 4; ++mi)
                ldm_x4(af[mi], aw + (mi * 16 * PADW + kk) * 4u);
#pragma unroll
            for (int p = 0; p < 2; ++p) {
                unsigned t[4];
                ldm_x4(t, bw + (p * 16 * PADW + kk) * 4u);
                bf[p * 2][0] = t[0]; bf[p * 2][1] = t[1];
                bf[p * 2 + 1][0] = t[2]; bf[p * 2 + 1][1] = t[3];
            }
#pragma unroll
            for (int mi = 0; mi < 4; ++mi)
#pragma unroll
                for (int nj = 0; nj < 4; ++nj)
                    mma_tf32(acc[mi][nj], af[mi], bf[nj]);
        }
        __syncthreads();
    }

#pragma unroll
    for (int mi = 0; mi < 4; ++mi) {
        int gm0 = bm + wm + mi * 16 + (lane >> 2);
#pragma unroll
        for (int nj = 0; nj < 4; ++nj) {
            int gn = bn + wn + nj * 8 + ((lane & 3) << 1);
            if (gn < N) {
                if (gm0 < M)
                    *reinterpret_cast<float2*>(&C[(size_t)gm0 * N + gn]) =
                        make_float2(acc[mi][nj][0], acc[mi][nj][1]);
                if (gm0 + 8 < M)
                    *reinterpret_cast<float2*>(&C[(size_t)(gm0 + 8) * N + gn]) =
                        make_float2(acc[mi][nj][2], acc[mi][nj][3]);
            }
        }
    }
}

// ---------------- fp32 fallback GEMM ----------------
#define BK 16
__global__ __launch_bounds__(256) void gemm_nt(
    const float* __restrict__ A, const float* __restrict__ B,
    float* __restrict__ C, int M, int N, int K)
{
    __shared__ float As[BK][128];
    __shared__ float Bs[BK][128];
    const int bm = blockIdx.y * 128;
    const int bn = blockIdx.x * 128;
    const int tid = threadIdx.x;
    const int tcol = (tid & 15) * 8;
    const int trow = (tid >> 4) * 8;

    float acc[8][8];
#pragma unroll
    for (int i = 0; i < 8; ++i)
#pragma unroll
        for (int j = 0; j < 8; ++j) acc[i][j] = 0.f;

    for (int k0 = 0; k0 < K; k0 += BK) {
#pragma unroll
        for (int it = 0; it < 2; ++it) {
            int lin = tid + it * 256;
            int r  = lin >> 2;
            int c4 = (lin & 3) << 2;
            int gm = bm + r; gm = gm < M ? gm : M - 1;
            float4 va = *reinterpret_cast<const float4*>(A + (size_t)gm * K + k0 + c4);
            As[c4 + 0][r] = va.x; As[c4 + 1][r] = va.y;
            As[c4 + 2][r] = va.z; As[c4 + 3][r] = va.w;
            int gn = bn + r; gn = gn < N ? gn : N - 1;
            float4 vb = *reinterpret_cast<const float4*>(B + (size_t)gn * K + k0 + c4);
            Bs[c4 + 0][r] = vb.x; Bs[c4 + 1][r] = vb.y;
            Bs[c4 + 2][r] = vb.z; Bs[c4 + 3][r] = vb.w;
        }
        __syncthreads();
#pragma unroll
        for (int k = 0; k < BK; ++k) {
            float4 a0 = *reinterpret_cast<const float4*>(&As[k][trow]);
            float4 a1 = *reinterpret_cast<const float4*>(&As[k][trow + 4]);
            float4 b0 = *reinterpret_cast<const float4*>(&Bs[k][tcol]);
            float4 b1 = *reinterpret_cast<const float4*>(&Bs[k][tcol + 4]);
            float ar[8] = {a0.x, a0.y, a0.z, a0.w, a1.x, a1.y, a1.z, a1.w};
            float br[8] = {b0.x, b0.y, b0.z, b0.w, b1.x, b1.y, b1.z, b1.w};
#pragma unroll
            for (int i = 0; i < 8; ++i)
#pragma unroll
                for (int j = 0; j < 8; ++j)
                    acc[i][j] = fmaf(ar[i], br[j], acc[i][j]);
        }
        __syncthreads();
    }

#pragma unroll
    for (int i = 0; i < 8; ++i) {
        int gm = bm + trow + i;
        if (gm >= M) break;
#pragma unroll
        for (int j = 0; j < 8; ++j) {
            int gn = bn + tcol + j;
            if (gn < N) C[(size_t)gm * N + gn] = acc[i][j];
        }
    }
}

// ---------------- prep ----------------
__global__ void cvt_tf32_vec(const float* __restrict__ in, float* __restrict__ out, int n4)
{
    int i = blockIdx.x * blockDim.x + threadIdx.x;
    if (i >= n4) return;
    float4 v = reinterpret_cast<const float4*>(in)[i];
    v.x = f2tf_f(v.x); v.y = f2tf_f(v.y); v.z = f2tf_f(v.z); v.w = f2tf_f(v.w);
    reinterpret_cast<float4*>(out)[i] = v;
}

__global__ void prep_weights(const float* __restrict__ Whh, const float* __restrict__ W2,
                             float* __restrict__ Whhc, float* __restrict__ W2c)
{
    int idx = blockIdx.x * blockDim.x + threadIdx.x;
    if (idx < 196608) Whhc[idx] = f2tf_f(Whh[idx]);
    else if (idx < 196608 + 65536) {
        int i = idx - 196608;
        W2c[i] = f2tf_f(W2[i]);
    }
}

// ---------------- CSR build ----------------
__global__ void edge_hist(const int* __restrict__ fg, int* __restrict__ deg, int E)
{
    int e = blockIdx.x * blockDim.x + threadIdx.x;
    if (e >= E) return;
    atomicAdd(&deg[fg[E + e]], 1);
}

__global__ void scan_blocks(const int* __restrict__ deg, int* __restrict__ start,
                            int* __restrict__ bsum, int nnode)
{
    __shared__ int ws[32];
    const int tid = threadIdx.x, lane = tid & 31, w = tid >> 5;
    int gid = blockIdx.x * 1024 + tid;
    int v = (gid < nnode) ? deg[gid] : 0;
    int x = v;
#pragma unroll
    for (int o = 1; o < 32; o <<= 1) {
        int y = __shfl_up_sync(0xFFFFFFFFu, x, o);
        if (lane >= o) x += y;
    }
    if (lane == 31) ws[w] = x;
    __syncthreads();
    if (w == 0) {
        int s = ws[lane];
#pragma unroll
        for (int o = 1; o < 32; o <<= 1) {
            int y = __shfl_up_sync(0xFFFFFFFFu, s, o);
            if (lane >= o) s += y;
        }
        ws[lane] = s;
    }
    __syncthreads();
    int excl = x - v + (w > 0 ? ws[w - 1] : 0);
    if (gid < nnode) start[gid] = excl;
    if (tid == 0) bsum[blockIdx.x] = ws[31];
}

__global__ void scan_totals(int* __restrict__ bsum, int nb)
{
    __shared__ int ws[32];
    const int tid = threadIdx.x, lane = tid & 31, w = tid >> 5;
    int v = (tid < nb) ? bsum[tid] : 0;
    int x = v;
#pragma unroll
    for (int o = 1; o < 32; o <<= 1) {
        int y = __shfl_up_sync(0xFFFFFFFFu, x, o);
        if (lane >= o) x += y;
    }
    if (lane == 31) ws[w] = x;
    __syncthreads();
    if (w == 0) {
        int s = ws[lane];
#pragma unroll
        for (int o = 1; o < 32; o <<= 1) {
            int y = __shfl_up_sync(0xFFFFFFFFu, s, o);
            if (lane >= o) s += y;
        }
        ws[lane] = s;
    }
    __syncthreads();
    int excl = x - v + (w > 0 ? ws[w - 1] : 0);
    if (tid < nb) bsum[tid] = excl;
    if (tid == 0) bsum[nb] = ws[31];
}

__global__ void add_offsets(int* __restrict__ start, const int* __restrict__ bsum,
                            int nnode, int nb)
{
    int gid = blockIdx.x * blockDim.x + threadIdx.x;
    if (gid < nnode) start[gid] += bsum[gid >> 10];
    if (gid == 0) start[nnode] = bsum[nb];
}

__global__ void csr_fill(const int* __restrict__ fg, const int* __restrict__ start,
                         int* __restrict__ cursor, int* __restrict__ csr, int E)
{
    int e = blockIdx.x * blockDim.x + threadIdx.x;
    if (e >= E) return;
    int dst = fg[E + e];
    int slot = atomicAdd(&cursor[dst], 1);
    csr[start[dst] + slot] = fg[e];
}

// per-position aggregation: aggEp[i] = cvt_tf32( sum_{e -> (x[i]-1)} emb[src_e] )
__global__ __launch_bounds__(256) void gather_agg_pos(
    const int* __restrict__ x, const int* __restrict__ start, const int* __restrict__ csr,
    const float* __restrict__ emb, float* __restrict__ aggEp)
{
    int i = blockIdx.x;
    int tid = threadIdx.x;
    int d = x[i] - 1;
    int s0 = start[d], s1 = start[d + 1];
    float acc = 0.f;
    for (int j = s0; j < s1; ++j) {
        int src = csr[j];
        acc += emb[(size_t)src * H + tid];
    }
    aggEp[(size_t)i * H + tid] = f2tf_f(acc);
}

// ---------------- fused GRU + relu-gather (per position) ----------------
__global__ void gru_fused(const int* __restrict__ x,
                          const float* __restrict__ gi, const float* __restrict__ gh,
                          const float* __restrict__ emb,
                          const float* __restrict__ bih, const float* __restrict__ bhh,
                          float* __restrict__ h2, float* __restrict__ h2c, int N)
{
    long long idx = (long long)blockIdx.x * blockDim.x + threadIdx.x;
    if (idx >= (long long)N * H) return;
    int i = (int)(idx >> 8), h = (int)(idx & 255);
    size_t base = (size_t)i * 768;
    float ir = gi[base + h]       + bih[h];
    float hr = gh[base + h]       + bhh[h];
    float iz = gi[base + 256 + h] + bih[256 + h];
    float hz = gh[base + 256 + h] + bhh[256 + h];
    float in_ = gi[base + 512 + h] + bih[512 + h];
    float hn  = gh[base + 512 + h] + bhh[512 + h];
    float r = 1.f / (1.f + expf(-(ir + hr)));
    float z = 1.f / (1.f + expf(-(iz + hz)));
    float nn = tanhf(in_ + r * hn);
    int node = x[i] - 1;
    float e = emb[(size_t)node * H + h];
    float v = (1.f - z) * nn + z * e;
    v = v > 0.f ? v : 0.f;
    h2[idx] = v;
    h2c[idx] = f2tf_f(v);
}

// ---------------- small helpers ----------------
__global__ void last_max(const int* __restrict__ batch, int* __restrict__ lastidx, int N)
{
    int i = blockIdx.x * blockDim.x + threadIdx.x;
    if (i >= N) return;
    atomicMax(&lastidx[batch[i]], i);
}

__global__ void vn_gather(const float* __restrict__ h2, const int* __restrict__ lastidx,
                          float* __restrict__ vn, int B)
{
    int idx = blockIdx.x * blockDim.x + threadIdx.x;
    if (idx >= B * H) return;
    int b = idx >> 8, h = idx & 255;
    vn[idx] = h2[(size_t)lastidx[b] * H + h];
}

__global__ void attn_kernel(const float* __restrict__ a, const float* __restrict__ bth,
                            const float* __restrict__ h2, const int* __restrict__ batch,
                            const float* __restrict__ W1_b, const float* __restrict__ W2_b,
                            const float* __restrict__ q_w, const float* __restrict__ q_b,
                            float* __restrict__ sg)
{
    __shared__ float red[256];
    int i = blockIdx.x;
    int h = threadIdx.x;
    int b = batch[i];
    float g = a[(size_t)b * H + h] + W1_b[h] + bth[(size_t)i * H + h] + W2_b[h];
    g = 1.f / (1.f + expf(-g));
    red[h] = g * q_w[h];
    __syncthreads();
#pragma unroll
    for (int s = 128; s > 0; s >>= 1) {
        if (h < s) red[h] += red[h + s];
        __syncthreads();
    }
    float alpha = red[0] + q_b[0];
    atomicAdd(&sg[(size_t)b * H + h], alpha * h2[(size_t)i * H + h]);
}

__global__ void concat_vns(const float* __restrict__ vn, const float* __restrict__ sg,
                           float* __restrict__ vns, int B)
{
    int idx = blockIdx.x * blockDim.x + threadIdx.x;
    if (idx >= B * 512) return;
    int b = idx >> 9, c = idx & 511;
    vns[idx] = (c < 256) ? vn[b * 256 + c] : sg[b * 256 + (c - 256)];
}

__global__ void add_bias_cvt(float* __restrict__ sh, const float* __restrict__ W3_b, int B)
{
    int idx = blockIdx.x * blockDim.x + threadIdx.x;
    if (idx >= B * H) return;
    sh[idx] = f2tf_f(sh[idx] + W3_b[idx & 255]);
}

__global__ void edges_to_float(const int* __restrict__ ei, float* __restrict__ out, int n)
{
    int idx = blockIdx.x * blockDim.x + threadIdx.x;
    if (idx >= n) return;
    out[idx] = (float)ei[idx];
}

// ---------------- driver ----------------
extern "C" void kernel_launch(void* const* d_in, const int* in_sizes, int n_in,
                              void* d_out, int out_size)
{
    const int*   x      = (const int*)d_in[0];
    const int*   batch  = (const int*)d_in[1];
    const int*   ei     = (const int*)d_in[2];
    const int*   fg     = (const int*)d_in[3];
    const float* emb    = (const float*)d_in[4];
    const float* ggnn_W = (const float*)d_in[5];
    const float* Wih    = (const float*)d_in[6];
    const float* Whh    = (const float*)d_in[7];
    const float* bih    = (const float*)d_in[8];
    const float* bhh    = (const float*)d_in[9];
    const float* W1_w   = (const float*)d_in[10];
    const float* W1_b   = (const float*)d_in[11];
    const float* W2_w   = (const float*)d_in[12];
    const float* W2_b   = (const float*)d_in[13];
    const float* q_w    = (const float*)d_in[14];
    const float* q_b    = (const float*)d_in[15];
    const float* W3_w   = (const float*)d_in[16];
    const float* W3_b   = (const float*)d_in[17];
    float* out = (float*)d_out;

    const int N     = in_sizes[0];          // 12288
    const int E     = in_sizes[3] / 2;      // 500000
    const int NNODE = in_sizes[4] / H;      // 50000
    const long long scores_elems = (long long)out_size - (long long)N * H - 2LL * N;
    const int B = (int)(scores_elems / NNODE);   // 1024

    static int smem_set = 0;
    if (!smem_set) {
        cudaFuncSetAttribute(gemm_tf32_nt, cudaFuncAttributeMaxDynamicSharedMemorySize, SMEM_BYTES);
        smem_set = 1;
    }

    float *aggEp, *gi, *gh, *embc, *F, *Fc, *Whhc, *W2c, *h2c;
    float *vn, *a, *bth, *sg, *vns, *sh;
    int *lastidx, *deg, *startp, *bsum, *cursor, *csr;
    cudaGetSymbolAddress((void**)&aggEp,  d_aggEp);
    cudaGetSymbolAddress((void**)&gi,     d_gi);
    cudaGetSymbolAddress((void**)&gh,     d_gh);
    cudaGetSymbolAddress((void**)&embc,   d_embc);
    cudaGetSymbolAddress((void**)&F,      d_F);
    cudaGetSymbolAddress((void**)&Fc,     d_Fc);
    cudaGetSymbolAddress((void**)&Whhc,   d_Whhc);
    cudaGetSymbolAddress((void**)&W2c,    d_W2c);
    cudaGetSymbolAddress((void**)&h2c,    d_h2c);
    cudaGetSymbolAddress((void**)&vn,     d_vn);
    cudaGetSymbolAddress((void**)&a,      d_a);
    cudaGetSymbolAddress((void**)&bth,    d_bth);
    cudaGetSymbolAddress((void**)&sg,     d_sg);
    cudaGetSymbolAddress((void**)&vns,    d_vns);
    cudaGetSymbolAddress((void**)&sh,     d_sh);
    cudaGetSymbolAddress((void**)&lastidx, d_lastidx);
    cudaGetSymbolAddress((void**)&deg,    d_deg);
    cudaGetSymbolAddress((void**)&startp, d_start);
    cudaGetSymbolAddress((void**)&bsum,   d_bsum);
    cudaGetSymbolAddress((void**)&cursor, d_cursor);
    cudaGetSymbolAddress((void**)&csr,    d_csr);

    float* scores = out;
    float* h2     = out + scores_elems;
    float* eout   = out + scores_elems + (long long)N * H;

    const int T = 256;
    dim3 blk(T);
    auto cdiv = [](long long v, long long d) { return (unsigned)((v + d - 1) / d); };
    const int NB = (int)cdiv(NNODE, 1024);

    // 0) prep: F = Wih @ ggnn_W^T ; tf32 conversions; CSR build
    gemm_nt<<<dim3(2, 6), blk>>>(Wih, ggnn_W, F, 3 * H, H, H);
    cvt_tf32_vec<<<cdiv(768 * 256 / 4, T), blk>>>(F, Fc, 768 * 256 / 4);
    cvt_tf32_vec<<<cdiv((long long)NNODE * H / 4, T), blk>>>(emb, embc, NNODE * H / 4);
    prep_weights<<<cdiv(196608 + 65536, T), blk>>>(Whh, W2_w, Whhc, W2c);
    cudaMemsetAsync(deg, 0, (size_t)NNODE * sizeof(int));
    edge_hist<<<cdiv(E, T), blk>>>(fg, deg, E);
    scan_blocks<<<NB, 1024>>>(deg, startp, bsum, NNODE);
    scan_totals<<<1, 1024>>>(bsum, NB);
    add_offsets<<<cdiv(NNODE, 1024), 1024>>>(startp, bsum, NNODE, NB);
    cudaMemsetAsync(cursor, 0, (size_t)NNODE * sizeof(int));
    csr_fill<<<cdiv(E, T), blk>>>(fg, startp, cursor, csr, E);

    // 1) per-position aggregation (only session nodes)
    gather_agg_pos<<<N, blk>>>(x, startp, csr, emb, aggEp);

    // 2) gi = aggEp @ F^T ; gh = emb[x-1] @ Whh^T   (12288-row GEMMs)
    gemm_tf32_nt<<<dim3(cdiv(3 * H, 128), cdiv(N, 128)), blk, SMEM_BYTES>>>(aggEp, nullptr, Fc, gi, N, 3 * H, H);
    gemm_tf32_nt<<<dim3(cdiv(3 * H, 128), cdiv(N, 128)), blk, SMEM_BYTES>>>(embc, x, Whhc, gh, N, 3 * H, H);

    // 3) fused GRU + relu -> h2 (d_out) + h2c (tf32)
    gru_fused<<<cdiv((long long)N * H, T), blk>>>(x, gi, gh, emb, bih, bhh, h2, h2c, N);

    // 4) last node per session
    cudaMemsetAsync(lastidx, 0xFF, (size_t)B * sizeof(int));
    last_max<<<cdiv(N, T), blk>>>(batch, lastidx, N);
    vn_gather<<<cdiv(B * H, T), blk>>>(h2, lastidx, vn, B);

    // 5) attention
    gemm_nt<<<dim3(cdiv(H, 128), cdiv(B, 128)), blk>>>(vn, W1_w, a, B, H, H);
    gemm_tf32_nt<<<dim3(cdiv(H, 128), cdiv(N, 128)), blk, SMEM_BYTES>>>(h2c, nullptr, W2c, bth, N, H, H);
    cudaMemsetAsync(sg, 0, (size_t)B * H * sizeof(float));
    attn_kernel<<<N, blk>>>(a, bth, h2, batch, W1_b, W2_b, q_w, q_b, sg);

    // 6) s_h = [vn | s_g] @ W3^T + b3, tf32-round
    concat_vns<<<cdiv(B * 512, T), blk>>>(vn, sg, vns, B);
    gemm_nt<<<dim3(cdiv(H, 128), cdiv(B, 128)), blk>>>(vns, W3_w, sh, B, H, 2 * H);
    add_bias_cvt<<<cdiv(B * H, T), blk>>>(sh, W3_b, B);

    // 7) scores = s_h @ emb^T
    gemm_tf32_nt<<<dim3(cdiv(NNODE, 128), cdiv(B, 128)), blk, SMEM_BYTES>>>(sh, nullptr, embc, scores, B, NNODE, H);

    // 8) passthrough edge_index as float
    edges_to_float<<<cdiv(2 * N, T), blk>>>(ei, eout, 2 * N);
}

// round 13
// speedup vs baseline: 5.3660x; 1.2253x over previous
#include <cuda_runtime.h>
#include <cuda_fp16.h>
#include <cstdint>
#include <cstddef>

#define H 256

// ---------------- scratch ----------------
__device__ __half d_aggEph[12288 * 256];
__device__ float  d_gi[12288 * 768];
__device__ float  d_gh[12288 * 768];
__device__ __half d_embch[50000 * 256];
__device__ float  d_F[768 * 256];
__device__ __half d_Fh[768 * 256];
__device__ __half d_Whhh[768 * 256];
__device__ __half d_W2h[256 * 256];
__device__ __half d_h2h[12288 * 256];
__device__ float  d_vn[1024 * 256];
__device__ float  d_a[1024 * 256];
__device__ float  d_bth[12288 * 256];
__device__ float  d_sg[1024 * 256];
__device__ float  d_vns[1024 * 512];
__device__ float  d_sh[1024 * 256];
__device__ __half d_shh[1024 * 256];
__device__ int    d_lastidx[1024];
__device__ int    d_deg[50176];
__device__ int    d_start[50001];
__device__ int    d_bsum[80];
__device__ int    d_cursor[50000];
__device__ int    d_csr[500000];

// ---------------- helpers ----------------
__device__ __forceinline__ void ldm_x4(unsigned r[4], unsigned addr) {
    asm volatile("ldmatrix.sync.aligned.m8n8.x4.shared.b16 {%0,%1,%2,%3}, [%4];"
                 : "=r"(r[0]), "=r"(r[1]), "=r"(r[2]), "=r"(r[3]) : "r"(addr));
}
__device__ __forceinline__ void mma_f16(float d[4], const unsigned a[4], const unsigned b[2]) {
    asm volatile("mma.sync.aligned.m16n8k16.row.col.f32.f16.f16.f32 "
                 "{%0,%1,%2,%3}, {%4,%5,%6,%7}, {%8,%9}, {%0,%1,%2,%3};"
                 : "+f"(d[0]), "+f"(d[1]), "+f"(d[2]), "+f"(d[3])
                 : "r"(a[0]), "r"(a[1]), "r"(a[2]), "r"(a[3]), "r"(b[0]), "r"(b[1]));
}
__device__ __forceinline__ void cp_async16(unsigned saddr, const void* gptr) {
    asm volatile("cp.async.cg.shared.global [%0], [%1], 16;" :: "r"(saddr), "l"(gptr));
}

// ---------------- fp16 tensor-core NT GEMM (operands pre-converted to fp16) ----------------
// C[m,n] = sum_k A[ra,k]*B[n,k], ra = Aidx ? Aidx[m]-1 : m. fp32 accumulate.
// Block 128x128, BK=32 (fp16), 8 warps of 64x32, 2 CTAs/SM. K % 32 == 0.
#define PADH 40
#define ASTG_H (128 * PADH)
#define BOFF_H (2 * ASTG_H)
#define BSTG_H (128 * PADH)
#define SMEMH_BYTES ((BOFF_H + 2 * BSTG_H) * 2)

__global__ __launch_bounds__(256, 2) void gemm_fp16_nt(
    const __half* __restrict__ A, const int* __restrict__ Aidx,
    const __half* __restrict__ B,
    float* __restrict__ C, int M, int N, int K)
{
    extern __shared__ __half smh[];
    const unsigned smu = (unsigned)__cvta_generic_to_shared(smh);

    const int tid  = threadIdx.x;
    const int warp = tid >> 5;
    const int lane = tid & 31;
    const int bm = blockIdx.y * 128;
    const int bn = blockIdx.x * 128;
    const int wm = (warp & 1) * 64;
    const int wn = (warp >> 1) * 32;

    float acc[4][4][4];
#pragma unroll
    for (int i = 0; i < 4; ++i)
#pragma unroll
        for (int j = 0; j < 4; ++j)
#pragma unroll
            for (int v = 0; v < 4; ++v) acc[i][j][v] = 0.f;

    // loaders: 2 chunks (16B = 8 halves) each for A and B per k-tile
    int arow[2], acol[2];
    const __half* agp[2];
    const __half* bgp[2];
#pragma unroll
    for (int i = 0; i < 2; ++i) {
        int lin = tid + i * 256;
        arow[i] = lin >> 2;          // 0..127
        acol[i] = (lin & 3) * 8;     // halves
        int gm = bm + arow[i]; gm = gm < M ? gm : M - 1;
        int ra = Aidx ? (Aidx[gm] - 1) : gm;
        agp[i] = A + (size_t)ra * K + acol[i];
        int gn = bn + arow[i]; gn = gn < N ? gn : N - 1;
        bgp[i] = B + (size_t)gn * K + acol[i];
    }

    // ldmatrix base addresses (bytes)
    // A: rows (lane&15), k-col (lane>>4)*8
    const unsigned aBase = smu + ((wm + (lane & 15)) * PADH + (lane >> 4) * 8) * 2u;
    // B: rows (lane>>4)*8 + (lane&7), k-col ((lane>>3)&1)*8
    const unsigned bBase = smu + (BOFF_H +
        (wn + (lane >> 4) * 8 + (lane & 7)) * PADH + ((lane >> 3) & 1) * 8) * 2u;

    const int KT = K >> 5;

    // prologue: stage 0
#pragma unroll
    for (int i = 0; i < 2; ++i) {
        cp_async16(smu + (arow[i] * PADH + acol[i]) * 2u, agp[i]);
        cp_async16(smu + (BOFF_H + arow[i] * PADH + acol[i]) * 2u, bgp[i]);
    }
    asm volatile("cp.async.commit_group;");

    for (int kt = 0; kt < KT; ++kt) {
        asm volatile("cp.async.wait_group 0;");
        __syncthreads();

        if (kt + 1 < KT) {
            int s1 = (kt + 1) & 1;
            int k0 = (kt + 1) << 5;
#pragma unroll
            for (int i = 0; i < 2; ++i) {
                cp_async16(smu + (s1 * ASTG_H + arow[i] * PADH + acol[i]) * 2u, agp[i] + k0);
                cp_async16(smu + (BOFF_H + s1 * BSTG_H + arow[i] * PADH + acol[i]) * 2u, bgp[i] + k0);
            }
            asm volatile("cp.async.commit_group;");
        }

        const int s = kt & 1;
        const unsigned aw = aBase + s * (ASTG_H * 2u);
        const unsigned bw = bBase + s * (BSTG_H * 2u);
#pragma unroll
        for (int kk = 0; kk < 32; kk += 16) {
            unsigned af[4][4];
            unsigned bf[4][2];
#pragma unroll
            for (int mi = 0; mi < 4; ++mi)
                ldm_x4(af[mi], aw + (mi * 16 * PADH + kk) * 2u);
#pragma unroll
            for (int p = 0; p < 2; ++p) {
                unsigned t[4];
                ldm_x4(t, bw + (p * 16 * PADH + kk) * 2u);
                bf[p * 2][0]     = t[0]; bf[p * 2][1]     = t[1];
                bf[p * 2 + 1][0] = t[2]; bf[p * 2 + 1][1] = t[3];
            }
#pragma unroll
            for (int mi = 0; mi < 4; ++mi)
#pragma unroll
                for (int nj = 0; nj < 4; ++nj)
                    mma_f16(acc[mi][nj], af[mi], bf[nj]);
        }
    }

    // epilogue (fp32)
#pragma unroll
    for (int mi = 0; mi < 4; ++mi) {
        int gm0 = bm + wm + mi * 16 + (lane >> 2);
#pragma unroll
        for (int nj = 0; nj < 4; ++nj) {
            int gn = bn + wn + nj * 8 + ((lane & 3) << 1);
            if (gn < N) {
                if (gm0 < M)
                    *reinterpret_cast<float2*>(&C[(size_t)gm0 * N + gn]) =
                        make_float2(acc[mi][nj][0], acc[mi][nj][1]);
                if (gm0 + 8 < M)
                    *reinterpret_cast<float2*>(&C[(size_t)(gm0 + 8) * N + gn]) =
                        make_float2(acc[mi][nj][2], acc[mi][nj][3]);
            }
        }
    }
}

// ---------------- fp32 fallback GEMM (small, precision-sensitive) ----------------
#define BK 16
__global__ __launch_bounds__(256) void gemm_nt(
    const float* __restrict__ A, const float* __restrict__ B,
    float* __restrict__ C, int M, int N, int K)
{
    __shared__ float As[BK][128];
    __shared__ float Bs[BK][128];
    const int bm = blockIdx.y * 128;
    const int bn = blockIdx.x * 128;
    const int tid = threadIdx.x;
    const int tcol = (tid & 15) * 8;
    const int trow = (tid >> 4) * 8;

    float acc[8][8];
#pragma unroll
    for (int i = 0; i < 8; ++i)
#pragma unroll
        for (int j = 0; j < 8; ++j) acc[i][j] = 0.f;

    for (int k0 = 0; k0 < K; k0 += BK) {
#pragma unroll
        for (int it = 0; it < 2; ++it) {
            int lin = tid + it * 256;
            int r  = lin >> 2;
            int c4 = (lin & 3) << 2;
            int gm = bm + r; gm = gm < M ? gm : M - 1;
            float4 va = *reinterpret_cast<const float4*>(A + (size_t)gm * K + k0 + c4);
            As[c4 + 0][r] = va.x; As[c4 + 1][r] = va.y;
            As[c4 + 2][r] = va.z; As[c4 + 3][r] = va.w;
            int gn = bn + r; gn = gn < N ? gn : N - 1;
            float4 vb = *reinterpret_cast<const float4*>(B + (size_t)gn * K + k0 + c4);
            Bs[c4 + 0][r] = vb.x; Bs[c4 + 1][r] = vb.y;
            Bs[c4 + 2][r] = vb.z; Bs[c4 + 3][r] = vb.w;
        }
        __syncthreads();
#pragma unroll
        for (int k = 0; k < BK; ++k) {
            float4 a0 = *reinterpret_cast<const float4*>(&As[k][trow]);
            float4 a1 = *reinterpret_cast<const float4*>(&As[k][trow + 4]);
            float4 b0 = *reinterpret_cast<const float4*>(&Bs[k][tcol]);
            float4 b1 = *reinterpret_cast<const float4*>(&Bs[k][tcol + 4]);
            float ar[8] = {a0.x, a0.y, a0.z, a0.w, a1.x, a1.y, a1.z, a1.w};
            float br[8] = {b0.x, b0.y, b0.z, b0.w, b1.x, b1.y, b1.z, b1.w};
#pragma unroll
            for (int i = 0; i < 8; ++i)
#pragma unroll
                for (int j = 0; j < 8; ++j)
                    acc[i][j] = fmaf(ar[i], br[j], acc[i][j]);
        }
        __syncthreads();
    }

#pragma unroll
    for (int i = 0; i < 8; ++i) {
        int gm = bm + trow + i;
        if (gm >= M) break;
#pragma unroll
        for (int j = 0; j < 8; ++j) {
            int gn = bn + tcol + j;
            if (gn < N) C[(size_t)gm * N + gn] = acc[i][j];
        }
    }
}

// ---------------- prep: fp16 conversions ----------------
__global__ void cvt_f2h(const float* __restrict__ in, __half* __restrict__ out, int n4)
{
    int i = blockIdx.x * blockDim.x + threadIdx.x;
    if (i >= n4) return;
    float4 v = reinterpret_cast<const float4*>(in)[i];
    reinterpret_cast<__half2*>(out)[2 * i]     = __floats2half2_rn(v.x, v.y);
    reinterpret_cast<__half2*>(out)[2 * i + 1] = __floats2half2_rn(v.z, v.w);
}

__global__ void prep_weights(const float* __restrict__ Whh, const float* __restrict__ W2,
                             __half* __restrict__ Whhh, __half* __restrict__ W2h)
{
    int idx = blockIdx.x * blockDim.x + threadIdx.x;
    if (idx < 196608) Whhh[idx] = __float2half_rn(Whh[idx]);
    else if (idx < 196608 + 65536) {
        int i = idx - 196608;
        W2h[i] = __float2half_rn(W2[i]);
    }
}

// ---------------- CSR build ----------------
__global__ void edge_hist(const int* __restrict__ fg, int* __restrict__ deg, int E)
{
    int e = blockIdx.x * blockDim.x + threadIdx.x;
    if (e >= E) return;
    atomicAdd(&deg[fg[E + e]], 1);
}

__global__ void scan_blocks(const int* __restrict__ deg, int* __restrict__ start,
                            int* __restrict__ bsum, int nnode)
{
    __shared__ int ws[32];
    const int tid = threadIdx.x, lane = tid & 31, w = tid >> 5;
    int gid = blockIdx.x * 1024 + tid;
    int v = (gid < nnode) ? deg[gid] : 0;
    int x = v;
#pragma unroll
    for (int o = 1; o < 32; o <<= 1) {
        int y = __shfl_up_sync(0xFFFFFFFFu, x, o);
        if (lane >= o) x += y;
    }
    if (lane == 31) ws[w] = x;
    __syncthreads();
    if (w == 0) {
        int s = ws[lane];
#pragma unroll
        for (int o = 1; o < 32; o <<= 1) {
            int y = __shfl_up_sync(0xFFFFFFFFu, s, o);
            if (lane >= o) s += y;
        }
        ws[lane] = s;
    }
    __syncthreads();
    int excl = x - v + (w > 0 ? ws[w - 1] : 0);
    if (gid < nnode) start[gid] = excl;
    if (tid == 0) bsum[blockIdx.x] = ws[31];
}

__global__ void scan_totals(int* __restrict__ bsum, int nb)
{
    __shared__ int ws[32];
    const int tid = threadIdx.x, lane = tid & 31, w = tid >> 5;
    int v = (tid < nb) ? bsum[tid] : 0;
    int x = v;
#pragma unroll
    for (int o = 1; o < 32; o <<= 1) {
        int y = __shfl_up_sync(0xFFFFFFFFu, x, o);
        if (lane >= o) x += y;
    }
    if (lane == 31) ws[w] = x;
    __syncthreads();
    if (w == 0) {
        int s = ws[lane];
#pragma unroll
        for (int o = 1; o < 32; o <<= 1) {
            int y = __shfl_up_sync(0xFFFFFFFFu, s, o);
            if (lane >= o) s += y;
        }
        ws[lane] = s;
    }
    __syncthreads();
    int excl = x - v + (w > 0 ? ws[w - 1] : 0);
    if (tid < nb) bsum[tid] = excl;
    if (tid == 0) bsum[nb] = ws[31];
}

__global__ void add_offsets(int* __restrict__ start, const int* __restrict__ bsum,
                            int nnode, int nb)
{
    int gid = blockIdx.x * blockDim.x + threadIdx.x;
    if (gid < nnode) start[gid] += bsum[gid >> 10];
    if (gid == 0) start[nnode] = bsum[nb];
}

__global__ void csr_fill(const int* __restrict__ fg, const int* __restrict__ start,
                         int* __restrict__ cursor, int* __restrict__ csr, int E)
{
    int e = blockIdx.x * blockDim.x + threadIdx.x;
    if (e >= E) return;
    int dst = fg[E + e];
    int slot = atomicAdd(&cursor[dst], 1);
    csr[start[dst] + slot] = fg[e];
}

// per-position aggregation (fp16 output): 128 threads, 2 cols each
__global__ __launch_bounds__(128) void gather_agg_pos(
    const int* __restrict__ x, const int* __restrict__ start, const int* __restrict__ csr,
    const float* __restrict__ emb, __half* __restrict__ aggEph)
{
    int i = blockIdx.x;
    int tid = threadIdx.x;
    int d = x[i] - 1;
    int s0 = start[d], s1 = start[d + 1];
    float a0 = 0.f, a1 = 0.f;
    for (int j = s0; j < s1; ++j) {
        int src = csr[j];
        float2 v = *reinterpret_cast<const float2*>(emb + (size_t)src * H + 2 * tid);
        a0 += v.x; a1 += v.y;
    }
    reinterpret_cast<__half2*>(aggEph + (size_t)i * H)[tid] = __floats2half2_rn(a0, a1);
}

// ---------------- fused GRU + relu-gather ----------------
__global__ void gru_fused(const int* __restrict__ x,
                          const float* __restrict__ gi, const float* __restrict__ gh,
                          const float* __restrict__ emb,
                          const float* __restrict__ bih, const float* __restrict__ bhh,
                          float* __restrict__ h2, __half* __restrict__ h2h, int N)
{
    long long idx = (long long)blockIdx.x * blockDim.x + threadIdx.x;
    if (idx >= (long long)N * H) return;
    int i = (int)(idx >> 8), h = (int)(idx & 255);
    size_t base = (size_t)i * 768;
    float ir = gi[base + h]       + bih[h];
    float hr = gh[base + h]       + bhh[h];
    float iz = gi[base + 256 + h] + bih[256 + h];
    float hz = gh[base + 256 + h] + bhh[256 + h];
    float in_ = gi[base + 512 + h] + bih[512 + h];
    float hn  = gh[base + 512 + h] + bhh[512 + h];
    float r = 1.f / (1.f + expf(-(ir + hr)));
    float z = 1.f / (1.f + expf(-(iz + hz)));
    float nn = tanhf(in_ + r * hn);
    int node = x[i] - 1;
    float e = emb[(size_t)node * H + h];
    float v = (1.f - z) * nn + z * e;
    v = v > 0.f ? v : 0.f;
    h2[idx] = v;
    h2h[idx] = __float2half_rn(v);
}

// ---------------- small helpers ----------------
__global__ void last_max(const int* __restrict__ batch, int* __restrict__ lastidx, int N)
{
    int i = blockIdx.x * blockDim.x + threadIdx.x;
    if (i >= N) return;
    atomicMax(&lastidx[batch[i]], i);
}

__global__ void vn_gather(const float* __restrict__ h2, const int* __restrict__ lastidx,
                          float* __restrict__ vn, int B)
{
    int idx = blockIdx.x * blockDim.x + threadIdx.x;
    if (idx >= B * H) return;
    int b = idx >> 8, h = idx & 255;
    vn[idx] = h2[(size_t)lastidx[b] * H + h];
}

__global__ void attn_kernel(const float* __restrict__ a, const float* __restrict__ bth,
                            const float* __restrict__ h2, const int* __restrict__ batch,
                            const float* __restrict__ W1_b, const float* __restrict__ W2_b,
                            const float* __restrict__ q_w, const float* __restrict__ q_b,
                            float* __restrict__ sg)
{
    __shared__ float red[256];
    int i = blockIdx.x;
    int h = threadIdx.x;
    int b = batch[i];
    float g = a[(size_t)b * H + h] + W1_b[h] + bth[(size_t)i * H + h] + W2_b[h];
    g = 1.f / (1.f + expf(-g));
    red[h] = g * q_w[h];
    __syncthreads();
#pragma unroll
    for (int s = 128; s > 0; s >>= 1) {
        if (h < s) red[h] += red[h + s];
        __syncthreads();
    }
    float alpha = red[0] + q_b[0];
    atomicAdd(&sg[(size_t)b * H + h], alpha * h2[(size_t)i * H + h]);
}

__global__ void concat_vns(const float* __restrict__ vn, const float* __restrict__ sg,
                           float* __restrict__ vns, int B)
{
    int idx = blockIdx.x * blockDim.x + threadIdx.x;
    if (idx >= B * 512) return;
    int b = idx >> 9, c = idx & 511;
    vns[idx] = (c < 256) ? vn[b * 256 + c] : sg[b * 256 + (c - 256)];
}

__global__ void add_bias_cvt(const float* __restrict__ sh, const float* __restrict__ W3_b,
                             __half* __restrict__ shh, int B)
{
    int idx = blockIdx.x * blockDim.x + threadIdx.x;
    if (idx >= B * H) return;
    shh[idx] = __float2half_rn(sh[idx] + W3_b[idx & 255]);
}

__global__ void edges_to_float(const int* __restrict__ ei, float* __restrict__ out, int n)
{
    int idx = blockIdx.x * blockDim.x + threadIdx.x;
    if (idx >= n) return;
    out[idx] = (float)ei[idx];
}

// ---------------- driver ----------------
extern "C" void kernel_launch(void* const* d_in, const int* in_sizes, int n_in,
                              void* d_out, int out_size)
{
    const int*   x      = (const int*)d_in[0];
    const int*   batch  = (const int*)d_in[1];
    const int*   ei     = (const int*)d_in[2];
    const int*   fg     = (const int*)d_in[3];
    const float* emb    = (const float*)d_in[4];
    const float* ggnn_W = (const float*)d_in[5];
    const float* Wih    = (const float*)d_in[6];
    const float* Whh    = (const float*)d_in[7];
    const float* bih    = (const float*)d_in[8];
    const float* bhh    = (const float*)d_in[9];
    const float* W1_w   = (const float*)d_in[10];
    const float* W1_b   = (const float*)d_in[11];
    const float* W2_w   = (const float*)d_in[12];
    const float* W2_b   = (const float*)d_in[13];
    const float* q_w    = (const float*)d_in[14];
    const float* q_b    = (const float*)d_in[15];
    const float* W3_w   = (const float*)d_in[16];
    const float* W3_b   = (const float*)d_in[17];
    float* out = (float*)d_out;

    const int N     = in_sizes[0];          // 12288
    const int E     = in_sizes[3] / 2;      // 500000
    const int NNODE = in_sizes[4] / H;      // 50000
    const long long scores_elems = (long long)out_size - (long long)N * H - 2LL * N;
    const int B = (int)(scores_elems / NNODE);   // 1024

    __half *aggEph, *embch, *Fh, *Whhh, *W2h, *h2h, *shh;
    float *gi, *gh, *F, *vn, *a, *bth, *sg, *vns, *sh;
    int *lastidx, *deg, *startp, *bsum, *cursor, *csr;
    cudaGetSymbolAddress((void**)&aggEph, d_aggEph);
    cudaGetSymbolAddress((void**)&gi,     d_gi);
    cudaGetSymbolAddress((void**)&gh,     d_gh);
    cudaGetSymbolAddress((void**)&embch,  d_embch);
    cudaGetSymbolAddress((void**)&F,      d_F);
    cudaGetSymbolAddress((void**)&Fh,     d_Fh);
    cudaGetSymbolAddress((void**)&Whhh,   d_Whhh);
    cudaGetSymbolAddress((void**)&W2h,    d_W2h);
    cudaGetSymbolAddress((void**)&h2h,    d_h2h);
    cudaGetSymbolAddress((void**)&vn,     d_vn);
    cudaGetSymbolAddress((void**)&a,      d_a);
    cudaGetSymbolAddress((void**)&bth,    d_bth);
    cudaGetSymbolAddress((void**)&sg,     d_sg);
    cudaGetSymbolAddress((void**)&vns,    d_vns);
    cudaGetSymbolAddress((void**)&sh,     d_sh);
    cudaGetSymbolAddress((void**)&shh,    d_shh);
    cudaGetSymbolAddress((void**)&lastidx, d_lastidx);
    cudaGetSymbolAddress((void**)&deg,    d_deg);
    cudaGetSymbolAddress((void**)&startp, d_start);
    cudaGetSymbolAddress((void**)&bsum,   d_bsum);
    cudaGetSymbolAddress((void**)&cursor, d_cursor);
    cudaGetSymbolAddress((void**)&csr,    d_csr);

    float* scores = out;
    float* h2     = out + scores_elems;
    float* eout   = out + scores_elems + (long long)N * H;

    const int T = 256;
    dim3 blk(T);
    auto cdiv = [](long long v, long long d) { return (unsigned)((v + d - 1) / d); };
    const int NB = (int)cdiv(NNODE, 1024);

    // 0) prep: F = Wih @ ggnn_W^T (fp32); fp16 conversions; CSR build
    gemm_nt<<<dim3(2, 6), blk>>>(Wih, ggnn_W, F, 3 * H, H, H);
    cvt_f2h<<<cdiv(768 * 256 / 4, T), blk>>>(F, Fh, 768 * 256 / 4);
    cvt_f2h<<<cdiv((long long)NNODE * H / 4, T), blk>>>(emb, embch, NNODE * H / 4);
    prep_weights<<<cdiv(196608 + 65536, T), blk>>>(Whh, W2_w, Whhh, W2h);
    cudaMemsetAsync(deg, 0, (size_t)NNODE * sizeof(int));
    edge_hist<<<cdiv(E, T), blk>>>(fg, deg, E);
    scan_blocks<<<NB, 1024>>>(deg, startp, bsum, NNODE);
    scan_totals<<<1, 1024>>>(bsum, NB);
    add_offsets<<<cdiv(NNODE, 1024), 1024>>>(startp, bsum, NNODE, NB);
    cudaMemsetAsync(cursor, 0, (size_t)NNODE * sizeof(int));
    csr_fill<<<cdiv(E, T), blk>>>(fg, startp, cursor, csr, E);

    // 1) per-position aggregation (fp16 out)
    gather_agg_pos<<<N, 128>>>(x, startp, csr, emb, aggEph);

    // 2) gi = aggEp @ F^T ; gh = emb[x-1] @ Whh^T   (fp16 tensor cores)
    gemm_fp16_nt<<<dim3(cdiv(3 * H, 128), cdiv(N, 128)), blk, SMEMH_BYTES>>>(aggEph, nullptr, Fh, gi, N, 3 * H, H);
    gemm_fp16_nt<<<dim3(cdiv(3 * H, 128), cdiv(N, 128)), blk, SMEMH_BYTES>>>(embch, x, Whhh, gh, N, 3 * H, H);

    // 3) fused GRU + relu -> h2 (d_out) + h2h (fp16)
    gru_fused<<<cdiv((long long)N * H, T), blk>>>(x, gi, gh, emb, bih, bhh, h2, h2h, N);

    // 4) last node per session
    cudaMemsetAsync(lastidx, 0xFF, (size_t)B * sizeof(int));
    last_max<<<cdiv(N, T), blk>>>(batch, lastidx, N);
    vn_gather<<<cdiv(B * H, T), blk>>>(h2, lastidx, vn, B);

    // 5) attention
    gemm_nt<<<dim3(cdiv(H, 128), cdiv(B, 128)), blk>>>(vn, W1_w, a, B, H, H);
    gemm_fp16_nt<<<dim3(cdiv(H, 128), cdiv(N, 128)), blk, SMEMH_BYTES>>>(h2h, nullptr, W2h, bth, N, H, H);
    cudaMemsetAsync(sg, 0, (size_t)B * H * sizeof(float));
    attn_kernel<<<N, blk>>>(a, bth, h2, batch, W1_b, W2_b, q_w, q_b, sg);

    // 6) s_h = [vn | s_g] @ W3^T + b3 (fp32) -> fp16
    concat_vns<<<cdiv(B * 512, T), blk>>>(vn, sg, vns, B);
    gemm_nt<<<dim3(cdiv(H, 128), cdiv(B, 128)), blk>>>(vns, W3_w, sh, B, H, 2 * H);
    add_bias_cvt<<<cdiv(B * H, T), blk>>>(sh, W3_b, shh, B);

    // 7) scores = s_h @ emb^T   (fp16 tensor cores)
    gemm_fp16_nt<<<dim3(cdiv(NNODE, 128), cdiv(B, 128)), blk, SMEMH_BYTES>>>(shh, nullptr, embch, scores, B, NNODE, H);

    // 8) passthrough edge_index as float
    edges_to_float<<<cdiv(2 * N, T), blk>>>(ei, eout, 2 * N);
}

// round 17
// speedup vs baseline: 6.0299x; 1.1237x over previous
#include <cuda_runtime.h>
#include <cuda_fp16.h>
#include <cstdint>
#include <cstddef>

#define H 256

// ---------------- scratch ----------------
__device__ __half d_aggEph[12288 * 256];
__device__ float  d_gi[12288 * 768];
__device__ float  d_gh[12288 * 768];
__device__ __half d_embch[50000 * 256];
__device__ float  d_F[768 * 256];
__device__ __half d_Fh[768 * 256];
__device__ __half d_Whhh[768 * 256];
__device__ __half d_W2h[256 * 256];
__device__ __half d_h2h[12288 * 256];
__device__ float  d_vn[1024 * 256];
__device__ float  d_a[1024 * 256];
__device__ float  d_bth[12288 * 256];
__device__ float  d_sg[1024 * 256];
__device__ float  d_vns[1024 * 512];
__device__ float  d_sh[1024 * 256];
__device__ __half d_shh[1024 * 256];
__device__ int    d_lastidx[1024];
__device__ int    d_deg[50176];
__device__ int    d_start[50001];
__device__ int    d_bsum[80];
__device__ int    d_cursor[50000];
__device__ int    d_csr[500000];

// ---------------- helpers ----------------
__device__ __forceinline__ void ldm_x4(unsigned r[4], unsigned addr) {
    asm volatile("ldmatrix.sync.aligned.m8n8.x4.shared.b16 {%0,%1,%2,%3}, [%4];"
                 : "=r"(r[0]), "=r"(r[1]), "=r"(r[2]), "=r"(r[3]) : "r"(addr));
}
__device__ __forceinline__ void mma_f16(float d[4], const unsigned a[4], const unsigned b[2]) {
    asm volatile("mma.sync.aligned.m16n8k16.row.col.f32.f16.f16.f32 "
                 "{%0,%1,%2,%3}, {%4,%5,%6,%7}, {%8,%9}, {%0,%1,%2,%3};"
                 : "+f"(d[0]), "+f"(d[1]), "+f"(d[2]), "+f"(d[3])
                 : "r"(a[0]), "r"(a[1]), "r"(a[2]), "r"(a[3]), "r"(b[0]), "r"(b[1]));
}
__device__ __forceinline__ void cp_async16(unsigned saddr, const void* gptr) {
    asm volatile("cp.async.cg.shared.global [%0], [%1], 16;" :: "r"(saddr), "l"(gptr));
}

// ---------------- fp16 tensor-core NT GEMM ----------------
#define PADH 40
#define ASTG_H (128 * PADH)
#define BOFF_H (2 * ASTG_H)
#define BSTG_H (128 * PADH)
#define SMEMH_BYTES ((BOFF_H + 2 * BSTG_H) * 2)

__global__ __launch_bounds__(256, 2) void gemm_fp16_nt(
    const __half* __restrict__ A, const int* __restrict__ Aidx,
    const __half* __restrict__ B,
    float* __restrict__ C, int M, int N, int K)
{
    extern __shared__ __half smh[];
    const unsigned smu = (unsigned)__cvta_generic_to_shared(smh);

    const int tid  = threadIdx.x;
    const int warp = tid >> 5;
    const int lane = tid & 31;
    const int bm = blockIdx.y * 128;
    const int bn = blockIdx.x * 128;
    const int wm = (warp & 1) * 64;
    const int wn = (warp >> 1) * 32;

    float acc[4][4][4];
#pragma unroll
    for (int i = 0; i < 4; ++i)
#pragma unroll
        for (int j = 0; j < 4; ++j)
#pragma unroll
            for (int v = 0; v < 4; ++v) acc[i][j][v] = 0.f;

    int arow[2], acol[2];
    const __half* agp[2];
    const __half* bgp[2];
#pragma unroll
    for (int i = 0; i < 2; ++i) {
        int lin = tid + i * 256;
        arow[i] = lin >> 2;
        acol[i] = (lin & 3) * 8;
        int gm = bm + arow[i]; gm = gm < M ? gm : M - 1;
        int ra = Aidx ? (Aidx[gm] - 1) : gm;
        agp[i] = A + (size_t)ra * K + acol[i];
        int gn = bn + arow[i]; gn = gn < N ? gn : N - 1;
        bgp[i] = B + (size_t)gn * K + acol[i];
    }

    const unsigned aBase = smu + ((wm + (lane & 15)) * PADH + (lane >> 4) * 8) * 2u;
    const unsigned bBase = smu + (BOFF_H +
        (wn + (lane >> 4) * 8 + (lane & 7)) * PADH + ((lane >> 3) & 1) * 8) * 2u;

    const int KT = K >> 5;

#pragma unroll
    for (int i = 0; i < 2; ++i) {
        cp_async16(smu + (arow[i] * PADH + acol[i]) * 2u, agp[i]);
        cp_async16(smu + (BOFF_H + arow[i] * PADH + acol[i]) * 2u, bgp[i]);
    }
    asm volatile("cp.async.commit_group;");

    for (int kt = 0; kt < KT; ++kt) {
        asm volatile("cp.async.wait_group 0;");
        __syncthreads();

        if (kt + 1 < KT) {
            int s1 = (kt + 1) & 1;
            int k0 = (kt + 1) << 5;
#pragma unroll
            for (int i = 0; i < 2; ++i) {
                cp_async16(smu + (s1 * ASTG_H + arow[i] * PADH + acol[i]) * 2u, agp[i] + k0);
                cp_async16(smu + (BOFF_H + s1 * BSTG_H + arow[i] * PADH + acol[i]) * 2u, bgp[i] + k0);
            }
            asm volatile("cp.async.commit_group;");
        }

        const int s = kt & 1;
        const unsigned aw = aBase + s * (ASTG_H * 2u);
        const unsigned bw = bBase + s * (BSTG_H * 2u);
#pragma unroll
        for (int kk = 0; kk < 32; kk += 16) {
            unsigned af[4][4];
            unsigned bf[4][2];
#pragma unroll
            for (int mi = 0; mi < 4; ++mi)
                ldm_x4(af[mi], aw + (mi * 16 * PADH + kk) * 2u);
#pragma unroll
            for (int p = 0; p < 2; ++p) {
                unsigned t[4];
                ldm_x4(t, bw + (p * 16 * PADH + kk) * 2u);
                bf[p * 2][0]     = t[0]; bf[p * 2][1]     = t[1];
                bf[p * 2 + 1][0] = t[2]; bf[p * 2 + 1][1] = t[3];
            }
#pragma unroll
            for (int mi = 0; mi < 4; ++mi)
#pragma unroll
                for (int nj = 0; nj < 4; ++nj)
                    mma_f16(acc[mi][nj], af[mi], bf[nj]);
        }
    }

#pragma unroll
    for (int mi = 0; mi < 4; ++mi) {
        int gm0 = bm + wm + mi * 16 + (lane >> 2);
#pragma unroll
        for (int nj = 0; nj < 4; ++nj) {
            int gn = bn + wn + nj * 8 + ((lane & 3) << 1);
            if (gn < N) {
                if (gm0 < M)
                    *reinterpret_cast<float2*>(&C[(size_t)gm0 * N + gn]) =
                        make_float2(acc[mi][nj][0], acc[mi][nj][1]);
                if (gm0 + 8 < M)
                    *reinterpret_cast<float2*>(&C[(size_t)(gm0 + 8) * N + gn]) =
                        make_float2(acc[mi][nj][2], acc[mi][nj][3]);
            }
        }
    }
}

// ---------------- fp32 fallback GEMM ----------------
#define BK 16
__global__ __launch_bounds__(256) void gemm_nt(
    const float* __restrict__ A, const float* __restrict__ B,
    float* __restrict__ C, int M, int N, int K)
{
    __shared__ float As[BK][128];
    __shared__ float Bs[BK][128];
    const int bm = blockIdx.y * 128;
    const int bn = blockIdx.x * 128;
    const int tid = threadIdx.x;
    const int tcol = (tid & 15) * 8;
    const int trow = (tid >> 4) * 8;

    float acc[8][8];
#pragma unroll
    for (int i = 0; i < 8; ++i)
#pragma unroll
        for (int j = 0; j < 8; ++j) acc[i][j] = 0.f;

    for (int k0 = 0; k0 < K; k0 += BK) {
#pragma unroll
        for (int it = 0; it < 2; ++it) {
            int lin = tid + it * 256;
            int r  = lin >> 2;
            int c4 = (lin & 3) << 2;
            int gm = bm + r; gm = gm < M ? gm : M - 1;
            float4 va = *reinterpret_cast<const float4*>(A + (size_t)gm * K + k0 + c4);
            As[c4 + 0][r] = va.x; As[c4 + 1][r] = va.y;
            As[c4 + 2][r] = va.z; As[c4 + 3][r] = va.w;
            int gn = bn + r; gn = gn < N ? gn : N - 1;
            float4 vb = *reinterpret_cast<const float4*>(B + (size_t)gn * K + k0 + c4);
            Bs[c4 + 0][r] = vb.x; Bs[c4 + 1][r] = vb.y;
            Bs[c4 + 2][r] = vb.z; Bs[c4 + 3][r] = vb.w;
        }
        __syncthreads();
#pragma unroll
        for (int k = 0; k < BK; ++k) {
            float4 a0 = *reinterpret_cast<const float4*>(&As[k][trow]);
            float4 a1 = *reinterpret_cast<const float4*>(&As[k][trow + 4]);
            float4 b0 = *reinterpret_cast<const float4*>(&Bs[k][tcol]);
            float4 b1 = *reinterpret_cast<const float4*>(&Bs[k][tcol + 4]);
            float ar[8] = {a0.x, a0.y, a0.z, a0.w, a1.x, a1.y, a1.z, a1.w};
            float br[8] = {b0.x, b0.y, b0.z, b0.w, b1.x, b1.y, b1.z, b1.w};
#pragma unroll
            for (int i = 0; i < 8; ++i)
#pragma unroll
                for (int j = 0; j < 8; ++j)
                    acc[i][j] = fmaf(ar[i], br[j], acc[i][j]);
        }
        __syncthreads();
    }

#pragma unroll
    for (int i = 0; i < 8; ++i) {
        int gm = bm + trow + i;
        if (gm >= M) break;
#pragma unroll
        for (int j = 0; j < 8; ++j) {
            int gn = bn + tcol + j;
            if (gn < N) C[(size_t)gm * N + gn] = acc[i][j];
        }
    }
}

// ---------------- prep ----------------
__global__ void cvt_f2h(const float* __restrict__ in, __half* __restrict__ out, int n4)
{
    int i = blockIdx.x * blockDim.x + threadIdx.x;
    if (i >= n4) return;
    float4 v = reinterpret_cast<const float4*>(in)[i];
    reinterpret_cast<__half2*>(out)[2 * i]     = __floats2half2_rn(v.x, v.y);
    reinterpret_cast<__half2*>(out)[2 * i + 1] = __floats2half2_rn(v.z, v.w);
}

__global__ void prep_weights(const float* __restrict__ Whh, const float* __restrict__ W2,
                             __half* __restrict__ Whhh, __half* __restrict__ W2h)
{
    int idx = blockIdx.x * blockDim.x + threadIdx.x;
    if (idx < 196608) Whhh[idx] = __float2half_rn(Whh[idx]);
    else if (idx < 196608 + 65536) {
        int i = idx - 196608;
        W2h[i] = __float2half_rn(W2[i]);
    }
}

// ---------------- CSR build ----------------
__global__ void edge_hist(const int* __restrict__ fg, int* __restrict__ deg, int E)
{
    int e = blockIdx.x * blockDim.x + threadIdx.x;
    if (e >= E) return;
    atomicAdd(&deg[fg[E + e]], 1);
}

__global__ void scan_blocks(const int* __restrict__ deg, int* __restrict__ start,
                            int* __restrict__ bsum, int nnode)
{
    __shared__ int ws[32];
    const int tid = threadIdx.x, lane = tid & 31, w = tid >> 5;
    int gid = blockIdx.x * 1024 + tid;
    int v = (gid < nnode) ? deg[gid] : 0;
    int x = v;
#pragma unroll
    for (int o = 1; o < 32; o <<= 1) {
        int y = __shfl_up_sync(0xFFFFFFFFu, x, o);
        if (lane >= o) x += y;
    }
    if (lane == 31) ws[w] = x;
    __syncthreads();
    if (w == 0) {
        int s = ws[lane];
#pragma unroll
        for (int o = 1; o < 32; o <<= 1) {
            int y = __shfl_up_sync(0xFFFFFFFFu, s, o);
            if (lane >= o) s += y;
        }
        ws[lane] = s;
    }
    __syncthreads();
    int excl = x - v + (w > 0 ? ws[w - 1] : 0);
    if (gid < nnode) start[gid] = excl;
    if (tid == 0) bsum[blockIdx.x] = ws[31];
}

__global__ void scan_totals(int* __restrict__ bsum, int nb)
{
    __shared__ int ws[32];
    const int tid = threadIdx.x, lane = tid & 31, w = tid >> 5;
    int v = (tid < nb) ? bsum[tid] : 0;
    int x = v;
#pragma unroll
    for (int o = 1; o < 32; o <<= 1) {
        int y = __shfl_up_sync(0xFFFFFFFFu, x, o);
        if (lane >= o) x += y;
    }
    if (lane == 31) ws[w] = x;
    __syncthreads();
    if (w == 0) {
        int s = ws[lane];
#pragma unroll
        for (int o = 1; o < 32; o <<= 1) {
            int y = __shfl_up_sync(0xFFFFFFFFu, s, o);
            if (lane >= o) s += y;
        }
        ws[lane] = s;
    }
    __syncthreads();
    int excl = x - v + (w > 0 ? ws[w - 1] : 0);
    if (tid < nb) bsum[tid] = excl;
    if (tid == 0) bsum[nb] = ws[31];
}

__global__ void add_offsets(int* __restrict__ start, const int* __restrict__ bsum,
                            int nnode, int nb)
{
    int gid = blockIdx.x * blockDim.x + threadIdx.x;
    if (gid < nnode) start[gid] += bsum[gid >> 10];
    if (gid == 0) start[nnode] = bsum[nb];
}

__global__ void csr_fill(const int* __restrict__ fg, const int* __restrict__ start,
                         int* __restrict__ cursor, int* __restrict__ csr, int E)
{
    int e = blockIdx.x * blockDim.x + threadIdx.x;
    if (e >= E) return;
    int dst = fg[E + e];
    int slot = atomicAdd(&cursor[dst], 1);
    csr[start[dst] + slot] = fg[e];
}

__global__ __launch_bounds__(128) void gather_agg_pos(
    const int* __restrict__ x, const int* __restrict__ start, const int* __restrict__ csr,
    const float* __restrict__ emb, __half* __restrict__ aggEph)
{
    int i = blockIdx.x;
    int tid = threadIdx.x;
    int d = x[i] - 1;
    int s0 = start[d], s1 = start[d + 1];
    float a0 = 0.f, a1 = 0.f;
    for (int j = s0; j < s1; ++j) {
        int src = csr[j];
        float2 v = *reinterpret_cast<const float2*>(emb + (size_t)src * H + 2 * tid);
        a0 += v.x; a1 += v.y;
    }
    reinterpret_cast<__half2*>(aggEph + (size_t)i * H)[tid] = __floats2half2_rn(a0, a1);
}

// ---------------- fused GRU + relu-gather ----------------
__global__ void gru_fused(const int* __restrict__ x,
                          const float* __restrict__ gi, const float* __restrict__ gh,
                          const float* __restrict__ emb,
                          const float* __restrict__ bih, const float* __restrict__ bhh,
                          float* __restrict__ h2, __half* __restrict__ h2h, int N)
{
    long long idx = (long long)blockIdx.x * blockDim.x + threadIdx.x;
    if (idx >= (long long)N * H) return;
    int i = (int)(idx >> 8), h = (int)(idx & 255);
    size_t base = (size_t)i * 768;
    float ir = gi[base + h]       + bih[h];
    float hr = gh[base + h]       + bhh[h];
    float iz = gi[base + 256 + h] + bih[256 + h];
    float hz = gh[base + 256 + h] + bhh[256 + h];
    float in_ = gi[base + 512 + h] + bih[512 + h];
    float hn  = gh[base + 512 + h] + bhh[512 + h];
    float r = 1.f / (1.f + expf(-(ir + hr)));
    float z = 1.f / (1.f + expf(-(iz + hz)));
    float nn = tanhf(in_ + r * hn);
    int node = x[i] - 1;
    float e = emb[(size_t)node * H + h];
    float v = (1.f - z) * nn + z * e;
    v = v > 0.f ? v : 0.f;
    h2[idx] = v;
    h2h[idx] = __float2half_rn(v);
}

// ---------------- small helpers ----------------
__global__ void last_max(const int* __restrict__ batch, int* __restrict__ lastidx, int N)
{
    int i = blockIdx.x * blockDim.x + threadIdx.x;
    if (i >= N) return;
    atomicMax(&lastidx[batch[i]], i);
}

__global__ void vn_gather(const float* __restrict__ h2, const int* __restrict__ lastidx,
                          float* __restrict__ vn, int B)
{
    int idx = blockIdx.x * blockDim.x + threadIdx.x;
    if (idx >= B * H) return;
    int b = idx >> 8, h = idx & 255;
    vn[idx] = h2[(size_t)lastidx[b] * H + h];
}

__global__ void attn_kernel(const float* __restrict__ a, const float* __restrict__ bth,
                            const float* __restrict__ h2, const int* __restrict__ batch,
                            const float* __restrict__ W1_b, const float* __restrict__ W2_b,
                            const float* __restrict__ q_w, const float* __restrict__ q_b,
                            float* __restrict__ sg)
{
    __shared__ float red[256];
    int i = blockIdx.x;
    int h = threadIdx.x;
    int b = batch[i];
    float g = a[(size_t)b * H + h] + W1_b[h] + bth[(size_t)i * H + h] + W2_b[h];
    g = 1.f / (1.f + expf(-g));
    red[h] = g * q_w[h];
    __syncthreads();
#pragma unroll
    for (int s = 128; s > 0; s >>= 1) {
        if (h < s) red[h] += red[h + s];
        __syncthreads();
    }
    float alpha = red[0] + q_b[0];
    atomicAdd(&sg[(size_t)b * H + h], alpha * h2[(size_t)i * H + h]);
}

__global__ void concat_vns(const float* __restrict__ vn, const float* __restrict__ sg,
                           float* __restrict__ vns, int B)
{
    int idx = blockIdx.x * blockDim.x + threadIdx.x;
    if (idx >= B * 512) return;
    int b = idx >> 9, c = idx & 511;
    vns[idx] = (c < 256) ? vn[b * 256 + c] : sg[b * 256 + (c - 256)];
}

__global__ void add_bias_cvt(const float* __restrict__ sh, const float* __restrict__ W3_b,
                             __half* __restrict__ shh, int B)
{
    int idx = blockIdx.x * blockDim.x + threadIdx.x;
    if (idx >= B * H) return;
    shh[idx] = __float2half_rn(sh[idx] + W3_b[idx & 255]);
}

__global__ void edges_to_float(const int* __restrict__ ei, float* __restrict__ out, int n)
{
    int idx = blockIdx.x * blockDim.x + threadIdx.x;
    if (idx >= n) return;
    out[idx] = (float)ei[idx];
}

// ---------------- driver ----------------
extern "C" void kernel_launch(void* const* d_in, const int* in_sizes, int n_in,
                              void* d_out, int out_size)
{
    const int*   x      = (const int*)d_in[0];
    const int*   batch  = (const int*)d_in[1];
    const int*   ei     = (const int*)d_in[2];
    const int*   fg     = (const int*)d_in[3];
    const float* emb    = (const float*)d_in[4];
    const float* ggnn_W = (const float*)d_in[5];
    const float* Wih    = (const float*)d_in[6];
    const float* Whh    = (const float*)d_in[7];
    const float* bih    = (const float*)d_in[8];
    const float* bhh    = (const float*)d_in[9];
    const float* W1_w   = (const float*)d_in[10];
    const float* W1_b   = (const float*)d_in[11];
    const float* W2_w   = (const float*)d_in[12];
    const float* W2_b   = (const float*)d_in[13];
    const float* q_w    = (const float*)d_in[14];
    const float* q_b    = (const float*)d_in[15];
    const float* W3_w   = (const float*)d_in[16];
    const float* W3_b   = (const float*)d_in[17];
    float* out = (float*)d_out;

    const int N     = in_sizes[0];          // 12288
    const int E     = in_sizes[3] / 2;      // 500000
    const int NNODE = in_sizes[4] / H;      // 50000
    const long long scores_elems = (long long)out_size - (long long)N * H - 2LL * N;
    const int B = (int)(scores_elems / NNODE);   // 1024

    // one-time host-side resources (created on the uncaptured correctness call)
    static bool s_init = false;
    static cudaStream_t s2;
    static cudaEvent_t evFork, evFh, evGi, evGru, evBth;
    if (!s_init) {
        cudaStreamCreateWithFlags(&s2, cudaStreamNonBlocking);
        cudaEventCreateWithFlags(&evFork, cudaEventDisableTiming);
        cudaEventCreateWithFlags(&evFh,   cudaEventDisableTiming);
        cudaEventCreateWithFlags(&evGi,   cudaEventDisableTiming);
        cudaEventCreateWithFlags(&evGru,  cudaEventDisableTiming);
        cudaEventCreateWithFlags(&evBth,  cudaEventDisableTiming);
        s_init = true;
    }

    __half *aggEph, *embch, *Fh, *Whhh, *W2h, *h2h, *shh;
    float *gi, *gh, *F, *vn, *a, *bth, *sg, *vns, *sh;
    int *lastidx, *deg, *startp, *bsum, *cursor, *csr;
    cudaGetSymbolAddress((void**)&aggEph, d_aggEph);
    cudaGetSymbolAddress((void**)&gi,     d_gi);
    cudaGetSymbolAddress((void**)&gh,     d_gh);
    cudaGetSymbolAddress((void**)&embch,  d_embch);
    cudaGetSymbolAddress((void**)&F,      d_F);
    cudaGetSymbolAddress((void**)&Fh,     d_Fh);
    cudaGetSymbolAddress((void**)&Whhh,   d_Whhh);
    cudaGetSymbolAddress((void**)&W2h,    d_W2h);
    cudaGetSymbolAddress((void**)&h2h,    d_h2h);
    cudaGetSymbolAddress((void**)&vn,     d_vn);
    cudaGetSymbolAddress((void**)&a,      d_a);
    cudaGetSymbolAddress((void**)&bth,    d_bth);
    cudaGetSymbolAddress((void**)&sg,     d_sg);
    cudaGetSymbolAddress((void**)&vns,    d_vns);
    cudaGetSymbolAddress((void**)&sh,     d_sh);
    cudaGetSymbolAddress((void**)&shh,    d_shh);
    cudaGetSymbolAddress((void**)&lastidx, d_lastidx);
    cudaGetSymbolAddress((void**)&deg,    d_deg);
    cudaGetSymbolAddress((void**)&startp, d_start);
    cudaGetSymbolAddress((void**)&bsum,   d_bsum);
    cudaGetSymbolAddress((void**)&cursor, d_cursor);
    cudaGetSymbolAddress((void**)&csr,    d_csr);

    float* scores = out;
    float* h2     = out + scores_elems;
    float* eout   = out + scores_elems + (long long)N * H;

    const int T = 256;
    dim3 blk(T);
    auto cdiv = [](long long v, long long d) { return (unsigned)((v + d - 1) / d); };
    const int NB = (int)cdiv(NNODE, 1024);

    // ---- fork: side stream s2 runs the CSR/aggregation chain ----
    cudaEventRecord(evFork, 0);
    cudaStreamWaitEvent(s2, evFork, 0);

    // s2: independent prep + CSR build + aggregation
    edges_to_float<<<cdiv(2 * N, T), blk, 0, s2>>>(ei, eout, 2 * N);
    cudaMemsetAsync(sg, 0, (size_t)B * H * sizeof(float), s2);
    cudaMemsetAsync(deg, 0, (size_t)NNODE * sizeof(int), s2);
    edge_hist<<<cdiv(E, T), blk, 0, s2>>>(fg, deg, E);
    scan_blocks<<<NB, 1024, 0, s2>>>(deg, startp, bsum, NNODE);
    scan_totals<<<1, 1024, 0, s2>>>(bsum, NB);
    add_offsets<<<cdiv(NNODE, 1024), 1024, 0, s2>>>(startp, bsum, NNODE, NB);
    cudaMemsetAsync(cursor, 0, (size_t)NNODE * sizeof(int), s2);
    csr_fill<<<cdiv(E, T), blk, 0, s2>>>(fg, startp, cursor, csr, E);
    gather_agg_pos<<<N, 128, 0, s2>>>(x, startp, csr, emb, aggEph);

    // main: weight prep chain
    gemm_nt<<<dim3(2, 6), blk>>>(Wih, ggnn_W, F, 3 * H, H, H);
    cvt_f2h<<<cdiv(768 * 256 / 4, T), blk>>>(F, Fh, 768 * 256 / 4);
    cudaEventRecord(evFh, 0);
    cvt_f2h<<<cdiv((long long)NNODE * H / 4, T), blk>>>(emb, embch, NNODE * H / 4);
    prep_weights<<<cdiv(196608 + 65536, T), blk>>>(Whh, W2_w, Whhh, W2h);

    // s2: gi = aggEp @ F^T  (needs Fh from main)
    cudaStreamWaitEvent(s2, evFh, 0);
    gemm_fp16_nt<<<dim3(cdiv(3 * H, 128), cdiv(N, 128)), blk, SMEMH_BYTES, s2>>>(aggEph, nullptr, Fh, gi, N, 3 * H, H);
    cudaEventRecord(evGi, s2);

    // main: gh = emb[x-1] @ Whh^T
    gemm_fp16_nt<<<dim3(cdiv(3 * H, 128), cdiv(N, 128)), blk, SMEMH_BYTES>>>(embch, x, Whhh, gh, N, 3 * H, H);

    // join gi, then GRU
    cudaStreamWaitEvent(0, evGi, 0);
    gru_fused<<<cdiv((long long)N * H, T), blk>>>(x, gi, gh, emb, bih, bhh, h2, h2h, N);
    cudaEventRecord(evGru, 0);

    // s2: bth = h2h @ W2h^T overlapping the vn path
    cudaStreamWaitEvent(s2, evGru, 0);
    gemm_fp16_nt<<<dim3(cdiv(H, 128), cdiv(N, 128)), blk, SMEMH_BYTES, s2>>>(h2h, nullptr, W2h, bth, N, H, H);
    cudaEventRecord(evBth, s2);

    // main: vn path
    cudaMemsetAsync(lastidx, 0xFF, (size_t)B * sizeof(int));
    last_max<<<cdiv(N, T), blk>>>(batch, lastidx, N);
    vn_gather<<<cdiv(B * H, T), blk>>>(h2, lastidx, vn, B);
    gemm_nt<<<dim3(cdiv(H, 128), cdiv(B, 128)), blk>>>(vn, W1_w, a, B, H, H);

    // join bth (also rejoins all remaining s2 work), then attention
    cudaStreamWaitEvent(0, evBth, 0);
    attn_kernel<<<N, blk>>>(a, bth, h2, batch, W1_b, W2_b, q_w, q_b, sg);

    // s_h = [vn | s_g] @ W3^T + b3 -> fp16
    concat_vns<<<cdiv(B * 512, T), blk>>>(vn, sg, vns, B);
    gemm_nt<<<dim3(cdiv(H, 128), cdiv(B, 128)), blk>>>(vns, W3_w, sh, B, H, 2 * H);
    add_bias_cvt<<<cdiv(B * H, T), blk>>>(sh, W3_b, shh, B);

    // scores = s_h @ emb^T
    gemm_fp16_nt<<<dim3(cdiv(NNODE, 128), cdiv(B, 128)), blk, SMEMH_BYTES>>>(shh, nullptr, embch, scores, B, NNODE, H);
}